// round 2
// baseline (speedup 1.0000x reference)
#include <cuda_runtime.h>
#include <math.h>
#include <stdint.h>

#define NB 64
#define NT 256
#define NN 1024
#define NO 512
#define NK_SPEED 20
#define NK_HD 50
#define NK_TOT 70
#define RNN_NCTA 32

__device__ float    g_drive[(size_t)NB * NT * NN];
__device__ float    g_hs[(size_t)NB * NT * NN];
__device__ float    g_h[2][NB * NN];
__device__ float    g_out[(size_t)NB * NT * NO];
__device__ float    g_centers[NB * NO * 2];
__device__ int      g_nnz_cnt[NN];
__device__ int      g_nnz_idx[(size_t)NN * NN];
__device__ float    g_nnz_val[(size_t)NN * NN];
__device__ unsigned g_flags[RNN_NCTA * 32];

__device__ __forceinline__ unsigned long long pack2(float lo, float hi) {
    unsigned long long o;
    asm("mov.b64 %0, {%1, %2};" : "=l"(o) : "r"(__float_as_uint(lo)), "r"(__float_as_uint(hi)));
    return o;
}
__device__ __forceinline__ void unpack2(unsigned long long v, float& lo, float& hi) {
    unsigned a, b;
    asm("mov.b64 {%0, %1}, %2;" : "=r"(a), "=r"(b) : "l"(v));
    lo = __uint_as_float(a); hi = __uint_as_float(b);
}
__device__ __forceinline__ unsigned long long fma2(unsigned long long a, unsigned long long b, unsigned long long c) {
    unsigned long long d;
    asm("fma.rn.f32x2 %0, %1, %2, %3;" : "=l"(d) : "l"(a), "l"(b), "l"(c));
    return d;
}

__global__ void reset_flags_kernel() {
    if (threadIdx.x < RNN_NCTA * 32) g_flags[threadIdx.x] = 0u;
}

__global__ void build_csc_kernel(const float* __restrict__ recW) {
    int n = blockIdx.x * blockDim.x + threadIdx.x;
    if (n >= NN) return;
    int cnt = 0;
    for (int k = 0; k < NN; k++) {
        float w = recW[(size_t)k * NN + n];
        if (w != 0.0f) {
            g_nnz_idx[(size_t)n * NN + cnt] = k;
            g_nnz_val[(size_t)n * NN + cnt] = w;
            cnt++;
        }
    }
    g_nnz_cnt[n] = cnt;
}

__global__ void __launch_bounds__(256) drive_kernel(const float* __restrict__ x,
                                                    const float* __restrict__ sW,
                                                    const float* __restrict__ hW) {
    __shared__ float feats[8][NK_TOT];
    const int b = blockIdx.y;
    const int t0 = blockIdx.x * 8;
    const int tid = threadIdx.x;
    const float TWO_PI = 6.2831853071795865f;
    const float LOGNORM = 6.3050317f;  // log(2*pi*I0(2*pi))

    for (int i = tid; i < 8 * NK_TOT; i += 256) {
        int tl = i / NK_TOT, k = i - tl * NK_TOT;
        int t = t0 + tl;
        float f;
        if (k < NK_SPEED) {
            float v = x[((size_t)b * NT + t) * 2 + 0];
            float dv = v - 0.5f * (float)k / 19.0f;
            f = expf(-800.0f * dv * dv);
        } else {
            float th = x[((size_t)b * NT + t) * 2 + 1];
            float c = TWO_PI * (float)(k - NK_SPEED) / 49.0f;
            f = expf(TWO_PI * cosf(th - c) - LOGNORM);
        }
        feats[tl][k] = f;
    }
    __syncthreads();

    float acc[8][4];
#pragma unroll
    for (int tt = 0; tt < 8; tt++)
#pragma unroll
        for (int i = 0; i < 4; i++) acc[tt][i] = 0.0f;

    for (int k = 0; k < NK_TOT; k++) {
        const float* __restrict__ Wr = (k < NK_SPEED) ? (sW + (size_t)k * NN)
                                                      : (hW + (size_t)(k - NK_SPEED) * NN);
        float w0 = Wr[tid], w1 = Wr[tid + 256], w2 = Wr[tid + 512], w3 = Wr[tid + 768];
#pragma unroll
        for (int tt = 0; tt < 8; tt++) {
            float f = feats[tt][k];
            acc[tt][0] += f * w0; acc[tt][1] += f * w1;
            acc[tt][2] += f * w2; acc[tt][3] += f * w3;
        }
    }
#pragma unroll
    for (int tt = 0; tt < 8; tt++) {
        float* dr = g_drive + ((size_t)b * NT + t0 + tt) * NN;
        dr[tid] = acc[tt][0]; dr[tid + 256] = acc[tt][1];
        dr[tid + 512] = acc[tt][2]; dr[tid + 768] = acc[tt][3];
    }
}

__device__ __forceinline__ void grid_barrier(unsigned phase) {
    __syncthreads();
    __threadfence();
    if (threadIdx.x == 0)
        *(volatile unsigned*)&g_flags[blockIdx.x * 32] = phase;
    if (threadIdx.x < RNN_NCTA) {
        volatile unsigned* f = &g_flags[threadIdx.x * 32];
        while (*f < phase) { }
    }
    __threadfence();
    __syncthreads();
}

__global__ void __launch_bounds__(256, 1) rnn_kernel(const float* __restrict__ rec_b,
                                                     const float* __restrict__ init_state) {
    const int tid = threadIdx.x;
    const int nloc = tid & 31;
    const int n = blockIdx.x * 32 + nloc;
    const int wrp = tid >> 5;

    const float rb = rec_b[n];
    const int cnt = g_nnz_cnt[n];
    const int CMAX = 4;
    int kk[CMAX]; float ww[CMAX];
    const int cr = cnt < CMAX ? cnt : CMAX;
    for (int j = 0; j < cr; j++) {
        kk[j] = g_nnz_idx[(size_t)n * NN + j];
        ww[j] = g_nnz_val[(size_t)n * NN + j];
    }

    const float h0v = init_state[n];
#pragma unroll
    for (int i = 0; i < 8; i++) g_h[0][(wrp + 8 * i) * NN + n] = h0v;
    grid_barrier(1u);

    float d[8];
#pragma unroll
    for (int i = 0; i < 8; i++)
        d[i] = g_drive[((size_t)(wrp + 8 * i) * NT) * NN + n];

    for (int t = 0; t < NT; t++) {
        const float* hp = g_h[t & 1];
        float* hn = g_h[(t + 1) & 1];
        float acc[8];
#pragma unroll
        for (int i = 0; i < 8; i++) acc[i] = rb + d[i];

        for (int j = 0; j < cr; j++) {
            int k = kk[j]; float wv = ww[j];
#pragma unroll
            for (int i = 0; i < 8; i++)
                acc[i] += __ldcg(hp + (wrp + 8 * i) * NN + k) * wv;
        }
        for (int j = CMAX; j < cnt; j++) {
            int k = g_nnz_idx[(size_t)n * NN + j];
            float wv = g_nnz_val[(size_t)n * NN + j];
#pragma unroll
            for (int i = 0; i < 8; i++)
                acc[i] += __ldcg(hp + (wrp + 8 * i) * NN + k) * wv;
        }

#pragma unroll
        for (int i = 0; i < 8; i++) {
            int b = wrp + 8 * i;
            float hv = fmaxf(acc[i], 0.0f);
            hn[b * NN + n] = hv;
            g_hs[((size_t)b * NT + t) * NN + n] = hv;
        }
        if (t + 1 < NT) {
#pragma unroll
            for (int i = 0; i < 8; i++)
                d[i] = g_drive[((size_t)(wrp + 8 * i) * NT + (t + 1)) * NN + n];
        }
        grid_barrier((unsigned)(t + 2));
    }
}

__global__ void __launch_bounds__(256) outgemm_kernel(const float* __restrict__ outW,
                                                      const float* __restrict__ outB) {
    __shared__ float As[32][68];
    __shared__ float Bs[32][64];

    const int n0 = blockIdx.x * 64;
    const int row0 = blockIdx.y * 64;
    const int tid = threadIdx.x;

    const int la_k = (tid & 7) * 4;
    const int la_m = tid >> 3;
    const int lb_n = (tid & 15) * 4;
    const int lb_k = tid >> 4;
    const int tm = (tid >> 4) * 4;
    const int tn = (tid & 15) * 4;

    unsigned long long acc[4][2];
#pragma unroll
    for (int i = 0; i < 4; i++) { acc[i][0] = 0ull; acc[i][1] = 0ull; }

    for (int k0 = 0; k0 < NN; k0 += 32) {
#pragma unroll
        for (int mm = 0; mm < 2; mm++) {
            int m = la_m + 32 * mm;
            float4 v = *(const float4*)(g_hs + (size_t)(row0 + m) * NN + k0 + la_k);
            As[la_k + 0][m] = v.x; As[la_k + 1][m] = v.y;
            As[la_k + 2][m] = v.z; As[la_k + 3][m] = v.w;
        }
#pragma unroll
        for (int kk2 = 0; kk2 < 2; kk2++) {
            int k = lb_k + 16 * kk2;
            *(float4*)&Bs[k][lb_n] = *(const float4*)(outW + (size_t)(k0 + k) * NO + n0 + lb_n);
        }
        __syncthreads();
#pragma unroll
        for (int k = 0; k < 32; k++) {
            float4 a = *(const float4*)&As[k][tm];
            float4 bq = *(const float4*)&Bs[k][tn];
            unsigned long long b0 = pack2(bq.x, bq.y);
            unsigned long long b1 = pack2(bq.z, bq.w);
            float av[4] = {a.x, a.y, a.z, a.w};
#pragma unroll
            for (int i = 0; i < 4; i++) {
                unsigned long long a2 = pack2(av[i], av[i]);
                acc[i][0] = fma2(a2, b0, acc[i][0]);
                acc[i][1] = fma2(a2, b1, acc[i][1]);
            }
        }
        __syncthreads();
    }

    float bb[4];
#pragma unroll
    for (int i = 0; i < 4; i++) bb[i] = outB[n0 + tn + i];
#pragma unroll
    for (int i = 0; i < 4; i++) {
        float x0, x1, y0, y1;
        unpack2(acc[i][0], x0, x1);
        unpack2(acc[i][1], y0, y1);
        float4 o;
        o.x = fmaxf(x0 + bb[0], 0.0f);
        o.y = fmaxf(x1 + bb[1], 0.0f);
        o.z = fmaxf(y0 + bb[2], 0.0f);
        o.w = fmaxf(y1 + bb[3], 0.0f);
        *(float4*)(g_out + (size_t)(row0 + tm + i) * NO + n0 + tn) = o;
    }
}

__global__ void __launch_bounds__(512) centers_kernel(const float* __restrict__ r) {
    const int b = blockIdx.x;
    const int n = threadIdx.x;
    float m = -1e30f, s = 0.0f, c0 = 0.0f, c1 = 0.0f;
    const float* ob = g_out + (size_t)b * NT * NO;
    const float* rb = r + (size_t)b * NT * 2;
    for (int t = 0; t < NT; t++) {
        float v = ob[(size_t)t * NO + n];
        float r0 = rb[t * 2 + 0], r1 = rb[t * 2 + 1];
        if (v > m) {
            float f = expf(m - v);
            s = s * f + 1.0f; c0 = c0 * f + r0; c1 = c1 * f + r1; m = v;
        } else {
            float p = expf(v - m);
            s += p; c0 += p * r0; c1 += p * r1;
        }
    }
    float inv = 1.0f / s;
    g_centers[((size_t)b * NO + n) * 2 + 0] = c0 * inv;
    g_centers[((size_t)b * NO + n) * 2 + 1] = c1 * inv;
}

__global__ void __launch_bounds__(256) final_kernel(float* __restrict__ outp) {
    const int wrp = threadIdx.x >> 5;
    const int lane = threadIdx.x & 31;
    const int row = blockIdx.x * 8 + wrp;   // row = b*NT + t
    const int b = row >> 8;
    const float* o = g_out + (size_t)row * NO;

    float v[16];
    float vmax = -1e30f;
#pragma unroll
    for (int i = 0; i < 16; i++) {
        v[i] = o[lane + 32 * i];
        vmax = fmaxf(vmax, v[i]);
    }
#pragma unroll
    for (int off = 16; off; off >>= 1)
        vmax = fmaxf(vmax, __shfl_xor_sync(0xffffffffu, vmax, off));

    float s = 0.0f, a0 = 0.0f, a1 = 0.0f;
    const float* cen = g_centers + (size_t)b * NO * 2;
#pragma unroll
    for (int i = 0; i < 16; i++) {
        int n = lane + 32 * i;
        float p = expf(v[i] - vmax);
        s += p;
        float2 c = *(const float2*)(cen + n * 2);
        a0 += p * c.x; a1 += p * c.y;
    }
#pragma unroll
    for (int off = 16; off; off >>= 1) {
        s  += __shfl_xor_sync(0xffffffffu, s, off);
        a0 += __shfl_xor_sync(0xffffffffu, a0, off);
        a1 += __shfl_xor_sync(0xffffffffu, a1, off);
    }
    if (lane == 0) {
        float inv = 1.0f / s;
        outp[row * 2 + 0] = a0 * inv;
        outp[row * 2 + 1] = a1 * inv;
    }
}

extern "C" void kernel_launch(void* const* d_in, const int* in_sizes, int n_in,
                              void* d_out, int out_size) {
    const float* x    = (const float*)d_in[0];
    const float* r    = (const float*)d_in[1];
    const float* sW   = (const float*)d_in[2];
    const float* hW   = (const float*)d_in[3];
    const float* recW = (const float*)d_in[4];
    const float* recb = (const float*)d_in[5];
    const float* outW = (const float*)d_in[6];
    const float* outb = (const float*)d_in[7];
    const float* init = (const float*)d_in[8];
    float* outp = (float*)d_out;

    reset_flags_kernel<<<1, 1024>>>();
    build_csc_kernel<<<NN / 256, 256>>>(recW);
    {
        dim3 g(NT / 8, NB);
        drive_kernel<<<g, 256>>>(x, sW, hW);
    }
    rnn_kernel<<<RNN_NCTA, 256>>>(recb, init);
    {
        dim3 g(NO / 64, (NB * NT) / 64);
        outgemm_kernel<<<g, 256>>>(outW, outb);
    }
    centers_kernel<<<NB, 512>>>(r);
    final_kernel<<<(NB * NT) / 8, 256>>>(outp);
}

// round 3
// speedup vs baseline: 1.1594x; 1.1594x over previous
#include <cuda_runtime.h>
#include <math.h>
#include <stdint.h>

#define NB 64
#define NT 256
#define NN 1024
#define NO 512
#define NK_SPEED 20
#define NK_HD 50
#define NK_TOT 70
#define CMAX 4

__device__ float g_drive[(size_t)NB * NT * NN];
__device__ float g_hs[(size_t)NB * NT * NN];
__device__ float g_out[(size_t)NB * NT * NO];
__device__ float g_centers[NB * NO * 2];
__device__ int   g_nnz_cnt[NN];
__device__ int   g_nnz_idx[(size_t)NN * NN];
__device__ float g_nnz_val[(size_t)NN * NN];

__device__ __forceinline__ unsigned long long pack2(float lo, float hi) {
    unsigned long long o;
    asm("mov.b64 %0, {%1, %2};" : "=l"(o) : "r"(__float_as_uint(lo)), "r"(__float_as_uint(hi)));
    return o;
}
__device__ __forceinline__ void unpack2(unsigned long long v, float& lo, float& hi) {
    unsigned a, b;
    asm("mov.b64 {%0, %1}, %2;" : "=r"(a), "=r"(b) : "l"(v));
    lo = __uint_as_float(a); hi = __uint_as_float(b);
}
__device__ __forceinline__ unsigned long long fma2(unsigned long long a, unsigned long long b, unsigned long long c) {
    unsigned long long d;
    asm("fma.rn.f32x2 %0, %1, %2, %3;" : "=l"(d) : "l"(a), "l"(b), "l"(c));
    return d;
}

// ---------------- CSC of rec_W (general; nnz=1/col at identity init) -------
__global__ void build_csc_kernel(const float* __restrict__ recW) {
    int n = blockIdx.x * blockDim.x + threadIdx.x;
    if (n >= NN) return;
    int cnt = 0;
    for (int k = 0; k < NN; k++) {
        float w = recW[(size_t)k * NN + n];
        if (w != 0.0f) {
            g_nnz_idx[(size_t)n * NN + cnt] = k;
            g_nnz_val[(size_t)n * NN + cnt] = w;
            cnt++;
        }
    }
    g_nnz_cnt[n] = cnt;
}

// ---------------- input drive: feats(x) @ [speed_W; hd_W] ------------------
// grid (NT/32, NB), 512 threads; each thread: 2 n-cols x 32 timesteps.
__global__ void __launch_bounds__(512) drive_kernel(const float* __restrict__ x,
                                                    const float* __restrict__ sW,
                                                    const float* __restrict__ hW) {
    __shared__ float feats[32][NK_TOT];
    const int b = blockIdx.y;
    const int t0 = blockIdx.x * 32;
    const int tid = threadIdx.x;
    const float TWO_PI = 6.2831853071795865f;
    const float LOGNORM = 6.3050317f;  // log(2*pi*I0(2*pi))

    for (int i = tid; i < 32 * NK_TOT; i += 512) {
        int tl = i / NK_TOT, k = i - tl * NK_TOT;
        int t = t0 + tl;
        float f;
        if (k < NK_SPEED) {
            float v = x[((size_t)b * NT + t) * 2 + 0];
            float dv = v - 0.5f * (float)k / 19.0f;
            f = expf(-800.0f * dv * dv);
        } else {
            float th = x[((size_t)b * NT + t) * 2 + 1];
            float c = TWO_PI * (float)(k - NK_SPEED) / 49.0f;
            f = expf(TWO_PI * cosf(th - c) - LOGNORM);
        }
        feats[tl][k] = f;
    }
    __syncthreads();

    float acc[32][2];
#pragma unroll
    for (int tt = 0; tt < 32; tt++) { acc[tt][0] = 0.0f; acc[tt][1] = 0.0f; }

    for (int k = 0; k < NK_TOT; k++) {
        const float* __restrict__ Wr = (k < NK_SPEED) ? (sW + (size_t)k * NN)
                                                      : (hW + (size_t)(k - NK_SPEED) * NN);
        float w0 = Wr[tid], w1 = Wr[tid + 512];
#pragma unroll
        for (int tt = 0; tt < 32; tt++) {
            float f = feats[tt][k];
            acc[tt][0] += f * w0;
            acc[tt][1] += f * w1;
        }
    }
#pragma unroll
    for (int tt = 0; tt < 32; tt++) {
        float* dr = g_drive + ((size_t)b * NT + t0 + tt) * NN;
        dr[tid] = acc[tt][0];
        dr[tid + 512] = acc[tt][1];
    }
}

// ---------------- RNN scan: one CTA per batch, h in SMEM, 1 bar/step -------
__global__ void __launch_bounds__(256, 1) rnn_kernel(const float* __restrict__ rec_b,
                                                     const float* __restrict__ init_state) {
    __shared__ float hbuf[2][NN];
    const int b = blockIdx.x;
    const int tid = threadIdx.x;

    float rb[4]; int cr[4]; int kk[4][CMAX]; float ww[4][CMAX]; int cnt[4];
#pragma unroll
    for (int i = 0; i < 4; i++) {
        int n = tid + 256 * i;
        rb[i] = rec_b[n];
        cnt[i] = g_nnz_cnt[n];
        cr[i] = cnt[i] < CMAX ? cnt[i] : CMAX;
        for (int j = 0; j < cr[i]; j++) {
            kk[i][j] = g_nnz_idx[(size_t)n * NN + j];
            ww[i][j] = g_nnz_val[(size_t)n * NN + j];
        }
        hbuf[0][n] = init_state[n];
    }
    __syncthreads();

    float d[4];
#pragma unroll
    for (int i = 0; i < 4; i++)
        d[i] = g_drive[(size_t)b * NT * NN + tid + 256 * i];

    for (int t = 0; t < NT; t++) {
        const float* cur = hbuf[t & 1];
        float* nxt = hbuf[(t + 1) & 1];
        float dn[4];
        if (t + 1 < NT) {
#pragma unroll
            for (int i = 0; i < 4; i++)
                dn[i] = g_drive[((size_t)b * NT + t + 1) * NN + tid + 256 * i];
        }
        float* hsrow = g_hs + ((size_t)b * NT + t) * NN;
#pragma unroll
        for (int i = 0; i < 4; i++) {
            int n = tid + 256 * i;
            float acc = rb[i] + d[i];
            for (int j = 0; j < cr[i]; j++)
                acc += cur[kk[i][j]] * ww[i][j];
            for (int j = CMAX; j < cnt[i]; j++)   // general dense fallback
                acc += cur[g_nnz_idx[(size_t)n * NN + j]] * g_nnz_val[(size_t)n * NN + j];
            float hv = fmaxf(acc, 0.0f);
            nxt[n] = hv;
            hsrow[n] = hv;
        }
        __syncthreads();
#pragma unroll
        for (int i = 0; i < 4; i++) d[i] = dn[i];
    }
}

// ---------------- out = relu(hs @ out_W + out_b), 128x64 tiles, f32x2 ------
__global__ void __launch_bounds__(256) outgemm_kernel(const float* __restrict__ outW,
                                                      const float* __restrict__ outB) {
    __shared__ float As[32][130];                  // [k][m], padded
    __shared__ unsigned long long Bs2[32][64];     // [k][n] pre-duplicated (w,w)

    const int n0 = blockIdx.x * 64;
    const int row0 = blockIdx.y * 128;
    const int tid = threadIdx.x;

    const int la_k = (tid & 7) * 4;   // 0..28
    const int la_m = tid >> 3;        // 0..31
    const int lb_n = (tid & 15) * 4;  // 0..60
    const int lb_k = tid >> 4;        // 0..15
    const int tm = (tid >> 4) * 8;    // 0..120
    const int tn = (tid & 15) * 4;    // 0..60

    unsigned long long acc[4][4];
#pragma unroll
    for (int i = 0; i < 4; i++)
#pragma unroll
        for (int j = 0; j < 4; j++) acc[i][j] = 0ull;

    for (int k0 = 0; k0 < NN; k0 += 32) {
#pragma unroll
        for (int mm = 0; mm < 4; mm++) {
            int m = la_m + 32 * mm;
            float4 v = *(const float4*)(g_hs + (size_t)(row0 + m) * NN + k0 + la_k);
            As[la_k + 0][m] = v.x; As[la_k + 1][m] = v.y;
            As[la_k + 2][m] = v.z; As[la_k + 3][m] = v.w;
        }
#pragma unroll
        for (int kc = 0; kc < 2; kc++) {
            int k = lb_k + 16 * kc;
            float4 w = *(const float4*)(outW + (size_t)(k0 + k) * NO + n0 + lb_n);
            Bs2[k][lb_n + 0] = pack2(w.x, w.x);
            Bs2[k][lb_n + 1] = pack2(w.y, w.y);
            Bs2[k][lb_n + 2] = pack2(w.z, w.z);
            Bs2[k][lb_n + 3] = pack2(w.w, w.w);
        }
        __syncthreads();
#pragma unroll
        for (int k = 0; k < 32; k++) {
            unsigned long long a2[4], b2[4];
#pragma unroll
            for (int mp = 0; mp < 4; mp++)
                a2[mp] = *(const unsigned long long*)&As[k][tm + 2 * mp];
#pragma unroll
            for (int nj = 0; nj < 4; nj++)
                b2[nj] = Bs2[k][tn + nj];
#pragma unroll
            for (int mp = 0; mp < 4; mp++)
#pragma unroll
                for (int nj = 0; nj < 4; nj++)
                    acc[mp][nj] = fma2(a2[mp], b2[nj], acc[mp][nj]);
        }
        __syncthreads();
    }

    float bb[4];
#pragma unroll
    for (int j = 0; j < 4; j++) bb[j] = outB[n0 + tn + j];
#pragma unroll
    for (int mp = 0; mp < 4; mp++) {
        float lo[4], hi[4];
#pragma unroll
        for (int j = 0; j < 4; j++) unpack2(acc[mp][j], lo[j], hi[j]);
        float4 o0, o1;
        o0.x = fmaxf(lo[0] + bb[0], 0.0f); o0.y = fmaxf(lo[1] + bb[1], 0.0f);
        o0.z = fmaxf(lo[2] + bb[2], 0.0f); o0.w = fmaxf(lo[3] + bb[3], 0.0f);
        o1.x = fmaxf(hi[0] + bb[0], 0.0f); o1.y = fmaxf(hi[1] + bb[1], 0.0f);
        o1.z = fmaxf(hi[2] + bb[2], 0.0f); o1.w = fmaxf(hi[3] + bb[3], 0.0f);
        *(float4*)(g_out + (size_t)(row0 + tm + 2 * mp + 0) * NO + n0 + tn) = o0;
        *(float4*)(g_out + (size_t)(row0 + tm + 2 * mp + 1) * NO + n0 + tn) = o1;
    }
}

// ---------------- time-softmax -> centers ----------------------------------
__global__ void __launch_bounds__(512) centers_kernel(const float* __restrict__ r) {
    const int b = blockIdx.x;
    const int n = threadIdx.x;
    float m = -1e30f, s = 0.0f, c0 = 0.0f, c1 = 0.0f;
    const float* ob = g_out + (size_t)b * NT * NO;
    const float* rb = r + (size_t)b * NT * 2;
    for (int t = 0; t < NT; t++) {
        float v = ob[(size_t)t * NO + n];
        float r0 = rb[t * 2 + 0], r1 = rb[t * 2 + 1];
        if (v > m) {
            float f = expf(m - v);
            s = s * f + 1.0f; c0 = c0 * f + r0; c1 = c1 * f + r1; m = v;
        } else {
            float p = expf(v - m);
            s += p; c0 += p * r0; c1 += p * r1;
        }
    }
    float inv = 1.0f / s;
    g_centers[((size_t)b * NO + n) * 2 + 0] = c0 * inv;
    g_centers[((size_t)b * NO + n) * 2 + 1] = c1 * inv;
}

// ---------------- cell-softmax -> expected position ------------------------
__global__ void __launch_bounds__(256) final_kernel(float* __restrict__ outp) {
    const int wrp = threadIdx.x >> 5;
    const int lane = threadIdx.x & 31;
    const int row = blockIdx.x * 8 + wrp;   // row = b*NT + t
    const int b = row >> 8;
    const float* o = g_out + (size_t)row * NO;

    float v[16];
    float vmax = -1e30f;
#pragma unroll
    for (int i = 0; i < 16; i++) {
        v[i] = o[lane + 32 * i];
        vmax = fmaxf(vmax, v[i]);
    }
#pragma unroll
    for (int off = 16; off; off >>= 1)
        vmax = fmaxf(vmax, __shfl_xor_sync(0xffffffffu, vmax, off));

    float s = 0.0f, a0 = 0.0f, a1 = 0.0f;
    const float* cen = g_centers + (size_t)b * NO * 2;
#pragma unroll
    for (int i = 0; i < 16; i++) {
        int n = lane + 32 * i;
        float p = expf(v[i] - vmax);
        s += p;
        float2 c = *(const float2*)(cen + n * 2);
        a0 += p * c.x; a1 += p * c.y;
    }
#pragma unroll
    for (int off = 16; off; off >>= 1) {
        s  += __shfl_xor_sync(0xffffffffu, s, off);
        a0 += __shfl_xor_sync(0xffffffffu, a0, off);
        a1 += __shfl_xor_sync(0xffffffffu, a1, off);
    }
    if (lane == 0) {
        float inv = 1.0f / s;
        outp[row * 2 + 0] = a0 * inv;
        outp[row * 2 + 1] = a1 * inv;
    }
}

extern "C" void kernel_launch(void* const* d_in, const int* in_sizes, int n_in,
                              void* d_out, int out_size) {
    const float* x    = (const float*)d_in[0];
    const float* r    = (const float*)d_in[1];
    const float* sW   = (const float*)d_in[2];
    const float* hW   = (const float*)d_in[3];
    const float* recW = (const float*)d_in[4];
    const float* recb = (const float*)d_in[5];
    const float* outW = (const float*)d_in[6];
    const float* outb = (const float*)d_in[7];
    const float* init = (const float*)d_in[8];
    float* outp = (float*)d_out;

    build_csc_kernel<<<NN / 256, 256>>>(recW);
    {
        dim3 g(NT / 32, NB);
        drive_kernel<<<g, 512>>>(x, sW, hW);
    }
    rnn_kernel<<<NB, 256>>>(recb, init);
    {
        dim3 g(NO / 64, (NB * NT) / 128);
        outgemm_kernel<<<g, 256>>>(outW, outb);
    }
    centers_kernel<<<NB, 512>>>(r);
    final_kernel<<<(NB * NT) / 8, 256>>>(outp);
}

// round 4
// speedup vs baseline: 1.5525x; 1.3391x over previous
#include <cuda_runtime.h>
#include <math.h>
#include <stdint.h>

#define NB 64
#define NT 256
#define NN 1024
#define NO 512
#define NK_SPEED 20
#define NK_HD 50
#define NK_TOT 70
#define CMAX 4

__device__ float g_drive[(size_t)NB * NT * NN];
__device__ float g_hs[(size_t)NB * NT * NN];
__device__ float g_out[(size_t)NB * NT * NO];
__device__ float g_centers[NB * NO * 2];
__device__ int   g_nnz_cnt[NN];
__device__ int   g_nnz_idx[(size_t)NN * NN];
__device__ float g_nnz_val[(size_t)NN * NN];

__device__ __forceinline__ unsigned long long pack2(float lo, float hi) {
    unsigned long long o;
    asm("mov.b64 %0, {%1, %2};" : "=l"(o) : "r"(__float_as_uint(lo)), "r"(__float_as_uint(hi)));
    return o;
}
__device__ __forceinline__ void unpack2(unsigned long long v, float& lo, float& hi) {
    unsigned a, b;
    asm("mov.b64 {%0, %1}, %2;" : "=r"(a), "=r"(b) : "l"(v));
    lo = __uint_as_float(a); hi = __uint_as_float(b);
}
__device__ __forceinline__ unsigned long long fma2(unsigned long long a, unsigned long long b, unsigned long long c) {
    unsigned long long d;
    asm("fma.rn.f32x2 %0, %1, %2, %3;" : "=l"(d) : "l"(a), "l"(b), "l"(c));
    return d;
}

// ---------------- CSC of rec_W: warp-per-column ballot compaction ----------
__global__ void __launch_bounds__(256) build_csc_kernel(const float* __restrict__ recW) {
    const int n = (blockIdx.x * blockDim.x + threadIdx.x) >> 5;   // column
    const int lane = threadIdx.x & 31;
    if (n >= NN) return;
    int cnt = 0;
    for (int k0 = 0; k0 < NN; k0 += 32) {
        float w = recW[(size_t)(k0 + lane) * NN + n];
        unsigned mask = __ballot_sync(0xffffffffu, w != 0.0f);
        if (w != 0.0f) {
            int off = __popc(mask & ((1u << lane) - 1u));
            g_nnz_idx[(size_t)n * NN + cnt + off] = k0 + lane;
            g_nnz_val[(size_t)n * NN + cnt + off] = w;
        }
        cnt += __popc(mask);
    }
    if (lane == 0) g_nnz_cnt[n] = cnt;
}

// ---------------- input drive: feats(x) @ [speed_W; hd_W] ------------------
__global__ void __launch_bounds__(512) drive_kernel(const float* __restrict__ x,
                                                    const float* __restrict__ sW,
                                                    const float* __restrict__ hW) {
    __shared__ float feats[32][NK_TOT];
    const int b = blockIdx.y;
    const int t0 = blockIdx.x * 32;
    const int tid = threadIdx.x;
    const float TWO_PI = 6.2831853071795865f;
    const float LOGNORM = 6.3050317f;  // log(2*pi*I0(2*pi))

    for (int i = tid; i < 32 * NK_TOT; i += 512) {
        int tl = i / NK_TOT, k = i - tl * NK_TOT;
        int t = t0 + tl;
        float f;
        if (k < NK_SPEED) {
            float v = x[((size_t)b * NT + t) * 2 + 0];
            float dv = v - 0.5f * (float)k / 19.0f;
            f = expf(-800.0f * dv * dv);
        } else {
            float th = x[((size_t)b * NT + t) * 2 + 1];
            float c = TWO_PI * (float)(k - NK_SPEED) / 49.0f;
            f = expf(TWO_PI * cosf(th - c) - LOGNORM);
        }
        feats[tl][k] = f;
    }
    __syncthreads();

    float acc[32][2];
#pragma unroll
    for (int tt = 0; tt < 32; tt++) { acc[tt][0] = 0.0f; acc[tt][1] = 0.0f; }

    for (int k = 0; k < NK_TOT; k++) {
        const float* __restrict__ Wr = (k < NK_SPEED) ? (sW + (size_t)k * NN)
                                                      : (hW + (size_t)(k - NK_SPEED) * NN);
        float w0 = Wr[tid], w1 = Wr[tid + 512];
#pragma unroll
        for (int tt = 0; tt < 32; tt++) {
            float f = feats[tt][k];
            acc[tt][0] += f * w0;
            acc[tt][1] += f * w1;
        }
    }
#pragma unroll
    for (int tt = 0; tt < 32; tt++) {
        float* dr = g_drive + ((size_t)b * NT + t0 + tt) * NN;
        dr[tid] = acc[tt][0];
        dr[tid + 512] = acc[tt][1];
    }
}

// ---------------- RNN scan: one CTA per batch, h in SMEM -------------------
__global__ void __launch_bounds__(256, 1) rnn_kernel(const float* __restrict__ rec_b,
                                                     const float* __restrict__ init_state) {
    __shared__ float hbuf[2][NN];
    const int b = blockIdx.x;
    const int tid = threadIdx.x;

    float rb[4]; int cr[4]; int kk[4][CMAX]; float ww[4][CMAX]; int cnt[4];
#pragma unroll
    for (int i = 0; i < 4; i++) {
        int n = tid + 256 * i;
        rb[i] = rec_b[n];
        cnt[i] = g_nnz_cnt[n];
        cr[i] = cnt[i] < CMAX ? cnt[i] : CMAX;
        for (int j = 0; j < cr[i]; j++) {
            kk[i][j] = g_nnz_idx[(size_t)n * NN + j];
            ww[i][j] = g_nnz_val[(size_t)n * NN + j];
        }
        hbuf[0][n] = init_state[n];
    }
    __syncthreads();

    float d[4];
#pragma unroll
    for (int i = 0; i < 4; i++)
        d[i] = g_drive[(size_t)b * NT * NN + tid + 256 * i];

    for (int t = 0; t < NT; t++) {
        const float* cur = hbuf[t & 1];
        float* nxt = hbuf[(t + 1) & 1];
        float dn[4];
        if (t + 1 < NT) {
#pragma unroll
            for (int i = 0; i < 4; i++)
                dn[i] = g_drive[((size_t)b * NT + t + 1) * NN + tid + 256 * i];
        }
        float* hsrow = g_hs + ((size_t)b * NT + t) * NN;
#pragma unroll
        for (int i = 0; i < 4; i++) {
            int n = tid + 256 * i;
            float acc = rb[i] + d[i];
            for (int j = 0; j < cr[i]; j++)
                acc += cur[kk[i][j]] * ww[i][j];
            for (int j = CMAX; j < cnt[i]; j++)
                acc += cur[g_nnz_idx[(size_t)n * NN + j]] * g_nnz_val[(size_t)n * NN + j];
            float hv = fmaxf(acc, 0.0f);
            nxt[n] = hv;
            hsrow[n] = hv;
        }
        __syncthreads();
#pragma unroll
        for (int i = 0; i < 4; i++) d[i] = dn[i];
    }
}

// ---------------- out = relu(hs @ out_W + out_b), 128x128 tiles ------------
// acc packed along n: B operand is natural consecutive-n f32x2 (no dup).
__global__ void __launch_bounds__(256, 2) outgemm_kernel(const float* __restrict__ outW,
                                                         const float* __restrict__ outB) {
    __shared__ float As[32][132];   // [k][m]
    __shared__ float Bs[32][132];   // [k][n]

    const int n0 = blockIdx.x * 128;
    const int row0 = blockIdx.y * 128;
    const int tid = threadIdx.x;

    const int al_m = tid >> 1;          // 0..127
    const int al_k = (tid & 1) * 16;    // 0 / 16
    const int bl_k = tid >> 3;          // 0..31
    const int bl_n = (tid & 7) * 16;    // 0..112

    const int tm = (tid >> 4) * 8;      // 0..120
    const int tn = (tid & 15) * 8;      // 0..120

    unsigned long long acc[8][4];
#pragma unroll
    for (int i = 0; i < 8; i++)
#pragma unroll
        for (int j = 0; j < 4; j++) acc[i][j] = 0ull;

    for (int k0 = 0; k0 < NN; k0 += 32) {
        const float* arow = g_hs + (size_t)(row0 + al_m) * NN + k0 + al_k;
#pragma unroll
        for (int q = 0; q < 4; q++) {
            float4 v = *(const float4*)(arow + 4 * q);
            As[al_k + 4 * q + 0][al_m] = v.x;
            As[al_k + 4 * q + 1][al_m] = v.y;
            As[al_k + 4 * q + 2][al_m] = v.z;
            As[al_k + 4 * q + 3][al_m] = v.w;
        }
        const float* brow = outW + (size_t)(k0 + bl_k) * NO + n0 + bl_n;
#pragma unroll
        for (int q = 0; q < 4; q++)
            *(float4*)&Bs[bl_k][bl_n + 4 * q] = *(const float4*)(brow + 4 * q);
        __syncthreads();

#pragma unroll
        for (int k = 0; k < 32; k++) {
            float4 a0 = *(const float4*)&As[k][tm];
            float4 a1 = *(const float4*)&As[k][tm + 4];
            ulonglong2 bA = *(const ulonglong2*)&Bs[k][tn];
            ulonglong2 bB = *(const ulonglong2*)&Bs[k][tn + 4];
            unsigned long long b2[4] = {bA.x, bA.y, bB.x, bB.y};
            float am[8] = {a0.x, a0.y, a0.z, a0.w, a1.x, a1.y, a1.z, a1.w};
#pragma unroll
            for (int m = 0; m < 8; m++) {
                unsigned long long a2 = pack2(am[m], am[m]);
#pragma unroll
                for (int j = 0; j < 4; j++)
                    acc[m][j] = fma2(a2, b2[j], acc[m][j]);
            }
        }
        __syncthreads();
    }

    float bb[8];
#pragma unroll
    for (int j = 0; j < 8; j++) bb[j] = outB[n0 + tn + j];
#pragma unroll
    for (int m = 0; m < 8; m++) {
        float v[8];
#pragma unroll
        for (int j = 0; j < 4; j++) unpack2(acc[m][j], v[2 * j], v[2 * j + 1]);
        float4 o0, o1;
        o0.x = fmaxf(v[0] + bb[0], 0.0f); o0.y = fmaxf(v[1] + bb[1], 0.0f);
        o0.z = fmaxf(v[2] + bb[2], 0.0f); o0.w = fmaxf(v[3] + bb[3], 0.0f);
        o1.x = fmaxf(v[4] + bb[4], 0.0f); o1.y = fmaxf(v[5] + bb[5], 0.0f);
        o1.z = fmaxf(v[6] + bb[6], 0.0f); o1.w = fmaxf(v[7] + bb[7], 0.0f);
        float* orow = g_out + (size_t)(row0 + tm + m) * NO + n0 + tn;
        *(float4*)(orow + 0) = o0;
        *(float4*)(orow + 4) = o1;
    }
}

// ---------------- time-softmax -> centers ----------------------------------
__global__ void __launch_bounds__(512) centers_kernel(const float* __restrict__ r) {
    const int b = blockIdx.x;
    const int n = threadIdx.x;
    float m = -1e30f, s = 0.0f, c0 = 0.0f, c1 = 0.0f;
    const float* ob = g_out + (size_t)b * NT * NO;
    const float* rb = r + (size_t)b * NT * 2;
    for (int t = 0; t < NT; t++) {
        float v = ob[(size_t)t * NO + n];
        float r0 = rb[t * 2 + 0], r1 = rb[t * 2 + 1];
        if (v > m) {
            float f = expf(m - v);
            s = s * f + 1.0f; c0 = c0 * f + r0; c1 = c1 * f + r1; m = v;
        } else {
            float p = expf(v - m);
            s += p; c0 += p * r0; c1 += p * r1;
        }
    }
    float inv = 1.0f / s;
    g_centers[((size_t)b * NO + n) * 2 + 0] = c0 * inv;
    g_centers[((size_t)b * NO + n) * 2 + 1] = c1 * inv;
}

// ---------------- cell-softmax -> expected position ------------------------
__global__ void __launch_bounds__(256) final_kernel(float* __restrict__ outp) {
    const int wrp = threadIdx.x >> 5;
    const int lane = threadIdx.x & 31;
    const int row = blockIdx.x * 8 + wrp;   // row = b*NT + t
    const int b = row >> 8;
    const float* o = g_out + (size_t)row * NO;

    float v[16];
    float vmax = -1e30f;
#pragma unroll
    for (int i = 0; i < 16; i++) {
        v[i] = o[lane + 32 * i];
        vmax = fmaxf(vmax, v[i]);
    }
#pragma unroll
    for (int off = 16; off; off >>= 1)
        vmax = fmaxf(vmax, __shfl_xor_sync(0xffffffffu, vmax, off));

    float s = 0.0f, a0 = 0.0f, a1 = 0.0f;
    const float* cen = g_centers + (size_t)b * NO * 2;
#pragma unroll
    for (int i = 0; i < 16; i++) {
        int n = lane + 32 * i;
        float p = expf(v[i] - vmax);
        s += p;
        float2 c = *(const float2*)(cen + n * 2);
        a0 += p * c.x; a1 += p * c.y;
    }
#pragma unroll
    for (int off = 16; off; off >>= 1) {
        s  += __shfl_xor_sync(0xffffffffu, s, off);
        a0 += __shfl_xor_sync(0xffffffffu, a0, off);
        a1 += __shfl_xor_sync(0xffffffffu, a1, off);
    }
    if (lane == 0) {
        float inv = 1.0f / s;
        outp[row * 2 + 0] = a0 * inv;
        outp[row * 2 + 1] = a1 * inv;
    }
}

extern "C" void kernel_launch(void* const* d_in, const int* in_sizes, int n_in,
                              void* d_out, int out_size) {
    const float* x    = (const float*)d_in[0];
    const float* r    = (const float*)d_in[1];
    const float* sW   = (const float*)d_in[2];
    const float* hW   = (const float*)d_in[3];
    const float* recW = (const float*)d_in[4];
    const float* recb = (const float*)d_in[5];
    const float* outW = (const float*)d_in[6];
    const float* outb = (const float*)d_in[7];
    const float* init = (const float*)d_in[8];
    float* outp = (float*)d_out;

    build_csc_kernel<<<(NN * 32) / 256, 256>>>(recW);
    {
        dim3 g(NT / 32, NB);
        drive_kernel<<<g, 512>>>(x, sW, hW);
    }
    rnn_kernel<<<NB, 256>>>(recb, init);
    {
        dim3 g(NO / 128, (NB * NT) / 128);
        outgemm_kernel<<<g, 256>>>(outW, outb);
    }
    centers_kernel<<<NB, 512>>>(r);
    final_kernel<<<(NB * NT) / 8, 256>>>(outp);
}

// round 7
// speedup vs baseline: 1.7788x; 1.1457x over previous
#include <cuda_runtime.h>
#include <cuda_bf16.h>
#include <math.h>
#include <stdint.h>

#define NB 64
#define NT 256
#define NN 1024
#define NO 512
#define NK_SPEED 20
#define NK_HD 50
#define NK_TOT 70
#define CMAX 4

__device__ float          g_drive[(size_t)NB * NT * NN];
__device__ __nv_bfloat16  g_hs_hi[(size_t)NB * NT * NN];
__device__ __nv_bfloat16  g_hs_lo[(size_t)NB * NT * NN];
__device__ __nv_bfloat16  g_wt_hi[(size_t)NO * NN];
__device__ __nv_bfloat16  g_wt_lo[(size_t)NO * NN];
__device__ float          g_out[(size_t)NB * NT * NO];
__device__ float          g_centers[NB * NO * 2];
__device__ int            g_nnz_cnt[NN];
__device__ int            g_nnz_idx[(size_t)NN * NN];
__device__ float          g_nnz_val[(size_t)NN * NN];

// ---------------- CSC of rec_W (coalesced over columns) --------------------
__global__ void build_csc_kernel(const float* __restrict__ recW) {
    int n = blockIdx.x * blockDim.x + threadIdx.x;
    if (n >= NN) return;
    int cnt = 0;
    for (int k = 0; k < NN; k++) {
        float w = recW[(size_t)k * NN + n];
        if (w != 0.0f) {
            g_nnz_idx[(size_t)n * NN + cnt] = k;
            g_nnz_val[(size_t)n * NN + cnt] = w;
            cnt++;
        }
    }
    g_nnz_cnt[n] = cnt;
}

// ---------------- transpose + bf16-split out_W -> [NO][NN] -----------------
__global__ void __launch_bounds__(256) wsplit_kernel(const float* __restrict__ outW) {
    __shared__ float tile[32][33];
    const int k0 = blockIdx.x * 32, n0 = blockIdx.y * 32;
    const int tx = threadIdx.x & 31, ty = threadIdx.x >> 5;
#pragma unroll
    for (int i = 0; i < 4; i++)
        tile[ty + 8 * i][tx] = outW[(size_t)(k0 + ty + 8 * i) * NO + n0 + tx];
    __syncthreads();
#pragma unroll
    for (int i = 0; i < 4; i++) {
        int row = ty + 8 * i;                       // n-local
        float v = tile[tx][row];                    // outW[k0+tx][n0+row]
        __nv_bfloat16 hi = __float2bfloat16(v);
        __nv_bfloat16 lo = __float2bfloat16(v - __bfloat162float(hi));
        size_t o = (size_t)(n0 + row) * NN + k0 + tx;
        g_wt_hi[o] = hi;
        g_wt_lo[o] = lo;
    }
}

// ---------------- input drive ----------------------------------------------
__global__ void __launch_bounds__(512) drive_kernel(const float* __restrict__ x,
                                                    const float* __restrict__ sW,
                                                    const float* __restrict__ hW) {
    __shared__ float feats[32][NK_TOT];
    const int b = blockIdx.y;
    const int t0 = blockIdx.x * 32;
    const int tid = threadIdx.x;
    const float TWO_PI = 6.2831853071795865f;
    const float LOGNORM = 6.3050317f;  // log(2*pi*I0(2*pi))

    for (int i = tid; i < 32 * NK_TOT; i += 512) {
        int tl = i / NK_TOT, k = i - tl * NK_TOT;
        int t = t0 + tl;
        float f;
        if (k < NK_SPEED) {
            float v = x[((size_t)b * NT + t) * 2 + 0];
            float dv = v - 0.5f * (float)k / 19.0f;
            f = expf(-800.0f * dv * dv);
        } else {
            float th = x[((size_t)b * NT + t) * 2 + 1];
            float c = TWO_PI * (float)(k - NK_SPEED) / 49.0f;
            f = expf(TWO_PI * cosf(th - c) - LOGNORM);
        }
        feats[tl][k] = f;
    }
    __syncthreads();

    float acc[32][2];
#pragma unroll
    for (int tt = 0; tt < 32; tt++) { acc[tt][0] = 0.0f; acc[tt][1] = 0.0f; }

    for (int k = 0; k < NK_TOT; k++) {
        const float* __restrict__ Wr = (k < NK_SPEED) ? (sW + (size_t)k * NN)
                                                      : (hW + (size_t)(k - NK_SPEED) * NN);
        float w0 = Wr[tid], w1 = Wr[tid + 512];
#pragma unroll
        for (int tt = 0; tt < 32; tt++) {
            float f = feats[tt][k];
            acc[tt][0] += f * w0;
            acc[tt][1] += f * w1;
        }
    }
#pragma unroll
    for (int tt = 0; tt < 32; tt++) {
        float* dr = g_drive + ((size_t)b * NT + t0 + tt) * NN;
        dr[tid] = acc[tt][0];
        dr[tid + 512] = acc[tt][1];
    }
}

// ---------------- RNN scan: one CTA per batch, h in SMEM -------------------
__global__ void __launch_bounds__(256, 1) rnn_kernel(const float* __restrict__ rec_b,
                                                     const float* __restrict__ init_state) {
    __shared__ float hbuf[2][NN];
    const int b = blockIdx.x;
    const int tid = threadIdx.x;

    float rb[4]; int cr[4]; int kk[4][CMAX]; float ww[4][CMAX]; int cnt[4];
#pragma unroll
    for (int i = 0; i < 4; i++) {
        int n = tid + 256 * i;
        rb[i] = rec_b[n];
        cnt[i] = g_nnz_cnt[n];
        cr[i] = cnt[i] < CMAX ? cnt[i] : CMAX;
        for (int j = 0; j < cr[i]; j++) {
            kk[i][j] = g_nnz_idx[(size_t)n * NN + j];
            ww[i][j] = g_nnz_val[(size_t)n * NN + j];
        }
        hbuf[0][n] = init_state[n];
    }
    __syncthreads();

    float d[4];
#pragma unroll
    for (int i = 0; i < 4; i++)
        d[i] = g_drive[(size_t)b * NT * NN + tid + 256 * i];

    for (int t = 0; t < NT; t++) {
        const float* cur = hbuf[t & 1];
        float* nxt = hbuf[(t + 1) & 1];
        float dn[4];
        if (t + 1 < NT) {
#pragma unroll
            for (int i = 0; i < 4; i++)
                dn[i] = g_drive[((size_t)b * NT + t + 1) * NN + tid + 256 * i];
        }
        const size_t row = ((size_t)b * NT + t) * NN;
#pragma unroll
        for (int i = 0; i < 4; i++) {
            int n = tid + 256 * i;
            float acc = rb[i] + d[i];
            for (int j = 0; j < cr[i]; j++)
                acc += cur[kk[i][j]] * ww[i][j];
            for (int j = CMAX; j < cnt[i]; j++)
                acc += cur[g_nnz_idx[(size_t)n * NN + j]] * g_nnz_val[(size_t)n * NN + j];
            float hv = fmaxf(acc, 0.0f);
            nxt[n] = hv;
            __nv_bfloat16 hb = __float2bfloat16(hv);
            g_hs_hi[row + n] = hb;
            g_hs_lo[row + n] = __float2bfloat16(hv - __bfloat162float(hb));
        }
        __syncthreads();
#pragma unroll
        for (int i = 0; i < 4; i++) d[i] = dn[i];
    }
}

// ---------------- mma.sync bf16-split out-GEMM -----------------------------
// D = Ahi*Bhi + Ahi*Blo + Alo*Bhi via mma.sync.m16n8k16. CTA 128x128, K-chunk 64.
#define TS 72                          // padded k-stride (bf16 elems)
#define GEMM_SMEM (4 * 128 * TS * 2)   // Ahi,Alo,Bhi,Blo

__device__ __forceinline__ void mma_bf16(float* d, const uint32_t* a, const uint32_t* b) {
    asm volatile(
        "mma.sync.aligned.m16n8k16.row.col.f32.bf16.bf16.f32 "
        "{%0,%1,%2,%3}, {%4,%5,%6,%7}, {%8,%9}, {%0,%1,%2,%3};"
        : "+f"(d[0]), "+f"(d[1]), "+f"(d[2]), "+f"(d[3])
        : "r"(a[0]), "r"(a[1]), "r"(a[2]), "r"(a[3]), "r"(b[0]), "r"(b[1]));
}

__global__ void __launch_bounds__(256, 1) outgemm_mma_kernel(const float* __restrict__ outB) {
    extern __shared__ __nv_bfloat16 smem[];
    __nv_bfloat16* Ah = smem;
    __nv_bfloat16* Al = smem + 128 * TS;
    __nv_bfloat16* Bh = smem + 2 * 128 * TS;
    __nv_bfloat16* Bl = smem + 3 * 128 * TS;

    const int tid = threadIdx.x;
    const int wid = tid >> 5, lane = tid & 31;
    const int gid = lane >> 2, tig = lane & 3;
    const int wm = wid >> 2, wn = wid & 3;          // 2 x 4 warps
    const int n0 = blockIdx.x * 128;
    const int row0 = blockIdx.y * 128;

    float acc[4][4][4];
#pragma unroll
    for (int mt = 0; mt < 4; mt++)
#pragma unroll
        for (int nt = 0; nt < 4; nt++)
#pragma unroll
            for (int j = 0; j < 4; j++) acc[mt][nt][j] = 0.0f;

    const int srow = tid >> 1;           // 0..127 (2 threads per row)
    const int scol = (tid & 1) * 32;     // 0 / 32  (32 bf16 = 4 uint4)

    for (int c = 0; c < 16; c++) {
        const int k0 = c * 64;
        __syncthreads();
        {
            const size_t ga = (size_t)(row0 + srow) * NN + k0 + scol;
            const size_t gb = (size_t)(n0 + srow) * NN + k0 + scol;
            __nv_bfloat16* da = Ah + srow * TS + scol;
            __nv_bfloat16* dl = Al + srow * TS + scol;
            __nv_bfloat16* db = Bh + srow * TS + scol;
            __nv_bfloat16* dm = Bl + srow * TS + scol;
#pragma unroll
            for (int q = 0; q < 4; q++) {            // 4 x uint4 = 4 x 8 bf16 = 32 elems
                *(uint4*)(da + q * 8) = *(const uint4*)(g_hs_hi + ga + q * 8);
                *(uint4*)(dl + q * 8) = *(const uint4*)(g_hs_lo + ga + q * 8);
                *(uint4*)(db + q * 8) = *(const uint4*)(g_wt_hi + gb + q * 8);
                *(uint4*)(dm + q * 8) = *(const uint4*)(g_wt_lo + gb + q * 8);
            }
        }
        __syncthreads();

#pragma unroll
        for (int ks = 0; ks < 4; ks++) {
            const int kc = ks * 16 + tig * 2;
            uint32_t ahi[4][4], alo[4][4], bhi[4][2], blo[4][2];
#pragma unroll
            for (int mt = 0; mt < 4; mt++) {
                const int r = wm * 64 + mt * 16 + gid;
                ahi[mt][0] = *(const uint32_t*)(Ah + r * TS + kc);
                ahi[mt][1] = *(const uint32_t*)(Ah + (r + 8) * TS + kc);
                ahi[mt][2] = *(const uint32_t*)(Ah + r * TS + kc + 8);
                ahi[mt][3] = *(const uint32_t*)(Ah + (r + 8) * TS + kc + 8);
                alo[mt][0] = *(const uint32_t*)(Al + r * TS + kc);
                alo[mt][1] = *(const uint32_t*)(Al + (r + 8) * TS + kc);
                alo[mt][2] = *(const uint32_t*)(Al + r * TS + kc + 8);
                alo[mt][3] = *(const uint32_t*)(Al + (r + 8) * TS + kc + 8);
            }
#pragma unroll
            for (int nt = 0; nt < 4; nt++) {
                const int nr = wn * 32 + nt * 8 + gid;
                bhi[nt][0] = *(const uint32_t*)(Bh + nr * TS + kc);
                bhi[nt][1] = *(const uint32_t*)(Bh + nr * TS + kc + 8);
                blo[nt][0] = *(const uint32_t*)(Bl + nr * TS + kc);
                blo[nt][1] = *(const uint32_t*)(Bl + nr * TS + kc + 8);
            }
#pragma unroll
            for (int mt = 0; mt < 4; mt++)
#pragma unroll
                for (int nt = 0; nt < 4; nt++) {
                    mma_bf16(acc[mt][nt], ahi[mt], bhi[nt]);
                    mma_bf16(acc[mt][nt], ahi[mt], blo[nt]);
                    mma_bf16(acc[mt][nt], alo[mt], bhi[nt]);
                }
        }
    }

    // epilogue: bias + relu
#pragma unroll
    for (int nt = 0; nt < 4; nt++) {
        const int col = n0 + wn * 32 + nt * 8 + tig * 2;
        const float b0 = outB[col], b1 = outB[col + 1];
#pragma unroll
        for (int mt = 0; mt < 4; mt++) {
            const int r = row0 + wm * 64 + mt * 16 + gid;
            float2 o0, o1;
            o0.x = fmaxf(acc[mt][nt][0] + b0, 0.0f);
            o0.y = fmaxf(acc[mt][nt][1] + b1, 0.0f);
            o1.x = fmaxf(acc[mt][nt][2] + b0, 0.0f);
            o1.y = fmaxf(acc[mt][nt][3] + b1, 0.0f);
            *(float2*)(g_out + (size_t)r * NO + col) = o0;
            *(float2*)(g_out + (size_t)(r + 8) * NO + col) = o1;
        }
    }
}

// ---------------- time-softmax -> centers ----------------------------------
__global__ void __launch_bounds__(512) centers_kernel(const float* __restrict__ r) {
    const int b = blockIdx.x;
    const int n = threadIdx.x;
    float m = -1e30f, s = 0.0f, c0 = 0.0f, c1 = 0.0f;
    const float* ob = g_out + (size_t)b * NT * NO;
    const float* rb = r + (size_t)b * NT * 2;
    for (int t = 0; t < NT; t++) {
        float v = ob[(size_t)t * NO + n];
        float r0 = rb[t * 2 + 0], r1 = rb[t * 2 + 1];
        if (v > m) {
            float f = expf(m - v);
            s = s * f + 1.0f; c0 = c0 * f + r0; c1 = c1 * f + r1; m = v;
        } else {
            float p = expf(v - m);
            s += p; c0 += p * r0; c1 += p * r1;
        }
    }
    float inv = 1.0f / s;
    g_centers[((size_t)b * NO + n) * 2 + 0] = c0 * inv;
    g_centers[((size_t)b * NO + n) * 2 + 1] = c1 * inv;
}

// ---------------- cell-softmax -> expected position ------------------------
__global__ void __launch_bounds__(256) final_kernel(float* __restrict__ outp) {
    const int wrp = threadIdx.x >> 5;
    const int lane = threadIdx.x & 31;
    const int row = blockIdx.x * 8 + wrp;   // row = b*NT + t
    const int b = row >> 8;
    const float* o = g_out + (size_t)row * NO;

    float v[16];
    float vmax = -1e30f;
#pragma unroll
    for (int i = 0; i < 16; i++) {
        v[i] = o[lane + 32 * i];
        vmax = fmaxf(vmax, v[i]);
    }
#pragma unroll
    for (int off = 16; off; off >>= 1)
        vmax = fmaxf(vmax, __shfl_xor_sync(0xffffffffu, vmax, off));

    float s = 0.0f, a0 = 0.0f, a1 = 0.0f;
    const float* cen = g_centers + (size_t)b * NO * 2;
#pragma unroll
    for (int i = 0; i < 16; i++) {
        int n = lane + 32 * i;
        float p = expf(v[i] - vmax);
        s += p;
        float2 c = *(const float2*)(cen + n * 2);
        a0 += p * c.x; a1 += p * c.y;
    }
#pragma unroll
    for (int off = 16; off; off >>= 1) {
        s  += __shfl_xor_sync(0xffffffffu, s, off);
        a0 += __shfl_xor_sync(0xffffffffu, a0, off);
        a1 += __shfl_xor_sync(0xffffffffu, a1, off);
    }
    if (lane == 0) {
        float inv = 1.0f / s;
        outp[row * 2 + 0] = a0 * inv;
        outp[row * 2 + 1] = a1 * inv;
    }
}

extern "C" void kernel_launch(void* const* d_in, const int* in_sizes, int n_in,
                              void* d_out, int out_size) {
    const float* x    = (const float*)d_in[0];
    const float* r    = (const float*)d_in[1];
    const float* sW   = (const float*)d_in[2];
    const float* hW   = (const float*)d_in[3];
    const float* recW = (const float*)d_in[4];
    const float* recb = (const float*)d_in[5];
    const float* outW = (const float*)d_in[6];
    const float* outb = (const float*)d_in[7];
    const float* init = (const float*)d_in[8];
    float* outp = (float*)d_out;

    build_csc_kernel<<<NN / 256, 256>>>(recW);
    {
        dim3 g(NN / 32, NO / 32);
        wsplit_kernel<<<g, 256>>>(outW);
    }
    {
        dim3 g(NT / 32, NB);
        drive_kernel<<<g, 512>>>(x, sW, hW);
    }
    rnn_kernel<<<NB, 256>>>(recb, init);
    {
        cudaFuncSetAttribute(outgemm_mma_kernel,
                             cudaFuncAttributeMaxDynamicSharedMemorySize, GEMM_SMEM);
        dim3 g(NO / 128, (NB * NT) / 128);
        outgemm_mma_kernel<<<g, 256, GEMM_SMEM>>>(outb);
    }
    centers_kernel<<<NB, 512>>>(r);
    final_kernel<<<(NB * NT) / 8, 256>>>(outp);
}

// round 8
// speedup vs baseline: 1.9166x; 1.0775x over previous
#include <cuda_runtime.h>
#include <cuda_bf16.h>
#include <math.h>
#include <stdint.h>

#define NB 64
#define NT 256
#define NN 1024
#define NO 512
#define NK_SPEED 20
#define NK_HD 50
#define NK_TOT 70
#define CMAX 4

__device__ float          g_drive[(size_t)NB * NT * NN];
__device__ __nv_bfloat16  g_hs_hi[(size_t)NB * NT * NN];
__device__ __nv_bfloat16  g_hs_lo[(size_t)NB * NT * NN];
__device__ __nv_bfloat16  g_wt_hi[(size_t)NO * NN];
__device__ __nv_bfloat16  g_wt_lo[(size_t)NO * NN];
__device__ float          g_out[(size_t)NB * NT * NO];
__device__ float          g_centers[NB * NO * 2];
__device__ int            g_nnz_cnt[NN];
__device__ int            g_nnz_idx[(size_t)NN * NN];
__device__ float          g_nnz_val[(size_t)NN * NN];

// ---------------- CSC of rec_W (coalesced over columns) --------------------
__global__ void build_csc_kernel(const float* __restrict__ recW) {
    int n = blockIdx.x * blockDim.x + threadIdx.x;
    if (n >= NN) return;
    int cnt = 0;
    for (int k = 0; k < NN; k++) {
        float w = recW[(size_t)k * NN + n];
        if (w != 0.0f) {
            g_nnz_idx[(size_t)n * NN + cnt] = k;
            g_nnz_val[(size_t)n * NN + cnt] = w;
            cnt++;
        }
    }
    g_nnz_cnt[n] = cnt;
}

// ---------------- transpose + bf16-split out_W -> [NO][NN] -----------------
__global__ void __launch_bounds__(256) wsplit_kernel(const float* __restrict__ outW) {
    __shared__ float tile[32][33];
    const int k0 = blockIdx.x * 32, n0 = blockIdx.y * 32;
    const int tx = threadIdx.x & 31, ty = threadIdx.x >> 5;
#pragma unroll
    for (int i = 0; i < 4; i++)
        tile[ty + 8 * i][tx] = outW[(size_t)(k0 + ty + 8 * i) * NO + n0 + tx];
    __syncthreads();
#pragma unroll
    for (int i = 0; i < 4; i++) {
        int row = ty + 8 * i;                       // n-local
        float v = tile[tx][row];                    // outW[k0+tx][n0+row]
        __nv_bfloat16 hi = __float2bfloat16(v);
        __nv_bfloat16 lo = __float2bfloat16(v - __bfloat162float(hi));
        size_t o = (size_t)(n0 + row) * NN + k0 + tx;
        g_wt_hi[o] = hi;
        g_wt_lo[o] = lo;
    }
}

// ---------------- input drive ----------------------------------------------
__global__ void __launch_bounds__(512) drive_kernel(const float* __restrict__ x,
                                                    const float* __restrict__ sW,
                                                    const float* __restrict__ hW) {
    __shared__ float feats[32][NK_TOT];
    const int b = blockIdx.y;
    const int t0 = blockIdx.x * 32;
    const int tid = threadIdx.x;
    const float TWO_PI = 6.2831853071795865f;
    const float LOGNORM = 6.3050317f;  // log(2*pi*I0(2*pi))

    for (int i = tid; i < 32 * NK_TOT; i += 512) {
        int tl = i / NK_TOT, k = i - tl * NK_TOT;
        int t = t0 + tl;
        float f;
        if (k < NK_SPEED) {
            float v = x[((size_t)b * NT + t) * 2 + 0];
            float dv = v - 0.5f * (float)k / 19.0f;
            f = expf(-800.0f * dv * dv);
        } else {
            float th = x[((size_t)b * NT + t) * 2 + 1];
            float c = TWO_PI * (float)(k - NK_SPEED) / 49.0f;
            f = expf(TWO_PI * cosf(th - c) - LOGNORM);
        }
        feats[tl][k] = f;
    }
    __syncthreads();

    float acc[32][2];
#pragma unroll
    for (int tt = 0; tt < 32; tt++) { acc[tt][0] = 0.0f; acc[tt][1] = 0.0f; }

    for (int k = 0; k < NK_TOT; k++) {
        const float* __restrict__ Wr = (k < NK_SPEED) ? (sW + (size_t)k * NN)
                                                      : (hW + (size_t)(k - NK_SPEED) * NN);
        float w0 = Wr[tid], w1 = Wr[tid + 512];
#pragma unroll
        for (int tt = 0; tt < 32; tt++) {
            float f = feats[tt][k];
            acc[tt][0] += f * w0;
            acc[tt][1] += f * w1;
        }
    }
#pragma unroll
    for (int tt = 0; tt < 32; tt++) {
        float* dr = g_drive + ((size_t)b * NT + t0 + tt) * NN;
        dr[tid] = acc[tt][0];
        dr[tid + 512] = acc[tt][1];
    }
}

// ---------------- RNN scan: 1024 threads, 1 n/thread, h in SMEM ------------
__global__ void __launch_bounds__(1024, 1) rnn_kernel(const float* __restrict__ rec_b,
                                                      const float* __restrict__ init_state) {
    __shared__ float hbuf[2][NN];
    const int b = blockIdx.x;
    const int n = threadIdx.x;

    const float rb = rec_b[n];
    const int cnt = g_nnz_cnt[n];
    const int cr = cnt < CMAX ? cnt : CMAX;
    int kk[CMAX]; float ww[CMAX];
    for (int j = 0; j < cr; j++) {
        kk[j] = g_nnz_idx[(size_t)n * NN + j];
        ww[j] = g_nnz_val[(size_t)n * NN + j];
    }
    hbuf[0][n] = init_state[n];
    __syncthreads();

    float d = g_drive[(size_t)b * NT * NN + n];

    for (int t = 0; t < NT; t++) {
        const float* cur = hbuf[t & 1];
        float* nxt = hbuf[(t + 1) & 1];
        float dn = 0.0f;
        if (t + 1 < NT)
            dn = g_drive[((size_t)b * NT + t + 1) * NN + n];

        float acc = rb + d;
        for (int j = 0; j < cr; j++)
            acc += cur[kk[j]] * ww[j];
        for (int j = CMAX; j < cnt; j++)
            acc += cur[g_nnz_idx[(size_t)n * NN + j]] * g_nnz_val[(size_t)n * NN + j];
        float hv = fmaxf(acc, 0.0f);
        nxt[n] = hv;
        const size_t row = ((size_t)b * NT + t) * NN;
        __nv_bfloat16 hb = __float2bfloat16(hv);
        g_hs_hi[row + n] = hb;
        g_hs_lo[row + n] = __float2bfloat16(hv - __bfloat162float(hb));
        __syncthreads();
        d = dn;
    }
}

// ---------------- mma.sync bf16-split out-GEMM (cp.async pipelined) --------
// D = Ahi*Bhi + Ahi*Blo + Alo*Bhi via mma.sync.m16n8k16. CTA 128x128, K-chunk 64,
// double-buffered cp.async staging.
#define TS 72                              // padded k-stride (bf16 elems); 144B row, 16B-aligned
#define TILE_ELEMS (128 * TS)              // one operand tile
#define BUF_ELEMS (4 * TILE_ELEMS)         // Ahi,Alo,Bhi,Blo
#define GEMM_SMEM (2 * BUF_ELEMS * 2)      // two buffers, bf16

__device__ __forceinline__ void cp16(void* smem_dst, const void* gsrc) {
    uint32_t s = (uint32_t)__cvta_generic_to_shared(smem_dst);
    asm volatile("cp.async.cg.shared.global [%0], [%1], 16;" :: "r"(s), "l"(gsrc) : "memory");
}
__device__ __forceinline__ void cp_commit() {
    asm volatile("cp.async.commit_group;" ::: "memory");
}
template <int N>
__device__ __forceinline__ void cp_wait() {
    asm volatile("cp.async.wait_group %0;" :: "n"(N) : "memory");
}

__device__ __forceinline__ void mma_bf16(float* d, const uint32_t* a, const uint32_t* b) {
    asm volatile(
        "mma.sync.aligned.m16n8k16.row.col.f32.bf16.bf16.f32 "
        "{%0,%1,%2,%3}, {%4,%5,%6,%7}, {%8,%9}, {%0,%1,%2,%3};"
        : "+f"(d[0]), "+f"(d[1]), "+f"(d[2]), "+f"(d[3])
        : "r"(a[0]), "r"(a[1]), "r"(a[2]), "r"(a[3]), "r"(b[0]), "r"(b[1]));
}

__global__ void __launch_bounds__(256, 1) outgemm_mma_kernel(const float* __restrict__ outB) {
    extern __shared__ __nv_bfloat16 smem[];

    const int tid = threadIdx.x;
    const int wid = tid >> 5, lane = tid & 31;
    const int gid = lane >> 2, tig = lane & 3;
    const int wm = wid >> 2, wn = wid & 3;          // 2 x 4 warps
    const int n0 = blockIdx.x * 128;
    const int row0 = blockIdx.y * 128;

    float acc[4][4][4];
#pragma unroll
    for (int mt = 0; mt < 4; mt++)
#pragma unroll
        for (int nt = 0; nt < 4; nt++)
#pragma unroll
            for (int j = 0; j < 4; j++) acc[mt][nt][j] = 0.0f;

    const int srow = tid >> 1;           // 0..127 (2 threads per row)
    const int scol = (tid & 1) * 32;     // 0 / 32  (32 bf16 = 4 x 16B)

    const __nv_bfloat16* gA = g_hs_hi + (size_t)(row0 + srow) * NN + scol;
    const __nv_bfloat16* gL = g_hs_lo + (size_t)(row0 + srow) * NN + scol;
    const __nv_bfloat16* gB = g_wt_hi + (size_t)(n0 + srow) * NN + scol;
    const __nv_bfloat16* gM = g_wt_lo + (size_t)(n0 + srow) * NN + scol;
    const int sbase = srow * TS + scol;

    // issue async loads for chunk c into buffer buf
    auto load_chunk = [&](int c, int buf) {
        __nv_bfloat16* base = smem + buf * BUF_ELEMS;
        const int k0 = c * 64;
#pragma unroll
        for (int q = 0; q < 4; q++) {
            cp16(base + 0 * TILE_ELEMS + sbase + q * 8, gA + k0 + q * 8);
            cp16(base + 1 * TILE_ELEMS + sbase + q * 8, gL + k0 + q * 8);
            cp16(base + 2 * TILE_ELEMS + sbase + q * 8, gB + k0 + q * 8);
            cp16(base + 3 * TILE_ELEMS + sbase + q * 8, gM + k0 + q * 8);
        }
    };

    load_chunk(0, 0);
    cp_commit();

    for (int c = 0; c < 16; c++) {
        if (c < 15) {
            load_chunk(c + 1, (c + 1) & 1);
            cp_commit();
            cp_wait<1>();          // chunk c done (this thread)
        } else {
            cp_wait<0>();
        }
        __syncthreads();           // chunk c visible to all

        const __nv_bfloat16* Ah = smem + (c & 1) * BUF_ELEMS;
        const __nv_bfloat16* Al = Ah + TILE_ELEMS;
        const __nv_bfloat16* Bh = Ah + 2 * TILE_ELEMS;
        const __nv_bfloat16* Bl = Ah + 3 * TILE_ELEMS;

#pragma unroll
        for (int ks = 0; ks < 4; ks++) {
            const int kc = ks * 16 + tig * 2;
            uint32_t ahi[4][4], alo[4][4], bhi[4][2], blo[4][2];
#pragma unroll
            for (int mt = 0; mt < 4; mt++) {
                const int r = wm * 64 + mt * 16 + gid;
                ahi[mt][0] = *(const uint32_t*)(Ah + r * TS + kc);
                ahi[mt][1] = *(const uint32_t*)(Ah + (r + 8) * TS + kc);
                ahi[mt][2] = *(const uint32_t*)(Ah + r * TS + kc + 8);
                ahi[mt][3] = *(const uint32_t*)(Ah + (r + 8) * TS + kc + 8);
                alo[mt][0] = *(const uint32_t*)(Al + r * TS + kc);
                alo[mt][1] = *(const uint32_t*)(Al + (r + 8) * TS + kc);
                alo[mt][2] = *(const uint32_t*)(Al + r * TS + kc + 8);
                alo[mt][3] = *(const uint32_t*)(Al + (r + 8) * TS + kc + 8);
            }
#pragma unroll
            for (int nt = 0; nt < 4; nt++) {
                const int nr = wn * 32 + nt * 8 + gid;
                bhi[nt][0] = *(const uint32_t*)(Bh + nr * TS + kc);
                bhi[nt][1] = *(const uint32_t*)(Bh + nr * TS + kc + 8);
                blo[nt][0] = *(const uint32_t*)(Bl + nr * TS + kc);
                blo[nt][1] = *(const uint32_t*)(Bl + nr * TS + kc + 8);
            }
#pragma unroll
            for (int mt = 0; mt < 4; mt++)
#pragma unroll
                for (int nt = 0; nt < 4; nt++) {
                    mma_bf16(acc[mt][nt], ahi[mt], bhi[nt]);
                    mma_bf16(acc[mt][nt], ahi[mt], blo[nt]);
                    mma_bf16(acc[mt][nt], alo[mt], bhi[nt]);
                }
        }
        __syncthreads();           // buf (c&1) free for load of chunk c+2
    }

    // epilogue: bias + relu
#pragma unroll
    for (int nt = 0; nt < 4; nt++) {
        const int col = n0 + wn * 32 + nt * 8 + tig * 2;
        const float b0 = outB[col], b1 = outB[col + 1];
#pragma unroll
        for (int mt = 0; mt < 4; mt++) {
            const int r = row0 + wm * 64 + mt * 16 + gid;
            float2 o0, o1;
            o0.x = fmaxf(acc[mt][nt][0] + b0, 0.0f);
            o0.y = fmaxf(acc[mt][nt][1] + b1, 0.0f);
            o1.x = fmaxf(acc[mt][nt][2] + b0, 0.0f);
            o1.y = fmaxf(acc[mt][nt][3] + b1, 0.0f);
            *(float2*)(g_out + (size_t)r * NO + col) = o0;
            *(float2*)(g_out + (size_t)(r + 8) * NO + col) = o1;
        }
    }
}

// ---------------- time-softmax -> centers ----------------------------------
__global__ void __launch_bounds__(512) centers_kernel(const float* __restrict__ r) {
    const int b = blockIdx.x;
    const int n = threadIdx.x;
    float m = -1e30f, s = 0.0f, c0 = 0.0f, c1 = 0.0f;
    const float* ob = g_out + (size_t)b * NT * NO;
    const float* rb = r + (size_t)b * NT * 2;
    for (int t = 0; t < NT; t++) {
        float v = ob[(size_t)t * NO + n];
        float r0 = rb[t * 2 + 0], r1 = rb[t * 2 + 1];
        if (v > m) {
            float f = expf(m - v);
            s = s * f + 1.0f; c0 = c0 * f + r0; c1 = c1 * f + r1; m = v;
        } else {
            float p = expf(v - m);
            s += p; c0 += p * r0; c1 += p * r1;
        }
    }
    float inv = 1.0f / s;
    g_centers[((size_t)b * NO + n) * 2 + 0] = c0 * inv;
    g_centers[((size_t)b * NO + n) * 2 + 1] = c1 * inv;
}

// ---------------- cell-softmax -> expected position ------------------------
__global__ void __launch_bounds__(256) final_kernel(float* __restrict__ outp) {
    const int wrp = threadIdx.x >> 5;
    const int lane = threadIdx.x & 31;
    const int row = blockIdx.x * 8 + wrp;   // row = b*NT + t
    const int b = row >> 8;
    const float* o = g_out + (size_t)row * NO;

    float v[16];
    float vmax = -1e30f;
#pragma unroll
    for (int i = 0; i < 16; i++) {
        v[i] = o[lane + 32 * i];
        vmax = fmaxf(vmax, v[i]);
    }
#pragma unroll
    for (int off = 16; off; off >>= 1)
        vmax = fmaxf(vmax, __shfl_xor_sync(0xffffffffu, vmax, off));

    float s = 0.0f, a0 = 0.0f, a1 = 0.0f;
    const float* cen = g_centers + (size_t)b * NO * 2;
#pragma unroll
    for (int i = 0; i < 16; i++) {
        int n = lane + 32 * i;
        float p = expf(v[i] - vmax);
        s += p;
        float2 c = *(const float2*)(cen + n * 2);
        a0 += p * c.x; a1 += p * c.y;
    }
#pragma unroll
    for (int off = 16; off; off >>= 1) {
        s  += __shfl_xor_sync(0xffffffffu, s, off);
        a0 += __shfl_xor_sync(0xffffffffu, a0, off);
        a1 += __shfl_xor_sync(0xffffffffu, a1, off);
    }
    if (lane == 0) {
        float inv = 1.0f / s;
        outp[row * 2 + 0] = a0 * inv;
        outp[row * 2 + 1] = a1 * inv;
    }
}

extern "C" void kernel_launch(void* const* d_in, const int* in_sizes, int n_in,
                              void* d_out, int out_size) {
    const float* x    = (const float*)d_in[0];
    const float* r    = (const float*)d_in[1];
    const float* sW   = (const float*)d_in[2];
    const float* hW   = (const float*)d_in[3];
    const float* recW = (const float*)d_in[4];
    const float* recb = (const float*)d_in[5];
    const float* outW = (const float*)d_in[6];
    const float* outb = (const float*)d_in[7];
    const float* init = (const float*)d_in[8];
    float* outp = (float*)d_out;

    build_csc_kernel<<<NN / 256, 256>>>(recW);
    {
        dim3 g(NN / 32, NO / 32);
        wsplit_kernel<<<g, 256>>>(outW);
    }
    {
        dim3 g(NT / 32, NB);
        drive_kernel<<<g, 512>>>(x, sW, hW);
    }
    rnn_kernel<<<NB, 1024>>>(recb, init);
    {
        cudaFuncSetAttribute(outgemm_mma_kernel,
                             cudaFuncAttributeMaxDynamicSharedMemorySize, GEMM_SMEM);
        dim3 g(NO / 128, (NB * NT) / 128);
        outgemm_mma_kernel<<<g, 256, GEMM_SMEM>>>(outb);
    }
    centers_kernel<<<NB, 512>>>(r);
    final_kernel<<<(NB * NT) / 8, 256>>>(outp);
}

// round 9
// speedup vs baseline: 2.3083x; 1.2044x over previous
#include <cuda_runtime.h>
#include <cuda_bf16.h>
#include <math.h>
#include <stdint.h>

#define NB 64
#define NT 256
#define NN 1024
#define NO 512
#define NK_SPEED 20
#define NK_HD 50
#define NK_TOT 70
#define CMAX 4

__device__ float          g_drive[(size_t)NB * NT * NN];
__device__ __nv_bfloat16  g_hs_hi[(size_t)NB * NT * NN];
__device__ __nv_bfloat16  g_hs_lo[(size_t)NB * NT * NN];
__device__ __nv_bfloat16  g_wt_hi[(size_t)NO * NN];
__device__ __nv_bfloat16  g_wt_lo[(size_t)NO * NN];
__device__ float          g_out[(size_t)NB * NT * NO];
__device__ float          g_centers[NB * NO * 2];
__device__ int            g_nnz_cnt[NN];
__device__ int            g_nnz_idx[(size_t)NN * NN];
__device__ float          g_nnz_val[(size_t)NN * NN];
__device__ int            g_tmp_idx[(size_t)NN * NN];
__device__ float          g_tmp_val[(size_t)NN * NN];
__device__ int            g_scnt[NN * 16];
__device__ float          g_wdiag[NN];
__device__ int            g_diag_flag;

// ---------------- CSC phase 1: 16 k-segments per column, 64 CTAs -----------
__global__ void __launch_bounds__(256) csc_phase1(const float* __restrict__ recW) {
    const int tid = threadIdx.x;
    const int n = blockIdx.x * 16 + (tid & 15);   // 16 columns per CTA
    const int kt = tid >> 4;                       // 16 segments of 64 rows
    int c = 0;
    const int kbase = kt * 64;
    for (int i = 0; i < 64; i++) {
        float w = recW[(size_t)(kbase + i) * NN + n];
        if (w != 0.0f) {
            g_tmp_idx[(size_t)n * NN + kbase + c] = kbase + i;
            g_tmp_val[(size_t)n * NN + kbase + c] = w;
            c++;
        }
    }
    g_scnt[n * 16 + kt] = c;
    if (blockIdx.x == 0 && tid == 0) g_diag_flag = 1;
}

// ---------------- CSC phase 2: concat segments, detect diagonality ---------
__global__ void __launch_bounds__(256) csc_phase2() {
    const int n = blockIdx.x * 256 + threadIdx.x;
    int off = 0;
    bool diag = true;
    float wsum = 0.0f;
    for (int s = 0; s < 16; s++) {
        const int c = g_scnt[n * 16 + s];
        for (int i = 0; i < c; i++) {
            int k = g_tmp_idx[(size_t)n * NN + s * 64 + i];
            float w = g_tmp_val[(size_t)n * NN + s * 64 + i];
            g_nnz_idx[(size_t)n * NN + off] = k;
            g_nnz_val[(size_t)n * NN + off] = w;
            off++;
            if (k != n) diag = false; else wsum += w;
        }
    }
    g_nnz_cnt[n] = off;
    g_wdiag[n] = wsum;
    if (!diag) g_diag_flag = 0;
}

// ---------------- transpose + bf16-split out_W -> [NO][NN] -----------------
__global__ void __launch_bounds__(256) wsplit_kernel(const float* __restrict__ outW) {
    __shared__ float tile[32][33];
    const int k0 = blockIdx.x * 32, n0 = blockIdx.y * 32;
    const int tx = threadIdx.x & 31, ty = threadIdx.x >> 5;
#pragma unroll
    for (int i = 0; i < 4; i++)
        tile[ty + 8 * i][tx] = outW[(size_t)(k0 + ty + 8 * i) * NO + n0 + tx];
    __syncthreads();
#pragma unroll
    for (int i = 0; i < 4; i++) {
        int row = ty + 8 * i;
        float v = tile[tx][row];
        __nv_bfloat16 hi = __float2bfloat16(v);
        __nv_bfloat16 lo = __float2bfloat16(v - __bfloat162float(hi));
        size_t o = (size_t)(n0 + row) * NN + k0 + tx;
        g_wt_hi[o] = hi;
        g_wt_lo[o] = lo;
    }
}

// ---------------- input drive ----------------------------------------------
__global__ void __launch_bounds__(512) drive_kernel(const float* __restrict__ x,
                                                    const float* __restrict__ sW,
                                                    const float* __restrict__ hW) {
    __shared__ float feats[32][NK_TOT];
    const int b = blockIdx.y;
    const int t0 = blockIdx.x * 32;
    const int tid = threadIdx.x;
    const float TWO_PI = 6.2831853071795865f;
    const float LOGNORM = 6.3050317f;  // log(2*pi*I0(2*pi))

    for (int i = tid; i < 32 * NK_TOT; i += 512) {
        int tl = i / NK_TOT, k = i - tl * NK_TOT;
        int t = t0 + tl;
        float f;
        if (k < NK_SPEED) {
            float v = x[((size_t)b * NT + t) * 2 + 0];
            float dv = v - 0.5f * (float)k / 19.0f;
            f = expf(-800.0f * dv * dv);
        } else {
            float th = x[((size_t)b * NT + t) * 2 + 1];
            float c = TWO_PI * (float)(k - NK_SPEED) / 49.0f;
            f = expf(TWO_PI * cosf(th - c) - LOGNORM);
        }
        feats[tl][k] = f;
    }
    __syncthreads();

    float acc[32][2];
#pragma unroll
    for (int tt = 0; tt < 32; tt++) { acc[tt][0] = 0.0f; acc[tt][1] = 0.0f; }

    for (int k = 0; k < NK_TOT; k++) {
        const float* __restrict__ Wr = (k < NK_SPEED) ? (sW + (size_t)k * NN)
                                                      : (hW + (size_t)(k - NK_SPEED) * NN);
        float w0 = Wr[tid], w1 = Wr[tid + 512];
#pragma unroll
        for (int tt = 0; tt < 32; tt++) {
            float f = feats[tt][k];
            acc[tt][0] += f * w0;
            acc[tt][1] += f * w1;
        }
    }
#pragma unroll
    for (int tt = 0; tt < 32; tt++) {
        float* dr = g_drive + ((size_t)b * NT + t0 + tt) * NN;
        dr[tid] = acc[tt][0];
        dr[tid + 512] = acc[tt][1];
    }
}

// ---------------- RNN fast path: diagonal rec_W, no barriers ---------------
// 65536 independent (b,n) chains; register h; pure streaming.
__global__ void __launch_bounds__(256) rnn_diag_kernel(const float* __restrict__ rec_b,
                                                       const float* __restrict__ init_state) {
    if (*(volatile int*)&g_diag_flag == 0) return;
    const int gtid = blockIdx.x * 256 + threadIdx.x;
    const int b = gtid >> 10;
    const int n = gtid & 1023;

    const float w = g_wdiag[n];
    const float rb = rec_b[n];
    float h = init_state[n];
    const float* dp = g_drive + (size_t)b * NT * NN + n;
    __nv_bfloat16* hh = g_hs_hi + (size_t)b * NT * NN + n;
    __nv_bfloat16* hl = g_hs_lo + (size_t)b * NT * NN + n;

    float d = dp[0];
    for (int t = 0; t < NT; t++) {
        float dn = (t + 1 < NT) ? dp[(size_t)(t + 1) * NN] : 0.0f;
        h = fmaxf(fmaf(h, w, rb + d), 0.0f);
        __nv_bfloat16 hb = __float2bfloat16(h);
        hh[(size_t)t * NN] = hb;
        hl[(size_t)t * NN] = __float2bfloat16(h - __bfloat162float(hb));
        d = dn;
    }
}

// ---------------- RNN general fallback: h in SMEM, 1 bar/step --------------
__global__ void __launch_bounds__(1024, 1) rnn_general_kernel(const float* __restrict__ rec_b,
                                                              const float* __restrict__ init_state) {
    if (*(volatile int*)&g_diag_flag != 0) return;
    __shared__ float hbuf[2][NN];
    const int b = blockIdx.x;
    const int n = threadIdx.x;

    const float rb = rec_b[n];
    const int cnt = g_nnz_cnt[n];
    const int cr = cnt < CMAX ? cnt : CMAX;
    int kk[CMAX]; float ww[CMAX];
    for (int j = 0; j < cr; j++) {
        kk[j] = g_nnz_idx[(size_t)n * NN + j];
        ww[j] = g_nnz_val[(size_t)n * NN + j];
    }
    hbuf[0][n] = init_state[n];
    __syncthreads();

    float d = g_drive[(size_t)b * NT * NN + n];

    for (int t = 0; t < NT; t++) {
        const float* cur = hbuf[t & 1];
        float* nxt = hbuf[(t + 1) & 1];
        float dn = 0.0f;
        if (t + 1 < NT)
            dn = g_drive[((size_t)b * NT + t + 1) * NN + n];

        float acc = rb + d;
        for (int j = 0; j < cr; j++)
            acc += cur[kk[j]] * ww[j];
        for (int j = CMAX; j < cnt; j++)
            acc += cur[g_nnz_idx[(size_t)n * NN + j]] * g_nnz_val[(size_t)n * NN + j];
        float hv = fmaxf(acc, 0.0f);
        nxt[n] = hv;
        const size_t row = ((size_t)b * NT + t) * NN;
        __nv_bfloat16 hb = __float2bfloat16(hv);
        g_hs_hi[row + n] = hb;
        g_hs_lo[row + n] = __float2bfloat16(hv - __bfloat162float(hb));
        __syncthreads();
        d = dn;
    }
}

// ---------------- mma.sync bf16-split out-GEMM (cp.async pipelined) --------
#define TS 72
#define TILE_ELEMS (128 * TS)
#define BUF_ELEMS (4 * TILE_ELEMS)
#define GEMM_SMEM (2 * BUF_ELEMS * 2)

__device__ __forceinline__ void cp16(void* smem_dst, const void* gsrc) {
    uint32_t s = (uint32_t)__cvta_generic_to_shared(smem_dst);
    asm volatile("cp.async.cg.shared.global [%0], [%1], 16;" :: "r"(s), "l"(gsrc) : "memory");
}
__device__ __forceinline__ void cp_commit() {
    asm volatile("cp.async.commit_group;" ::: "memory");
}
template <int N>
__device__ __forceinline__ void cp_wait() {
    asm volatile("cp.async.wait_group %0;" :: "n"(N) : "memory");
}
__device__ __forceinline__ void mma_bf16(float* d, const uint32_t* a, const uint32_t* b) {
    asm volatile(
        "mma.sync.aligned.m16n8k16.row.col.f32.bf16.bf16.f32 "
        "{%0,%1,%2,%3}, {%4,%5,%6,%7}, {%8,%9}, {%0,%1,%2,%3};"
        : "+f"(d[0]), "+f"(d[1]), "+f"(d[2]), "+f"(d[3])
        : "r"(a[0]), "r"(a[1]), "r"(a[2]), "r"(a[3]), "r"(b[0]), "r"(b[1]));
}

__global__ void __launch_bounds__(256, 1) outgemm_mma_kernel(const float* __restrict__ outB) {
    extern __shared__ __nv_bfloat16 smem[];

    const int tid = threadIdx.x;
    const int wid = tid >> 5, lane = tid & 31;
    const int gid = lane >> 2, tig = lane & 3;
    const int wm = wid >> 2, wn = wid & 3;
    const int n0 = blockIdx.x * 128;
    const int row0 = blockIdx.y * 128;

    float acc[4][4][4];
#pragma unroll
    for (int mt = 0; mt < 4; mt++)
#pragma unroll
        for (int nt = 0; nt < 4; nt++)
#pragma unroll
            for (int j = 0; j < 4; j++) acc[mt][nt][j] = 0.0f;

    const int srow = tid >> 1;
    const int scol = (tid & 1) * 32;

    const __nv_bfloat16* gA = g_hs_hi + (size_t)(row0 + srow) * NN + scol;
    const __nv_bfloat16* gL = g_hs_lo + (size_t)(row0 + srow) * NN + scol;
    const __nv_bfloat16* gB = g_wt_hi + (size_t)(n0 + srow) * NN + scol;
    const __nv_bfloat16* gM = g_wt_lo + (size_t)(n0 + srow) * NN + scol;
    const int sbase = srow * TS + scol;

    auto load_chunk = [&](int c, int buf) {
        __nv_bfloat16* base = smem + buf * BUF_ELEMS;
        const int k0 = c * 64;
#pragma unroll
        for (int q = 0; q < 4; q++) {
            cp16(base + 0 * TILE_ELEMS + sbase + q * 8, gA + k0 + q * 8);
            cp16(base + 1 * TILE_ELEMS + sbase + q * 8, gL + k0 + q * 8);
            cp16(base + 2 * TILE_ELEMS + sbase + q * 8, gB + k0 + q * 8);
            cp16(base + 3 * TILE_ELEMS + sbase + q * 8, gM + k0 + q * 8);
        }
    };

    load_chunk(0, 0);
    cp_commit();

    for (int c = 0; c < 16; c++) {
        if (c < 15) {
            load_chunk(c + 1, (c + 1) & 1);
            cp_commit();
            cp_wait<1>();
        } else {
            cp_wait<0>();
        }
        __syncthreads();

        const __nv_bfloat16* Ah = smem + (c & 1) * BUF_ELEMS;
        const __nv_bfloat16* Al = Ah + TILE_ELEMS;
        const __nv_bfloat16* Bh = Ah + 2 * TILE_ELEMS;
        const __nv_bfloat16* Bl = Ah + 3 * TILE_ELEMS;

#pragma unroll
        for (int ks = 0; ks < 4; ks++) {
            const int kc = ks * 16 + tig * 2;
            uint32_t ahi[4][4], alo[4][4], bhi[4][2], blo[4][2];
#pragma unroll
            for (int mt = 0; mt < 4; mt++) {
                const int r = wm * 64 + mt * 16 + gid;
                ahi[mt][0] = *(const uint32_t*)(Ah + r * TS + kc);
                ahi[mt][1] = *(const uint32_t*)(Ah + (r + 8) * TS + kc);
                ahi[mt][2] = *(const uint32_t*)(Ah + r * TS + kc + 8);
                ahi[mt][3] = *(const uint32_t*)(Ah + (r + 8) * TS + kc + 8);
                alo[mt][0] = *(const uint32_t*)(Al + r * TS + kc);
                alo[mt][1] = *(const uint32_t*)(Al + (r + 8) * TS + kc);
                alo[mt][2] = *(const uint32_t*)(Al + r * TS + kc + 8);
                alo[mt][3] = *(const uint32_t*)(Al + (r + 8) * TS + kc + 8);
            }
#pragma unroll
            for (int nt = 0; nt < 4; nt++) {
                const int nr = wn * 32 + nt * 8 + gid;
                bhi[nt][0] = *(const uint32_t*)(Bh + nr * TS + kc);
                bhi[nt][1] = *(const uint32_t*)(Bh + nr * TS + kc + 8);
                blo[nt][0] = *(const uint32_t*)(Bl + nr * TS + kc);
                blo[nt][1] = *(const uint32_t*)(Bl + nr * TS + kc + 8);
            }
#pragma unroll
            for (int mt = 0; mt < 4; mt++)
#pragma unroll
                for (int nt = 0; nt < 4; nt++) {
                    mma_bf16(acc[mt][nt], ahi[mt], bhi[nt]);
                    mma_bf16(acc[mt][nt], ahi[mt], blo[nt]);
                    mma_bf16(acc[mt][nt], alo[mt], bhi[nt]);
                }
        }
        __syncthreads();
    }

#pragma unroll
    for (int nt = 0; nt < 4; nt++) {
        const int col = n0 + wn * 32 + nt * 8 + tig * 2;
        const float b0 = outB[col], b1 = outB[col + 1];
#pragma unroll
        for (int mt = 0; mt < 4; mt++) {
            const int r = row0 + wm * 64 + mt * 16 + gid;
            float2 o0, o1;
            o0.x = fmaxf(acc[mt][nt][0] + b0, 0.0f);
            o0.y = fmaxf(acc[mt][nt][1] + b1, 0.0f);
            o1.x = fmaxf(acc[mt][nt][2] + b0, 0.0f);
            o1.y = fmaxf(acc[mt][nt][3] + b1, 0.0f);
            *(float2*)(g_out + (size_t)r * NO + col) = o0;
            *(float2*)(g_out + (size_t)(r + 8) * NO + col) = o1;
        }
    }
}

// ---------------- time-softmax -> centers ----------------------------------
__global__ void __launch_bounds__(512) centers_kernel(const float* __restrict__ r) {
    const int b = blockIdx.x;
    const int n = threadIdx.x;
    float m = -1e30f, s = 0.0f, c0 = 0.0f, c1 = 0.0f;
    const float* ob = g_out + (size_t)b * NT * NO;
    const float* rb = r + (size_t)b * NT * 2;
    for (int t = 0; t < NT; t++) {
        float v = ob[(size_t)t * NO + n];
        float r0 = rb[t * 2 + 0], r1 = rb[t * 2 + 1];
        if (v > m) {
            float f = expf(m - v);
            s = s * f + 1.0f; c0 = c0 * f + r0; c1 = c1 * f + r1; m = v;
        } else {
            float p = expf(v - m);
            s += p; c0 += p * r0; c1 += p * r1;
        }
    }
    float inv = 1.0f / s;
    g_centers[((size_t)b * NO + n) * 2 + 0] = c0 * inv;
    g_centers[((size_t)b * NO + n) * 2 + 1] = c1 * inv;
}

// ---------------- cell-softmax -> expected position ------------------------
__global__ void __launch_bounds__(256) final_kernel(float* __restrict__ outp) {
    const int wrp = threadIdx.x >> 5;
    const int lane = threadIdx.x & 31;
    const int row = blockIdx.x * 8 + wrp;
    const int b = row >> 8;
    const float* o = g_out + (size_t)row * NO;

    float v[16];
    float vmax = -1e30f;
#pragma unroll
    for (int i = 0; i < 16; i++) {
        v[i] = o[lane + 32 * i];
        vmax = fmaxf(vmax, v[i]);
    }
#pragma unroll
    for (int off = 16; off; off >>= 1)
        vmax = fmaxf(vmax, __shfl_xor_sync(0xffffffffu, vmax, off));

    float s = 0.0f, a0 = 0.0f, a1 = 0.0f;
    const float* cen = g_centers + (size_t)b * NO * 2;
#pragma unroll
    for (int i = 0; i < 16; i++) {
        int n = lane + 32 * i;
        float p = expf(v[i] - vmax);
        s += p;
        float2 c = *(const float2*)(cen + n * 2);
        a0 += p * c.x; a1 += p * c.y;
    }
#pragma unroll
    for (int off = 16; off; off >>= 1) {
        s  += __shfl_xor_sync(0xffffffffu, s, off);
        a0 += __shfl_xor_sync(0xffffffffu, a0, off);
        a1 += __shfl_xor_sync(0xffffffffu, a1, off);
    }
    if (lane == 0) {
        float inv = 1.0f / s;
        outp[row * 2 + 0] = a0 * inv;
        outp[row * 2 + 1] = a1 * inv;
    }
}

extern "C" void kernel_launch(void* const* d_in, const int* in_sizes, int n_in,
                              void* d_out, int out_size) {
    const float* x    = (const float*)d_in[0];
    const float* r    = (const float*)d_in[1];
    const float* sW   = (const float*)d_in[2];
    const float* hW   = (const float*)d_in[3];
    const float* recW = (const float*)d_in[4];
    const float* recb = (const float*)d_in[5];
    const float* outW = (const float*)d_in[6];
    const float* outb = (const float*)d_in[7];
    const float* init = (const float*)d_in[8];
    float* outp = (float*)d_out;

    csc_phase1<<<NN / 16, 256>>>(recW);
    csc_phase2<<<NN / 256, 256>>>();
    {
        dim3 g(NN / 32, NO / 32);
        wsplit_kernel<<<g, 256>>>(outW);
    }
    {
        dim3 g(NT / 32, NB);
        drive_kernel<<<g, 512>>>(x, sW, hW);
    }
    rnn_diag_kernel<<<(NB * NN) / 256, 256>>>(recb, init);
    rnn_general_kernel<<<NB, 1024>>>(recb, init);
    {
        cudaFuncSetAttribute(outgemm_mma_kernel,
                             cudaFuncAttributeMaxDynamicSharedMemorySize, GEMM_SMEM);
        dim3 g(NO / 128, (NB * NT) / 128);
        outgemm_mma_kernel<<<g, 256, GEMM_SMEM>>>(outb);
    }
    centers_kernel<<<NB, 512>>>(r);
    final_kernel<<<(NB * NT) / 8, 256>>>(outp);
}

// round 10
// speedup vs baseline: 3.1066x; 1.3458x over previous
#include <cuda_runtime.h>
#include <cuda_bf16.h>
#include <math.h>
#include <stdint.h>

#define NB 64
#define NT 256
#define NN 1024
#define NO 512
#define NK_SPEED 20
#define NK_HD 50
#define NK_TOT 70
#define CMAX 4

__device__ float          g_drive[(size_t)NB * NT * NN];
__device__ __nv_bfloat16  g_hs_hi[(size_t)NB * NT * NN];
__device__ __nv_bfloat16  g_hs_lo[(size_t)NB * NT * NN];
__device__ __nv_bfloat16  g_wt_hi[(size_t)NO * NN];
__device__ __nv_bfloat16  g_wt_lo[(size_t)NO * NN];
__device__ float          g_out[(size_t)NB * NT * NO];
__device__ float          g_centers[NB * NO * 2];
__device__ float4         g_cpart[4 * NB * NO];
__device__ int            g_nnz_cnt[NN];
__device__ int            g_nnz_idx[(size_t)NN * NN];
__device__ float          g_nnz_val[(size_t)NN * NN];
__device__ int            g_tmp_idx[(size_t)NN * NN];
__device__ float          g_tmp_val[(size_t)NN * NN];
__device__ int            g_scnt[NN * 16];
__device__ float          g_wdiag[NN];
__device__ int            g_diag_flag;

__device__ __forceinline__ unsigned long long pack2(float lo, float hi) {
    unsigned long long o;
    asm("mov.b64 %0, {%1, %2};" : "=l"(o) : "r"(__float_as_uint(lo)), "r"(__float_as_uint(hi)));
    return o;
}
__device__ __forceinline__ void unpack2(unsigned long long v, float& lo, float& hi) {
    unsigned a, b;
    asm("mov.b64 {%0, %1}, %2;" : "=r"(a), "=r"(b) : "l"(v));
    lo = __uint_as_float(a); hi = __uint_as_float(b);
}
__device__ __forceinline__ unsigned long long fma2(unsigned long long a, unsigned long long b, unsigned long long c) {
    unsigned long long d;
    asm("fma.rn.f32x2 %0, %1, %2, %3;" : "=l"(d) : "l"(a), "l"(b), "l"(c));
    return d;
}

// ---------------- CSC phase 1: 16 k-segments per column, 64 CTAs -----------
__global__ void __launch_bounds__(256) csc_phase1(const float* __restrict__ recW) {
    const int tid = threadIdx.x;
    const int n = blockIdx.x * 16 + (tid & 15);
    const int kt = tid >> 4;
    int c = 0;
    const int kbase = kt * 64;
    for (int i = 0; i < 64; i++) {
        float w = recW[(size_t)(kbase + i) * NN + n];
        if (w != 0.0f) {
            g_tmp_idx[(size_t)n * NN + kbase + c] = kbase + i;
            g_tmp_val[(size_t)n * NN + kbase + c] = w;
            c++;
        }
    }
    g_scnt[n * 16 + kt] = c;
    if (blockIdx.x == 0 && tid == 0) g_diag_flag = 1;
}

// ---------------- CSC phase 2: concat segments, detect diagonality ---------
__global__ void __launch_bounds__(256) csc_phase2() {
    const int n = blockIdx.x * 256 + threadIdx.x;
    int off = 0;
    bool diag = true;
    float wsum = 0.0f;
    for (int s = 0; s < 16; s++) {
        const int c = g_scnt[n * 16 + s];
        for (int i = 0; i < c; i++) {
            int k = g_tmp_idx[(size_t)n * NN + s * 64 + i];
            float w = g_tmp_val[(size_t)n * NN + s * 64 + i];
            g_nnz_idx[(size_t)n * NN + off] = k;
            g_nnz_val[(size_t)n * NN + off] = w;
            off++;
            if (k != n) diag = false; else wsum += w;
        }
    }
    g_nnz_cnt[n] = off;
    g_wdiag[n] = wsum;
    if (!diag) g_diag_flag = 0;
}

// ---------------- transpose + bf16-split out_W -> [NO][NN] -----------------
__global__ void __launch_bounds__(256) wsplit_kernel(const float* __restrict__ outW) {
    __shared__ float tile[32][33];
    const int k0 = blockIdx.x * 32, n0 = blockIdx.y * 32;
    const int tx = threadIdx.x & 31, ty = threadIdx.x >> 5;
#pragma unroll
    for (int i = 0; i < 4; i++)
        tile[ty + 8 * i][tx] = outW[(size_t)(k0 + ty + 8 * i) * NO + n0 + tx];
    __syncthreads();
#pragma unroll
    for (int i = 0; i < 4; i++) {
        int row = ty + 8 * i;
        float v = tile[tx][row];
        __nv_bfloat16 hi = __float2bfloat16(v);
        __nv_bfloat16 lo = __float2bfloat16(v - __bfloat162float(hi));
        size_t o = (size_t)(n0 + row) * NN + k0 + tx;
        g_wt_hi[o] = hi;
        g_wt_lo[o] = lo;
    }
}

// ---------------- input drive: f32x2 packed over time pairs ----------------
__global__ void __launch_bounds__(512) drive_kernel(const float* __restrict__ x,
                                                    const float* __restrict__ sW,
                                                    const float* __restrict__ hW) {
    __shared__ float feats[NK_TOT][34];   // [k][t], even stride for float2 LDS
    const int b = blockIdx.y;
    const int t0 = blockIdx.x * 32;
    const int tid = threadIdx.x;
    const float TWO_PI = 6.2831853071795865f;
    const float LOGNORM = 6.3050317f;  // log(2*pi*I0(2*pi))

    for (int i = tid; i < 32 * NK_TOT; i += 512) {
        int tl = i / NK_TOT, k = i - tl * NK_TOT;
        int t = t0 + tl;
        float f;
        if (k < NK_SPEED) {
            float v = x[((size_t)b * NT + t) * 2 + 0];
            float dv = v - 0.5f * (float)k / 19.0f;
            f = expf(-800.0f * dv * dv);
        } else {
            float th = x[((size_t)b * NT + t) * 2 + 1];
            float c = TWO_PI * (float)(k - NK_SPEED) / 49.0f;
            f = expf(TWO_PI * cosf(th - c) - LOGNORM);
        }
        feats[k][tl] = f;
    }
    __syncthreads();

    unsigned long long acc[16][2];
#pragma unroll
    for (int p = 0; p < 16; p++) { acc[p][0] = 0ull; acc[p][1] = 0ull; }

    for (int k = 0; k < NK_TOT; k++) {
        const float* __restrict__ Wr = (k < NK_SPEED) ? (sW + (size_t)k * NN)
                                                      : (hW + (size_t)(k - NK_SPEED) * NN);
        const unsigned long long w00 = pack2(Wr[tid], Wr[tid]);
        const unsigned long long w11 = pack2(Wr[tid + 512], Wr[tid + 512]);
        const unsigned long long* frow = (const unsigned long long*)&feats[k][0];
#pragma unroll
        for (int p = 0; p < 16; p++) {
            unsigned long long f2 = frow[p];       // (f[2p], f[2p+1]) broadcast LDS.64
            acc[p][0] = fma2(f2, w00, acc[p][0]);
            acc[p][1] = fma2(f2, w11, acc[p][1]);
        }
    }
#pragma unroll
    for (int p = 0; p < 16; p++) {
        float a0, a1, b0, b1;
        unpack2(acc[p][0], a0, a1);
        unpack2(acc[p][1], b0, b1);
        float* d0 = g_drive + ((size_t)b * NT + t0 + 2 * p) * NN;
        float* d1 = g_drive + ((size_t)b * NT + t0 + 2 * p + 1) * NN;
        d0[tid] = a0;       d1[tid] = a1;
        d0[tid + 512] = b0; d1[tid + 512] = b1;
    }
}

// ---------------- RNN fast path: diagonal rec_W, no barriers ---------------
__global__ void __launch_bounds__(256) rnn_diag_kernel(const float* __restrict__ rec_b,
                                                       const float* __restrict__ init_state) {
    if (*(volatile int*)&g_diag_flag == 0) return;
    const int gtid = blockIdx.x * 256 + threadIdx.x;
    const int b = gtid >> 10;
    const int n = gtid & 1023;

    const float w = g_wdiag[n];
    const float rb = rec_b[n];
    float h = init_state[n];
    const float* dp = g_drive + (size_t)b * NT * NN + n;
    __nv_bfloat16* hh = g_hs_hi + (size_t)b * NT * NN + n;
    __nv_bfloat16* hl = g_hs_lo + (size_t)b * NT * NN + n;

    float d = dp[0];
    for (int t = 0; t < NT; t++) {
        float dn = (t + 1 < NT) ? dp[(size_t)(t + 1) * NN] : 0.0f;
        h = fmaxf(fmaf(h, w, rb + d), 0.0f);
        __nv_bfloat16 hb = __float2bfloat16(h);
        hh[(size_t)t * NN] = hb;
        hl[(size_t)t * NN] = __float2bfloat16(h - __bfloat162float(hb));
        d = dn;
    }
}

// ---------------- RNN general fallback: h in SMEM, 1 bar/step --------------
__global__ void __launch_bounds__(1024, 1) rnn_general_kernel(const float* __restrict__ rec_b,
                                                              const float* __restrict__ init_state) {
    if (*(volatile int*)&g_diag_flag != 0) return;
    __shared__ float hbuf[2][NN];
    const int b = blockIdx.x;
    const int n = threadIdx.x;

    const float rb = rec_b[n];
    const int cnt = g_nnz_cnt[n];
    const int cr = cnt < CMAX ? cnt : CMAX;
    int kk[CMAX]; float ww[CMAX];
    for (int j = 0; j < cr; j++) {
        kk[j] = g_nnz_idx[(size_t)n * NN + j];
        ww[j] = g_nnz_val[(size_t)n * NN + j];
    }
    hbuf[0][n] = init_state[n];
    __syncthreads();

    float d = g_drive[(size_t)b * NT * NN + n];

    for (int t = 0; t < NT; t++) {
        const float* cur = hbuf[t & 1];
        float* nxt = hbuf[(t + 1) & 1];
        float dn = 0.0f;
        if (t + 1 < NT)
            dn = g_drive[((size_t)b * NT + t + 1) * NN + n];

        float acc = rb + d;
        for (int j = 0; j < cr; j++)
            acc += cur[kk[j]] * ww[j];
        for (int j = CMAX; j < cnt; j++)
            acc += cur[g_nnz_idx[(size_t)n * NN + j]] * g_nnz_val[(size_t)n * NN + j];
        float hv = fmaxf(acc, 0.0f);
        nxt[n] = hv;
        const size_t row = ((size_t)b * NT + t) * NN;
        __nv_bfloat16 hb = __float2bfloat16(hv);
        g_hs_hi[row + n] = hb;
        g_hs_lo[row + n] = __float2bfloat16(hv - __bfloat162float(hb));
        __syncthreads();
        d = dn;
    }
}

// ---------------- mma.sync bf16-split out-GEMM (cp.async pipelined) --------
#define TS 72
#define TILE_ELEMS (128 * TS)
#define BUF_ELEMS (4 * TILE_ELEMS)
#define GEMM_SMEM (2 * BUF_ELEMS * 2)

__device__ __forceinline__ void cp16(void* smem_dst, const void* gsrc) {
    uint32_t s = (uint32_t)__cvta_generic_to_shared(smem_dst);
    asm volatile("cp.async.cg.shared.global [%0], [%1], 16;" :: "r"(s), "l"(gsrc) : "memory");
}
__device__ __forceinline__ void cp_commit() {
    asm volatile("cp.async.commit_group;" ::: "memory");
}
template <int N>
__device__ __forceinline__ void cp_wait() {
    asm volatile("cp.async.wait_group %0;" :: "n"(N) : "memory");
}
__device__ __forceinline__ void mma_bf16(float* d, const uint32_t* a, const uint32_t* b) {
    asm volatile(
        "mma.sync.aligned.m16n8k16.row.col.f32.bf16.bf16.f32 "
        "{%0,%1,%2,%3}, {%4,%5,%6,%7}, {%8,%9}, {%0,%1,%2,%3};"
        : "+f"(d[0]), "+f"(d[1]), "+f"(d[2]), "+f"(d[3])
        : "r"(a[0]), "r"(a[1]), "r"(a[2]), "r"(a[3]), "r"(b[0]), "r"(b[1]));
}

__global__ void __launch_bounds__(256, 1) outgemm_mma_kernel(const float* __restrict__ outB) {
    extern __shared__ __nv_bfloat16 smem[];

    const int tid = threadIdx.x;
    const int wid = tid >> 5, lane = tid & 31;
    const int gid = lane >> 2, tig = lane & 3;
    const int wm = wid >> 2, wn = wid & 3;
    const int n0 = blockIdx.x * 128;
    const int row0 = blockIdx.y * 128;

    float acc[4][4][4];
#pragma unroll
    for (int mt = 0; mt < 4; mt++)
#pragma unroll
        for (int nt = 0; nt < 4; nt++)
#pragma unroll
            for (int j = 0; j < 4; j++) acc[mt][nt][j] = 0.0f;

    const int srow = tid >> 1;
    const int scol = (tid & 1) * 32;

    const __nv_bfloat16* gA = g_hs_hi + (size_t)(row0 + srow) * NN + scol;
    const __nv_bfloat16* gL = g_hs_lo + (size_t)(row0 + srow) * NN + scol;
    const __nv_bfloat16* gB = g_wt_hi + (size_t)(n0 + srow) * NN + scol;
    const __nv_bfloat16* gM = g_wt_lo + (size_t)(n0 + srow) * NN + scol;
    const int sbase = srow * TS + scol;

    auto load_chunk = [&](int c, int buf) {
        __nv_bfloat16* base = smem + buf * BUF_ELEMS;
        const int k0 = c * 64;
#pragma unroll
        for (int q = 0; q < 4; q++) {
            cp16(base + 0 * TILE_ELEMS + sbase + q * 8, gA + k0 + q * 8);
            cp16(base + 1 * TILE_ELEMS + sbase + q * 8, gL + k0 + q * 8);
            cp16(base + 2 * TILE_ELEMS + sbase + q * 8, gB + k0 + q * 8);
            cp16(base + 3 * TILE_ELEMS + sbase + q * 8, gM + k0 + q * 8);
        }
    };

    load_chunk(0, 0);
    cp_commit();

    for (int c = 0; c < 16; c++) {
        if (c < 15) {
            load_chunk(c + 1, (c + 1) & 1);
            cp_commit();
            cp_wait<1>();
        } else {
            cp_wait<0>();
        }
        __syncthreads();

        const __nv_bfloat16* Ah = smem + (c & 1) * BUF_ELEMS;
        const __nv_bfloat16* Al = Ah + TILE_ELEMS;
        const __nv_bfloat16* Bh = Ah + 2 * TILE_ELEMS;
        const __nv_bfloat16* Bl = Ah + 3 * TILE_ELEMS;

#pragma unroll
        for (int ks = 0; ks < 4; ks++) {
            const int kc = ks * 16 + tig * 2;
            uint32_t ahi[4][4], alo[4][4], bhi[4][2], blo[4][2];
#pragma unroll
            for (int mt = 0; mt < 4; mt++) {
                const int r = wm * 64 + mt * 16 + gid;
                ahi[mt][0] = *(const uint32_t*)(Ah + r * TS + kc);
                ahi[mt][1] = *(const uint32_t*)(Ah + (r + 8) * TS + kc);
                ahi[mt][2] = *(const uint32_t*)(Ah + r * TS + kc + 8);
                ahi[mt][3] = *(const uint32_t*)(Ah + (r + 8) * TS + kc + 8);
                alo[mt][0] = *(const uint32_t*)(Al + r * TS + kc);
                alo[mt][1] = *(const uint32_t*)(Al + (r + 8) * TS + kc);
                alo[mt][2] = *(const uint32_t*)(Al + r * TS + kc + 8);
                alo[mt][3] = *(const uint32_t*)(Al + (r + 8) * TS + kc + 8);
            }
#pragma unroll
            for (int nt = 0; nt < 4; nt++) {
                const int nr = wn * 32 + nt * 8 + gid;
                bhi[nt][0] = *(const uint32_t*)(Bh + nr * TS + kc);
                bhi[nt][1] = *(const uint32_t*)(Bh + nr * TS + kc + 8);
                blo[nt][0] = *(const uint32_t*)(Bl + nr * TS + kc);
                blo[nt][1] = *(const uint32_t*)(Bl + nr * TS + kc + 8);
            }
#pragma unroll
            for (int mt = 0; mt < 4; mt++)
#pragma unroll
                for (int nt = 0; nt < 4; nt++) {
                    mma_bf16(acc[mt][nt], ahi[mt], bhi[nt]);
                    mma_bf16(acc[mt][nt], ahi[mt], blo[nt]);
                    mma_bf16(acc[mt][nt], alo[mt], bhi[nt]);
                }
        }
        __syncthreads();
    }

#pragma unroll
    for (int nt = 0; nt < 4; nt++) {
        const int col = n0 + wn * 32 + nt * 8 + tig * 2;
        const float b0 = outB[col], b1 = outB[col + 1];
#pragma unroll
        for (int mt = 0; mt < 4; mt++) {
            const int r = row0 + wm * 64 + mt * 16 + gid;
            float2 o0, o1;
            o0.x = fmaxf(acc[mt][nt][0] + b0, 0.0f);
            o0.y = fmaxf(acc[mt][nt][1] + b1, 0.0f);
            o1.x = fmaxf(acc[mt][nt][2] + b0, 0.0f);
            o1.y = fmaxf(acc[mt][nt][3] + b1, 0.0f);
            *(float2*)(g_out + (size_t)r * NO + col) = o0;
            *(float2*)(g_out + (size_t)(r + 8) * NO + col) = o1;
        }
    }
}

// ---------------- time-softmax -> centers, 2-phase -------------------------
__global__ void __launch_bounds__(512) centers_part_kernel(const float* __restrict__ r) {
    const int b = blockIdx.x;
    const int ch = blockIdx.y;            // 4 time chunks of 64
    const int n = threadIdx.x;
    float m = -1e30f, s = 0.0f, c0 = 0.0f, c1 = 0.0f;
    const float* ob = g_out + (size_t)b * NT * NO + (size_t)ch * 64 * NO;
    const float* rb = r + (size_t)b * NT * 2 + ch * 64 * 2;
    for (int t = 0; t < 64; t++) {
        float v = ob[(size_t)t * NO + n];
        float r0 = rb[t * 2 + 0], r1 = rb[t * 2 + 1];
        if (v > m) {
            float f = expf(m - v);
            s = s * f + 1.0f; c0 = c0 * f + r0; c1 = c1 * f + r1; m = v;
        } else {
            float p = expf(v - m);
            s += p; c0 += p * r0; c1 += p * r1;
        }
    }
    float4 part = make_float4(m, s, c0, c1);
    g_cpart[((size_t)ch * NB + b) * NO + n] = part;
}

__global__ void __launch_bounds__(512) centers_comb_kernel() {
    const int b = blockIdx.x;
    const int n = threadIdx.x;
    float m = -1e30f;
#pragma unroll
    for (int ch = 0; ch < 4; ch++)
        m = fmaxf(m, g_cpart[((size_t)ch * NB + b) * NO + n].x);
    float s = 0.0f, c0 = 0.0f, c1 = 0.0f;
#pragma unroll
    for (int ch = 0; ch < 4; ch++) {
        float4 p = g_cpart[((size_t)ch * NB + b) * NO + n];
        float f = expf(p.x - m);
        s += p.y * f; c0 += p.z * f; c1 += p.w * f;
    }
    float inv = 1.0f / s;
    g_centers[((size_t)b * NO + n) * 2 + 0] = c0 * inv;
    g_centers[((size_t)b * NO + n) * 2 + 1] = c1 * inv;
}

// ---------------- cell-softmax -> expected position ------------------------
__global__ void __launch_bounds__(256) final_kernel(float* __restrict__ outp) {
    const int wrp = threadIdx.x >> 5;
    const int lane = threadIdx.x & 31;
    const int row = blockIdx.x * 8 + wrp;
    const int b = row >> 8;
    const float* o = g_out + (size_t)row * NO;

    float v[16];
    float vmax = -1e30f;
#pragma unroll
    for (int i = 0; i < 16; i++) {
        v[i] = o[lane + 32 * i];
        vmax = fmaxf(vmax, v[i]);
    }
#pragma unroll
    for (int off = 16; off; off >>= 1)
        vmax = fmaxf(vmax, __shfl_xor_sync(0xffffffffu, vmax, off));

    float s = 0.0f, a0 = 0.0f, a1 = 0.0f;
    const float* cen = g_centers + (size_t)b * NO * 2;
#pragma unroll
    for (int i = 0; i < 16; i++) {
        int n = lane + 32 * i;
        float p = expf(v[i] - vmax);
        s += p;
        float2 c = *(const float2*)(cen + n * 2);
        a0 += p * c.x; a1 += p * c.y;
    }
#pragma unroll
    for (int off = 16; off; off >>= 1) {
        s  += __shfl_xor_sync(0xffffffffu, s, off);
        a0 += __shfl_xor_sync(0xffffffffu, a0, off);
        a1 += __shfl_xor_sync(0xffffffffu, a1, off);
    }
    if (lane == 0) {
        float inv = 1.0f / s;
        outp[row * 2 + 0] = a0 * inv;
        outp[row * 2 + 1] = a1 * inv;
    }
}

extern "C" void kernel_launch(void* const* d_in, const int* in_sizes, int n_in,
                              void* d_out, int out_size) {
    const float* x    = (const float*)d_in[0];
    const float* r    = (const float*)d_in[1];
    const float* sW   = (const float*)d_in[2];
    const float* hW   = (const float*)d_in[3];
    const float* recW = (const float*)d_in[4];
    const float* recb = (const float*)d_in[5];
    const float* outW = (const float*)d_in[6];
    const float* outb = (const float*)d_in[7];
    const float* init = (const float*)d_in[8];
    float* outp = (float*)d_out;

    csc_phase1<<<NN / 16, 256>>>(recW);
    csc_phase2<<<NN / 256, 256>>>();
    {
        dim3 g(NN / 32, NO / 32);
        wsplit_kernel<<<g, 256>>>(outW);
    }
    {
        dim3 g(NT / 32, NB);
        drive_kernel<<<g, 512>>>(x, sW, hW);
    }
    rnn_diag_kernel<<<(NB * NN) / 256, 256>>>(recb, init);
    rnn_general_kernel<<<NB, 1024>>>(recb, init);
    {
        cudaFuncSetAttribute(outgemm_mma_kernel,
                             cudaFuncAttributeMaxDynamicSharedMemorySize, GEMM_SMEM);
        dim3 g(NO / 128, (NB * NT) / 128);
        outgemm_mma_kernel<<<g, 256, GEMM_SMEM>>>(outb);
    }
    {
        dim3 g(NB, 4);
        centers_part_kernel<<<g, 512>>>(r);
    }
    centers_comb_kernel<<<NB, 512>>>();
    final_kernel<<<(NB * NT) / 8, 256>>>(outp);
}

// round 11
// speedup vs baseline: 3.3137x; 1.0667x over previous
#include <cuda_runtime.h>
#include <cuda_bf16.h>
#include <math.h>
#include <stdint.h>

#define NB 64
#define NT 256
#define NN 1024
#define NO 512
#define NK_SPEED 20
#define NK_HD 50
#define NK_TOT 70
#define NKP 128
#define CMAX 4

__device__ float          g_drive[(size_t)NB * NT * NN];
__device__ __nv_bfloat16  g_ft_hi[(size_t)NB * NT * NKP];
__device__ __nv_bfloat16  g_ft_lo[(size_t)NB * NT * NKP];
__device__ __nv_bfloat16  g_wd_hi[(size_t)NN * NKP];
__device__ __nv_bfloat16  g_wd_lo[(size_t)NN * NKP];
__device__ __nv_bfloat16  g_hs_hi[(size_t)NB * NT * NN];
__device__ __nv_bfloat16  g_hs_lo[(size_t)NB * NT * NN];
__device__ __nv_bfloat16  g_wt_hi[(size_t)NO * NN];
__device__ __nv_bfloat16  g_wt_lo[(size_t)NO * NN];
__device__ float          g_out[(size_t)NB * NT * NO];
__device__ float          g_centers[NB * NO * 2];
__device__ float4         g_cpart[8 * NB * NO];
__device__ int            g_nnz_cnt[NN];
__device__ int            g_nnz_idx[(size_t)NN * NN];
__device__ float          g_nnz_val[(size_t)NN * NN];
__device__ int            g_tmp_idx[(size_t)NN * NN];
__device__ float          g_tmp_val[(size_t)NN * NN];
__device__ int            g_scnt[NN * 16];
__device__ float          g_wdiag[NN];
__device__ int            g_diag_flag;

// ---------------- CSC phase 1: 16 k-segments per column, 64 CTAs -----------
__global__ void __launch_bounds__(256) csc_phase1(const float* __restrict__ recW) {
    const int tid = threadIdx.x;
    const int n = blockIdx.x * 16 + (tid & 15);
    const int kt = tid >> 4;
    int c = 0;
    const int kbase = kt * 64;
    for (int i = 0; i < 64; i++) {
        float w = recW[(size_t)(kbase + i) * NN + n];
        if (w != 0.0f) {
            g_tmp_idx[(size_t)n * NN + kbase + c] = kbase + i;
            g_tmp_val[(size_t)n * NN + kbase + c] = w;
            c++;
        }
    }
    g_scnt[n * 16 + kt] = c;
    if (blockIdx.x == 0 && tid == 0) g_diag_flag = 1;
}

// ---------------- CSC phase 2: concat segments, detect diagonality ---------
__global__ void __launch_bounds__(256) csc_phase2() {
    const int n = blockIdx.x * 256 + threadIdx.x;
    int off = 0;
    bool diag = true;
    float wsum = 0.0f;
    for (int s = 0; s < 16; s++) {
        const int c = g_scnt[n * 16 + s];
        for (int i = 0; i < c; i++) {
            int k = g_tmp_idx[(size_t)n * NN + s * 64 + i];
            float w = g_tmp_val[(size_t)n * NN + s * 64 + i];
            g_nnz_idx[(size_t)n * NN + off] = k;
            g_nnz_val[(size_t)n * NN + off] = w;
            off++;
            if (k != n) diag = false; else wsum += w;
        }
    }
    g_nnz_cnt[n] = off;
    g_wdiag[n] = wsum;
    if (!diag) g_diag_flag = 0;
}

// ---------------- transpose + bf16-split out_W -> [NO][NN] -----------------
__global__ void __launch_bounds__(256) wsplit_kernel(const float* __restrict__ outW) {
    __shared__ float tile[32][33];
    const int k0 = blockIdx.x * 32, n0 = blockIdx.y * 32;
    const int tx = threadIdx.x & 31, ty = threadIdx.x >> 5;
#pragma unroll
    for (int i = 0; i < 4; i++)
        tile[ty + 8 * i][tx] = outW[(size_t)(k0 + ty + 8 * i) * NO + n0 + tx];
    __syncthreads();
#pragma unroll
    for (int i = 0; i < 4; i++) {
        int row = ty + 8 * i;
        float v = tile[tx][row];
        __nv_bfloat16 hi = __float2bfloat16(v);
        __nv_bfloat16 lo = __float2bfloat16(v - __bfloat162float(hi));
        size_t o = (size_t)(n0 + row) * NN + k0 + tx;
        g_wt_hi[o] = hi;
        g_wt_lo[o] = lo;
    }
}

// ---------------- bf16-split [speed_W; hd_W]^T -> [NN][NKP] ----------------
__global__ void __launch_bounds__(256) wdsplit_kernel(const float* __restrict__ sW,
                                                      const float* __restrict__ hW) {
    const int idx = blockIdx.x * 256 + threadIdx.x;   // over NN*NKP
    const int n = idx >> 7;
    const int k = idx & 127;
    float v = 0.0f;
    if (k < NK_SPEED)      v = sW[(size_t)k * NN + n];
    else if (k < NK_TOT)   v = hW[(size_t)(k - NK_SPEED) * NN + n];
    __nv_bfloat16 hi = __float2bfloat16(v);
    __nv_bfloat16 lo = __float2bfloat16(v - __bfloat162float(hi));
    g_wd_hi[idx] = hi;
    g_wd_lo[idx] = lo;
}

// ---------------- features -> bf16 hi/lo, K padded to 128 ------------------
__global__ void __launch_bounds__(256) feat_kernel(const float* __restrict__ x) {
    const int idx = blockIdx.x * 256 + threadIdx.x;   // over 16384*NKP
    const int row = idx >> 7;                         // b*NT + t
    const int k = idx & 127;
    const float TWO_PI = 6.2831853071795865f;
    const float LOGNORM = 6.3050317f;  // log(2*pi*I0(2*pi))
    float f = 0.0f;
    if (k < NK_SPEED) {
        float v = x[(size_t)row * 2 + 0];
        float dv = v - 0.5f * (float)k / 19.0f;
        f = expf(-800.0f * dv * dv);
    } else if (k < NK_TOT) {
        float th = x[(size_t)row * 2 + 1];
        float c = TWO_PI * (float)(k - NK_SPEED) / 49.0f;
        f = expf(TWO_PI * cosf(th - c) - LOGNORM);
    }
    __nv_bfloat16 hi = __float2bfloat16(f);
    __nv_bfloat16 lo = __float2bfloat16(f - __bfloat162float(hi));
    g_ft_hi[idx] = hi;
    g_ft_lo[idx] = lo;
}

// ---------------- common GEMM machinery ------------------------------------
#define TS 72
#define TILE_ELEMS (128 * TS)
#define BUF_ELEMS (4 * TILE_ELEMS)
#define GEMM_SMEM (2 * BUF_ELEMS * 2)

__device__ __forceinline__ void cp16(void* smem_dst, const void* gsrc) {
    uint32_t s = (uint32_t)__cvta_generic_to_shared(smem_dst);
    asm volatile("cp.async.cg.shared.global [%0], [%1], 16;" :: "r"(s), "l"(gsrc) : "memory");
}
__device__ __forceinline__ void cp_commit() {
    asm volatile("cp.async.commit_group;" ::: "memory");
}
template <int N>
__device__ __forceinline__ void cp_wait() {
    asm volatile("cp.async.wait_group %0;" :: "n"(N) : "memory");
}
__device__ __forceinline__ void mma_bf16(float* d, const uint32_t* a, const uint32_t* b) {
    asm volatile(
        "mma.sync.aligned.m16n8k16.row.col.f32.bf16.bf16.f32 "
        "{%0,%1,%2,%3}, {%4,%5,%6,%7}, {%8,%9}, {%0,%1,%2,%3};"
        : "+f"(d[0]), "+f"(d[1]), "+f"(d[2]), "+f"(d[3])
        : "r"(a[0]), "r"(a[1]), "r"(a[2]), "r"(a[3]), "r"(b[0]), "r"(b[1]));
}

// compute one 64-k chunk of MMAs from staged tiles
__device__ __forceinline__ void gemm_chunk(const __nv_bfloat16* Ah, float acc[4][4][4],
                                           int wm, int wn, int gid, int tig) {
    const __nv_bfloat16* Al = Ah + TILE_ELEMS;
    const __nv_bfloat16* Bh = Ah + 2 * TILE_ELEMS;
    const __nv_bfloat16* Bl = Ah + 3 * TILE_ELEMS;
#pragma unroll
    for (int ks = 0; ks < 4; ks++) {
        const int kc = ks * 16 + tig * 2;
        uint32_t ahi[4][4], alo[4][4], bhi[4][2], blo[4][2];
#pragma unroll
        for (int mt = 0; mt < 4; mt++) {
            const int r = wm * 64 + mt * 16 + gid;
            ahi[mt][0] = *(const uint32_t*)(Ah + r * TS + kc);
            ahi[mt][1] = *(const uint32_t*)(Ah + (r + 8) * TS + kc);
            ahi[mt][2] = *(const uint32_t*)(Ah + r * TS + kc + 8);
            ahi[mt][3] = *(const uint32_t*)(Ah + (r + 8) * TS + kc + 8);
            alo[mt][0] = *(const uint32_t*)(Al + r * TS + kc);
            alo[mt][1] = *(const uint32_t*)(Al + (r + 8) * TS + kc);
            alo[mt][2] = *(const uint32_t*)(Al + r * TS + kc + 8);
            alo[mt][3] = *(const uint32_t*)(Al + (r + 8) * TS + kc + 8);
        }
#pragma unroll
        for (int nt = 0; nt < 4; nt++) {
            const int nr = wn * 32 + nt * 8 + gid;
            bhi[nt][0] = *(const uint32_t*)(Bh + nr * TS + kc);
            bhi[nt][1] = *(const uint32_t*)(Bh + nr * TS + kc + 8);
            blo[nt][0] = *(const uint32_t*)(Bl + nr * TS + kc);
            blo[nt][1] = *(const uint32_t*)(Bl + nr * TS + kc + 8);
        }
#pragma unroll
        for (int mt = 0; mt < 4; mt++)
#pragma unroll
            for (int nt = 0; nt < 4; nt++) {
                mma_bf16(acc[mt][nt], ahi[mt], bhi[nt]);
                mma_bf16(acc[mt][nt], ahi[mt], blo[nt]);
                mma_bf16(acc[mt][nt], alo[mt], bhi[nt]);
            }
    }
}

// ---------------- drive GEMM: feats @ Wd, K=128 (2 chunks) -----------------
__global__ void __launch_bounds__(256, 1) drivegemm_mma_kernel() {
    extern __shared__ __nv_bfloat16 smem[];
    const int tid = threadIdx.x;
    const int wid = tid >> 5, lane = tid & 31;
    const int gid = lane >> 2, tig = lane & 3;
    const int wm = wid >> 2, wn = wid & 3;
    const int n0 = blockIdx.x * 128;
    const int row0 = blockIdx.y * 128;

    float acc[4][4][4];
#pragma unroll
    for (int mt = 0; mt < 4; mt++)
#pragma unroll
        for (int nt = 0; nt < 4; nt++)
#pragma unroll
            for (int j = 0; j < 4; j++) acc[mt][nt][j] = 0.0f;

    const int srow = tid >> 1;
    const int scol = (tid & 1) * 32;
    const __nv_bfloat16* gA = g_ft_hi + (size_t)(row0 + srow) * NKP + scol;
    const __nv_bfloat16* gL = g_ft_lo + (size_t)(row0 + srow) * NKP + scol;
    const __nv_bfloat16* gB = g_wd_hi + (size_t)(n0 + srow) * NKP + scol;
    const __nv_bfloat16* gM = g_wd_lo + (size_t)(n0 + srow) * NKP + scol;
    const int sbase = srow * TS + scol;

#pragma unroll
    for (int c = 0; c < 2; c++) {
        __nv_bfloat16* base = smem + c * BUF_ELEMS;
        const int k0 = c * 64;
#pragma unroll
        for (int q = 0; q < 4; q++) {
            cp16(base + 0 * TILE_ELEMS + sbase + q * 8, gA + k0 + q * 8);
            cp16(base + 1 * TILE_ELEMS + sbase + q * 8, gL + k0 + q * 8);
            cp16(base + 2 * TILE_ELEMS + sbase + q * 8, gB + k0 + q * 8);
            cp16(base + 3 * TILE_ELEMS + sbase + q * 8, gM + k0 + q * 8);
        }
        cp_commit();
    }
    cp_wait<1>();
    __syncthreads();
    gemm_chunk(smem, acc, wm, wn, gid, tig);
    cp_wait<0>();
    __syncthreads();
    gemm_chunk(smem + BUF_ELEMS, acc, wm, wn, gid, tig);

#pragma unroll
    for (int nt = 0; nt < 4; nt++) {
        const int col = n0 + wn * 32 + nt * 8 + tig * 2;
#pragma unroll
        for (int mt = 0; mt < 4; mt++) {
            const int r = row0 + wm * 64 + mt * 16 + gid;
            *(float2*)(g_drive + (size_t)r * NN + col) = make_float2(acc[mt][nt][0], acc[mt][nt][1]);
            *(float2*)(g_drive + (size_t)(r + 8) * NN + col) = make_float2(acc[mt][nt][2], acc[mt][nt][3]);
        }
    }
}

// ---------------- RNN fast path: diagonal rec_W, no barriers ---------------
__global__ void __launch_bounds__(256) rnn_diag_kernel(const float* __restrict__ rec_b,
                                                       const float* __restrict__ init_state) {
    if (*(volatile int*)&g_diag_flag == 0) return;
    const int gtid = blockIdx.x * 256 + threadIdx.x;
    const int b = gtid >> 10;
    const int n = gtid & 1023;

    const float w = g_wdiag[n];
    const float rb = rec_b[n];
    float h = init_state[n];
    const float* dp = g_drive + (size_t)b * NT * NN + n;
    __nv_bfloat16* hh = g_hs_hi + (size_t)b * NT * NN + n;
    __nv_bfloat16* hl = g_hs_lo + (size_t)b * NT * NN + n;

    float d = dp[0];
    for (int t = 0; t < NT; t++) {
        float dn = (t + 1 < NT) ? dp[(size_t)(t + 1) * NN] : 0.0f;
        h = fmaxf(fmaf(h, w, rb + d), 0.0f);
        __nv_bfloat16 hb = __float2bfloat16(h);
        hh[(size_t)t * NN] = hb;
        hl[(size_t)t * NN] = __float2bfloat16(h - __bfloat162float(hb));
        d = dn;
    }
}

// ---------------- RNN general fallback: h in SMEM, 1 bar/step --------------
__global__ void __launch_bounds__(1024, 1) rnn_general_kernel(const float* __restrict__ rec_b,
                                                              const float* __restrict__ init_state) {
    if (*(volatile int*)&g_diag_flag != 0) return;
    __shared__ float hbuf[2][NN];
    const int b = blockIdx.x;
    const int n = threadIdx.x;

    const float rb = rec_b[n];
    const int cnt = g_nnz_cnt[n];
    const int cr = cnt < CMAX ? cnt : CMAX;
    int kk[CMAX]; float ww[CMAX];
    for (int j = 0; j < cr; j++) {
        kk[j] = g_nnz_idx[(size_t)n * NN + j];
        ww[j] = g_nnz_val[(size_t)n * NN + j];
    }
    hbuf[0][n] = init_state[n];
    __syncthreads();

    float d = g_drive[(size_t)b * NT * NN + n];

    for (int t = 0; t < NT; t++) {
        const float* cur = hbuf[t & 1];
        float* nxt = hbuf[(t + 1) & 1];
        float dn = 0.0f;
        if (t + 1 < NT)
            dn = g_drive[((size_t)b * NT + t + 1) * NN + n];

        float acc = rb + d;
        for (int j = 0; j < cr; j++)
            acc += cur[kk[j]] * ww[j];
        for (int j = CMAX; j < cnt; j++)
            acc += cur[g_nnz_idx[(size_t)n * NN + j]] * g_nnz_val[(size_t)n * NN + j];
        float hv = fmaxf(acc, 0.0f);
        nxt[n] = hv;
        const size_t row = ((size_t)b * NT + t) * NN;
        __nv_bfloat16 hb = __float2bfloat16(hv);
        g_hs_hi[row + n] = hb;
        g_hs_lo[row + n] = __float2bfloat16(hv - __bfloat162float(hb));
        __syncthreads();
        d = dn;
    }
}

// ---------------- out-GEMM: hs @ out_W^T, K=1024 (16 chunks) ---------------
__global__ void __launch_bounds__(256, 1) outgemm_mma_kernel(const float* __restrict__ outB) {
    extern __shared__ __nv_bfloat16 smem[];
    const int tid = threadIdx.x;
    const int wid = tid >> 5, lane = tid & 31;
    const int gid = lane >> 2, tig = lane & 3;
    const int wm = wid >> 2, wn = wid & 3;
    const int n0 = blockIdx.x * 128;
    const int row0 = blockIdx.y * 128;

    float acc[4][4][4];
#pragma unroll
    for (int mt = 0; mt < 4; mt++)
#pragma unroll
        for (int nt = 0; nt < 4; nt++)
#pragma unroll
            for (int j = 0; j < 4; j++) acc[mt][nt][j] = 0.0f;

    const int srow = tid >> 1;
    const int scol = (tid & 1) * 32;
    const __nv_bfloat16* gA = g_hs_hi + (size_t)(row0 + srow) * NN + scol;
    const __nv_bfloat16* gL = g_hs_lo + (size_t)(row0 + srow) * NN + scol;
    const __nv_bfloat16* gB = g_wt_hi + (size_t)(n0 + srow) * NN + scol;
    const __nv_bfloat16* gM = g_wt_lo + (size_t)(n0 + srow) * NN + scol;
    const int sbase = srow * TS + scol;

    auto load_chunk = [&](int c, int buf) {
        __nv_bfloat16* base = smem + buf * BUF_ELEMS;
        const int k0 = c * 64;
#pragma unroll
        for (int q = 0; q < 4; q++) {
            cp16(base + 0 * TILE_ELEMS + sbase + q * 8, gA + k0 + q * 8);
            cp16(base + 1 * TILE_ELEMS + sbase + q * 8, gL + k0 + q * 8);
            cp16(base + 2 * TILE_ELEMS + sbase + q * 8, gB + k0 + q * 8);
            cp16(base + 3 * TILE_ELEMS + sbase + q * 8, gM + k0 + q * 8);
        }
    };

    load_chunk(0, 0);
    cp_commit();

    for (int c = 0; c < 16; c++) {
        if (c < 15) {
            load_chunk(c + 1, (c + 1) & 1);
            cp_commit();
            cp_wait<1>();
        } else {
            cp_wait<0>();
        }
        __syncthreads();
        gemm_chunk(smem + (c & 1) * BUF_ELEMS, acc, wm, wn, gid, tig);
        __syncthreads();
    }

#pragma unroll
    for (int nt = 0; nt < 4; nt++) {
        const int col = n0 + wn * 32 + nt * 8 + tig * 2;
        const float b0 = outB[col], b1 = outB[col + 1];
#pragma unroll
        for (int mt = 0; mt < 4; mt++) {
            const int r = row0 + wm * 64 + mt * 16 + gid;
            float2 o0, o1;
            o0.x = fmaxf(acc[mt][nt][0] + b0, 0.0f);
            o0.y = fmaxf(acc[mt][nt][1] + b1, 0.0f);
            o1.x = fmaxf(acc[mt][nt][2] + b0, 0.0f);
            o1.y = fmaxf(acc[mt][nt][3] + b1, 0.0f);
            *(float2*)(g_out + (size_t)r * NO + col) = o0;
            *(float2*)(g_out + (size_t)(r + 8) * NO + col) = o1;
        }
    }
}

// ---------------- time-softmax -> centers, 2-phase (8 chunks) --------------
__global__ void __launch_bounds__(512) centers_part_kernel(const float* __restrict__ r) {
    const int b = blockIdx.x;
    const int ch = blockIdx.y;            // 8 time chunks of 32
    const int n = threadIdx.x;
    float m = -1e30f, s = 0.0f, c0 = 0.0f, c1 = 0.0f;
    const float* ob = g_out + (size_t)b * NT * NO + (size_t)ch * 32 * NO;
    const float* rb = r + (size_t)b * NT * 2 + ch * 32 * 2;
    for (int t = 0; t < 32; t++) {
        float v = ob[(size_t)t * NO + n];
        float r0 = rb[t * 2 + 0], r1 = rb[t * 2 + 1];
        if (v > m) {
            float f = expf(m - v);
            s = s * f + 1.0f; c0 = c0 * f + r0; c1 = c1 * f + r1; m = v;
        } else {
            float p = expf(v - m);
            s += p; c0 += p * r0; c1 += p * r1;
        }
    }
    g_cpart[((size_t)ch * NB + b) * NO + n] = make_float4(m, s, c0, c1);
}

__global__ void __launch_bounds__(512) centers_comb_kernel() {
    const int b = blockIdx.x;
    const int n = threadIdx.x;
    float m = -1e30f;
#pragma unroll
    for (int ch = 0; ch < 8; ch++)
        m = fmaxf(m, g_cpart[((size_t)ch * NB + b) * NO + n].x);
    float s = 0.0f, c0 = 0.0f, c1 = 0.0f;
#pragma unroll
    for (int ch = 0; ch < 8; ch++) {
        float4 p = g_cpart[((size_t)ch * NB + b) * NO + n];
        float f = expf(p.x - m);
        s += p.y * f; c0 += p.z * f; c1 += p.w * f;
    }
    float inv = 1.0f / s;
    g_centers[((size_t)b * NO + n) * 2 + 0] = c0 * inv;
    g_centers[((size_t)b * NO + n) * 2 + 1] = c1 * inv;
}

// ---------------- cell-softmax -> expected position ------------------------
__global__ void __launch_bounds__(256) final_kernel(float* __restrict__ outp) {
    const int wrp = threadIdx.x >> 5;
    const int lane = threadIdx.x & 31;
    const int row = blockIdx.x * 8 + wrp;
    const int b = row >> 8;
    const float* o = g_out + (size_t)row * NO;

    float v[16];
    float vmax = -1e30f;
#pragma unroll
    for (int i = 0; i < 16; i++) {
        v[i] = o[lane + 32 * i];
        vmax = fmaxf(vmax, v[i]);
    }
#pragma unroll
    for (int off = 16; off; off >>= 1)
        vmax = fmaxf(vmax, __shfl_xor_sync(0xffffffffu, vmax, off));

    float s = 0.0f, a0 = 0.0f, a1 = 0.0f;
    const float* cen = g_centers + (size_t)b * NO * 2;
#pragma unroll
    for (int i = 0; i < 16; i++) {
        int n = lane + 32 * i;
        float p = expf(v[i] - vmax);
        s += p;
        float2 c = *(const float2*)(cen + n * 2);
        a0 += p * c.x; a1 += p * c.y;
    }
#pragma unroll
    for (int off = 16; off; off >>= 1) {
        s  += __shfl_xor_sync(0xffffffffu, s, off);
        a0 += __shfl_xor_sync(0xffffffffu, a0, off);
        a1 += __shfl_xor_sync(0xffffffffu, a1, off);
    }
    if (lane == 0) {
        float inv = 1.0f / s;
        outp[row * 2 + 0] = a0 * inv;
        outp[row * 2 + 1] = a1 * inv;
    }
}

extern "C" void kernel_launch(void* const* d_in, const int* in_sizes, int n_in,
                              void* d_out, int out_size) {
    const float* x    = (const float*)d_in[0];
    const float* r    = (const float*)d_in[1];
    const float* sW   = (const float*)d_in[2];
    const float* hW   = (const float*)d_in[3];
    const float* recW = (const float*)d_in[4];
    const float* recb = (const float*)d_in[5];
    const float* outW = (const float*)d_in[6];
    const float* outb = (const float*)d_in[7];
    const float* init = (const float*)d_in[8];
    float* outp = (float*)d_out;

    csc_phase1<<<NN / 16, 256>>>(recW);
    csc_phase2<<<NN / 256, 256>>>();
    {
        dim3 g(NN / 32, NO / 32);
        wsplit_kernel<<<g, 256>>>(outW);
    }
    wdsplit_kernel<<<(NN * NKP) / 256, 256>>>(sW, hW);
    feat_kernel<<<(NB * NT * NKP) / 256, 256>>>(x);
    {
        cudaFuncSetAttribute(drivegemm_mma_kernel,
                             cudaFuncAttributeMaxDynamicSharedMemorySize, GEMM_SMEM);
        dim3 g(NN / 128, (NB * NT) / 128);
        drivegemm_mma_kernel<<<g, 256, GEMM_SMEM>>>();
    }
    rnn_diag_kernel<<<(NB * NN) / 256, 256>>>(recb, init);
    rnn_general_kernel<<<NB, 1024>>>(recb, init);
    {
        cudaFuncSetAttribute(outgemm_mma_kernel,
                             cudaFuncAttributeMaxDynamicSharedMemorySize, GEMM_SMEM);
        dim3 g(NO / 128, (NB * NT) / 128);
        outgemm_mma_kernel<<<g, 256, GEMM_SMEM>>>(outb);
    }
    {
        dim3 g(NB, 8);
        centers_part_kernel<<<g, 512>>>(r);
    }
    centers_comb_kernel<<<NB, 512>>>();
    final_kernel<<<(NB * NT) / 8, 256>>>(outp);
}

// round 12
// speedup vs baseline: 3.3617x; 1.0145x over previous
#include <cuda_runtime.h>
#include <cuda_bf16.h>
#include <math.h>
#include <stdint.h>

#define NB 64
#define NT 256
#define NN 1024
#define NO 512
#define NK_SPEED 20
#define NK_HD 50
#define NK_TOT 70
#define NKP 128
#define CMAX 4

__device__ float          g_drive[(size_t)NB * NT * NN];
__device__ __nv_bfloat16  g_ft_hi[(size_t)NB * NT * NKP];
__device__ __nv_bfloat16  g_ft_lo[(size_t)NB * NT * NKP];
__device__ __nv_bfloat16  g_wd_hi[(size_t)NN * NKP];
__device__ __nv_bfloat16  g_wd_lo[(size_t)NN * NKP];
__device__ __nv_bfloat16  g_hs_hi[(size_t)NB * NT * NN];
__device__ __nv_bfloat16  g_hs_lo[(size_t)NB * NT * NN];
__device__ __nv_bfloat16  g_wt_hi[(size_t)NO * NN];
__device__ __nv_bfloat16  g_wt_lo[(size_t)NO * NN];
__device__ float          g_out[(size_t)NB * NT * NO];
__device__ float          g_centers[NB * NO * 2];
__device__ float4         g_cpart[8 * NB * NO];
__device__ int            g_nnz_cnt[NN];
__device__ int            g_nnz_idx[(size_t)NN * NN];
__device__ float          g_nnz_val[(size_t)NN * NN];
__device__ int            g_tmp_idx[(size_t)NN * NN];
__device__ float          g_tmp_val[(size_t)NN * NN];
__device__ int            g_scnt[NN * 16];
__device__ float          g_wdiag[NN];
__device__ int            g_diag_flag;

// ---------------- CSC phase 1: 16 k-segments per column, 64 CTAs -----------
__global__ void __launch_bounds__(256) csc_phase1(const float* __restrict__ recW) {
    const int tid = threadIdx.x;
    const int n = blockIdx.x * 16 + (tid & 15);
    const int kt = tid >> 4;
    int c = 0;
    const int kbase = kt * 64;
    for (int i = 0; i < 64; i++) {
        float w = recW[(size_t)(kbase + i) * NN + n];
        if (w != 0.0f) {
            g_tmp_idx[(size_t)n * NN + kbase + c] = kbase + i;
            g_tmp_val[(size_t)n * NN + kbase + c] = w;
            c++;
        }
    }
    g_scnt[n * 16 + kt] = c;
    if (blockIdx.x == 0 && tid == 0) g_diag_flag = 1;
}

// ---------------- CSC phase 2: concat segments, detect diagonality ---------
__global__ void __launch_bounds__(256) csc_phase2() {
    const int n = blockIdx.x * 256 + threadIdx.x;
    int off = 0;
    bool diag = true;
    float wsum = 0.0f;
    for (int s = 0; s < 16; s++) {
        const int c = g_scnt[n * 16 + s];
        for (int i = 0; i < c; i++) {
            int k = g_tmp_idx[(size_t)n * NN + s * 64 + i];
            float w = g_tmp_val[(size_t)n * NN + s * 64 + i];
            g_nnz_idx[(size_t)n * NN + off] = k;
            g_nnz_val[(size_t)n * NN + off] = w;
            off++;
            if (k != n) diag = false; else wsum += w;
        }
    }
    g_nnz_cnt[n] = off;
    g_wdiag[n] = wsum;
    if (!diag) g_diag_flag = 0;
}

// ---------------- transpose + bf16-split out_W -> [NO][NN] -----------------
__global__ void __launch_bounds__(256) wsplit_kernel(const float* __restrict__ outW) {
    __shared__ float tile[32][33];
    const int k0 = blockIdx.x * 32, n0 = blockIdx.y * 32;
    const int tx = threadIdx.x & 31, ty = threadIdx.x >> 5;
#pragma unroll
    for (int i = 0; i < 4; i++)
        tile[ty + 8 * i][tx] = outW[(size_t)(k0 + ty + 8 * i) * NO + n0 + tx];
    __syncthreads();
#pragma unroll
    for (int i = 0; i < 4; i++) {
        int row = ty + 8 * i;
        float v = tile[tx][row];
        __nv_bfloat16 hi = __float2bfloat16(v);
        __nv_bfloat16 lo = __float2bfloat16(v - __bfloat162float(hi));
        size_t o = (size_t)(n0 + row) * NN + k0 + tx;
        g_wt_hi[o] = hi;
        g_wt_lo[o] = lo;
    }
}

// ---------------- bf16-split [speed_W; hd_W]^T -> [NN][NKP] ----------------
__global__ void __launch_bounds__(256) wdsplit_kernel(const float* __restrict__ sW,
                                                      const float* __restrict__ hW) {
    const int idx = blockIdx.x * 256 + threadIdx.x;
    const int n = idx >> 7;
    const int k = idx & 127;
    float v = 0.0f;
    if (k < NK_SPEED)      v = sW[(size_t)k * NN + n];
    else if (k < NK_TOT)   v = hW[(size_t)(k - NK_SPEED) * NN + n];
    __nv_bfloat16 hi = __float2bfloat16(v);
    __nv_bfloat16 lo = __float2bfloat16(v - __bfloat162float(hi));
    g_wd_hi[idx] = hi;
    g_wd_lo[idx] = lo;
}

// ---------------- features -> bf16 hi/lo, K padded to 128 ------------------
__global__ void __launch_bounds__(256) feat_kernel(const float* __restrict__ x) {
    const int idx = blockIdx.x * 256 + threadIdx.x;
    const int row = idx >> 7;
    const int k = idx & 127;
    const float TWO_PI = 6.2831853071795865f;
    const float LOGNORM = 6.3050317f;  // log(2*pi*I0(2*pi))
    float f = 0.0f;
    if (k < NK_SPEED) {
        float v = x[(size_t)row * 2 + 0];
        float dv = v - 0.5f * (float)k / 19.0f;
        f = expf(-800.0f * dv * dv);
    } else if (k < NK_TOT) {
        float th = x[(size_t)row * 2 + 1];
        float c = TWO_PI * (float)(k - NK_SPEED) / 49.0f;
        f = expf(TWO_PI * cosf(th - c) - LOGNORM);
    }
    __nv_bfloat16 hi = __float2bfloat16(f);
    __nv_bfloat16 lo = __float2bfloat16(f - __bfloat162float(hi));
    g_ft_hi[idx] = hi;
    g_ft_lo[idx] = lo;
}

// ---------------- common GEMM machinery ------------------------------------
#define TS 72
#define TILE_ELEMS (128 * TS)
#define BUF_ELEMS (4 * TILE_ELEMS)
#define GEMM_SMEM2 (2 * BUF_ELEMS * 2)
#define GEMM_SMEM3 (3 * BUF_ELEMS * 2)

__device__ __forceinline__ void cp16(void* smem_dst, const void* gsrc) {
    uint32_t s = (uint32_t)__cvta_generic_to_shared(smem_dst);
    asm volatile("cp.async.cg.shared.global [%0], [%1], 16;" :: "r"(s), "l"(gsrc) : "memory");
}
__device__ __forceinline__ void cp_commit() {
    asm volatile("cp.async.commit_group;" ::: "memory");
}
template <int N>
__device__ __forceinline__ void cp_wait() {
    asm volatile("cp.async.wait_group %0;" :: "n"(N) : "memory");
}
__device__ __forceinline__ void mma_bf16(float* d, const uint32_t* a, const uint32_t* b) {
    asm volatile(
        "mma.sync.aligned.m16n8k16.row.col.f32.bf16.bf16.f32 "
        "{%0,%1,%2,%3}, {%4,%5,%6,%7}, {%8,%9}, {%0,%1,%2,%3};"
        : "+f"(d[0]), "+f"(d[1]), "+f"(d[2]), "+f"(d[3])
        : "r"(a[0]), "r"(a[1]), "r"(a[2]), "r"(a[3]), "r"(b[0]), "r"(b[1]));
}
__device__ __forceinline__ void ldsm4(uint32_t* r, const __nv_bfloat16* p) {
    uint32_t a = (uint32_t)__cvta_generic_to_shared(p);
    asm volatile("ldmatrix.sync.aligned.m8n8.x4.shared.b16 {%0,%1,%2,%3}, [%4];"
                 : "=r"(r[0]), "=r"(r[1]), "=r"(r[2]), "=r"(r[3]) : "r"(a));
}

// one 64-k chunk of MMAs from staged tiles, ldmatrix fragment loads
__device__ __forceinline__ void gemm_chunk(const __nv_bfloat16* Ah, float acc[4][4][4],
                                           int wm, int wn, int lane) {
    const __nv_bfloat16* Al = Ah + TILE_ELEMS;
    const __nv_bfloat16* Bh = Ah + 2 * TILE_ELEMS;
    const __nv_bfloat16* Bl = Ah + 3 * TILE_ELEMS;
    const int quad = lane >> 3, rowin = lane & 7;
    // A: quads -> (m + {0,8}, k + {0,8});  B: quads -> (n + {0,8}, k + {0,8})
    const int a_m = wm * 64 + (quad & 1) * 8 + rowin;
    const int a_k = (quad >> 1) * 8;
    const int b_n = wn * 32 + (quad >> 1) * 8 + rowin;
    const int b_k = (quad & 1) * 8;
#pragma unroll
    for (int ks = 0; ks < 4; ks++) {
        const int kc0 = ks * 16;
        uint32_t ahi[4][4], alo[4][4], bhi[4][2], blo[4][2];
#pragma unroll
        for (int mt = 0; mt < 4; mt++) {
            const int off = (a_m + mt * 16) * TS + kc0 + a_k;
            ldsm4(ahi[mt], Ah + off);
            ldsm4(alo[mt], Al + off);
        }
#pragma unroll
        for (int j = 0; j < 2; j++) {      // nt pair (2j, 2j+1)
            const int off = (b_n + j * 16) * TS + kc0 + b_k;
            uint32_t th[4], tl[4];
            ldsm4(th, Bh + off);
            ldsm4(tl, Bl + off);
            bhi[2 * j][0] = th[0]; bhi[2 * j][1] = th[1];
            bhi[2 * j + 1][0] = th[2]; bhi[2 * j + 1][1] = th[3];
            blo[2 * j][0] = tl[0]; blo[2 * j][1] = tl[1];
            blo[2 * j + 1][0] = tl[2]; blo[2 * j + 1][1] = tl[3];
        }
#pragma unroll
        for (int mt = 0; mt < 4; mt++)
#pragma unroll
            for (int nt = 0; nt < 4; nt++) {
                mma_bf16(acc[mt][nt], ahi[mt], bhi[nt]);
                mma_bf16(acc[mt][nt], ahi[mt], blo[nt]);
                mma_bf16(acc[mt][nt], alo[mt], bhi[nt]);
            }
    }
}

// ---------------- drive GEMM: feats @ Wd, K=128 (2 chunks) -----------------
__global__ void __launch_bounds__(256, 1) drivegemm_mma_kernel() {
    extern __shared__ __nv_bfloat16 smem[];
    const int tid = threadIdx.x;
    const int wid = tid >> 5, lane = tid & 31;
    const int gid = lane >> 2, tig = lane & 3;
    const int wm = wid >> 2, wn = wid & 3;
    const int n0 = blockIdx.x * 128;
    const int row0 = blockIdx.y * 128;

    float acc[4][4][4];
#pragma unroll
    for (int mt = 0; mt < 4; mt++)
#pragma unroll
        for (int nt = 0; nt < 4; nt++)
#pragma unroll
            for (int j = 0; j < 4; j++) acc[mt][nt][j] = 0.0f;

    const int srow = tid >> 1;
    const int scol = (tid & 1) * 32;
    const __nv_bfloat16* gA = g_ft_hi + (size_t)(row0 + srow) * NKP + scol;
    const __nv_bfloat16* gL = g_ft_lo + (size_t)(row0 + srow) * NKP + scol;
    const __nv_bfloat16* gB = g_wd_hi + (size_t)(n0 + srow) * NKP + scol;
    const __nv_bfloat16* gM = g_wd_lo + (size_t)(n0 + srow) * NKP + scol;
    const int sbase = srow * TS + scol;

#pragma unroll
    for (int c = 0; c < 2; c++) {
        __nv_bfloat16* base = smem + c * BUF_ELEMS;
        const int k0 = c * 64;
#pragma unroll
        for (int q = 0; q < 4; q++) {
            cp16(base + 0 * TILE_ELEMS + sbase + q * 8, gA + k0 + q * 8);
            cp16(base + 1 * TILE_ELEMS + sbase + q * 8, gL + k0 + q * 8);
            cp16(base + 2 * TILE_ELEMS + sbase + q * 8, gB + k0 + q * 8);
            cp16(base + 3 * TILE_ELEMS + sbase + q * 8, gM + k0 + q * 8);
        }
        cp_commit();
    }
    cp_wait<1>();
    __syncthreads();
    gemm_chunk(smem, acc, wm, wn, lane);
    cp_wait<0>();
    __syncthreads();
    gemm_chunk(smem + BUF_ELEMS, acc, wm, wn, lane);

#pragma unroll
    for (int nt = 0; nt < 4; nt++) {
        const int col = n0 + wn * 32 + nt * 8 + tig * 2;
#pragma unroll
        for (int mt = 0; mt < 4; mt++) {
            const int r = row0 + wm * 64 + mt * 16 + gid;
            *(float2*)(g_drive + (size_t)r * NN + col) = make_float2(acc[mt][nt][0], acc[mt][nt][1]);
            *(float2*)(g_drive + (size_t)(r + 8) * NN + col) = make_float2(acc[mt][nt][2], acc[mt][nt][3]);
        }
    }
}

// ---------------- RNN fast path: diagonal rec_W, no barriers ---------------
__global__ void __launch_bounds__(256) rnn_diag_kernel(const float* __restrict__ rec_b,
                                                       const float* __restrict__ init_state) {
    if (*(volatile int*)&g_diag_flag == 0) return;
    const int gtid = blockIdx.x * 256 + threadIdx.x;
    const int b = gtid >> 10;
    const int n = gtid & 1023;

    const float w = g_wdiag[n];
    const float rb = rec_b[n];
    float h = init_state[n];
    const float* dp = g_drive + (size_t)b * NT * NN + n;
    __nv_bfloat16* hh = g_hs_hi + (size_t)b * NT * NN + n;
    __nv_bfloat16* hl = g_hs_lo + (size_t)b * NT * NN + n;

    float d = dp[0];
    for (int t = 0; t < NT; t++) {
        float dn = (t + 1 < NT) ? dp[(size_t)(t + 1) * NN] : 0.0f;
        h = fmaxf(fmaf(h, w, rb + d), 0.0f);
        __nv_bfloat16 hb = __float2bfloat16(h);
        hh[(size_t)t * NN] = hb;
        hl[(size_t)t * NN] = __float2bfloat16(h - __bfloat162float(hb));
        d = dn;
    }
}

// ---------------- RNN general fallback: h in SMEM, 1 bar/step --------------
__global__ void __launch_bounds__(1024, 1) rnn_general_kernel(const float* __restrict__ rec_b,
                                                              const float* __restrict__ init_state) {
    if (*(volatile int*)&g_diag_flag != 0) return;
    __shared__ float hbuf[2][NN];
    const int b = blockIdx.x;
    const int n = threadIdx.x;

    const float rb = rec_b[n];
    const int cnt = g_nnz_cnt[n];
    const int cr = cnt < CMAX ? cnt : CMAX;
    int kk[CMAX]; float ww[CMAX];
    for (int j = 0; j < cr; j++) {
        kk[j] = g_nnz_idx[(size_t)n * NN + j];
        ww[j] = g_nnz_val[(size_t)n * NN + j];
    }
    hbuf[0][n] = init_state[n];
    __syncthreads();

    float d = g_drive[(size_t)b * NT * NN + n];

    for (int t = 0; t < NT; t++) {
        const float* cur = hbuf[t & 1];
        float* nxt = hbuf[(t + 1) & 1];
        float dn = 0.0f;
        if (t + 1 < NT)
            dn = g_drive[((size_t)b * NT + t + 1) * NN + n];

        float acc = rb + d;
        for (int j = 0; j < cr; j++)
            acc += cur[kk[j]] * ww[j];
        for (int j = CMAX; j < cnt; j++)
            acc += cur[g_nnz_idx[(size_t)n * NN + j]] * g_nnz_val[(size_t)n * NN + j];
        float hv = fmaxf(acc, 0.0f);
        nxt[n] = hv;
        const size_t row = ((size_t)b * NT + t) * NN;
        __nv_bfloat16 hb = __float2bfloat16(hv);
        g_hs_hi[row + n] = hb;
        g_hs_lo[row + n] = __float2bfloat16(hv - __bfloat162float(hb));
        __syncthreads();
        d = dn;
    }
}

// ---------------- out-GEMM: hs @ out_W^T, K=1024, 3-stage pipeline ---------
__global__ void __launch_bounds__(256, 1) outgemm_mma_kernel(const float* __restrict__ outB) {
    extern __shared__ __nv_bfloat16 smem[];
    const int tid = threadIdx.x;
    const int wid = tid >> 5, lane = tid & 31;
    const int gid = lane >> 2, tig = lane & 3;
    const int wm = wid >> 2, wn = wid & 3;
    const int n0 = blockIdx.x * 128;
    const int row0 = blockIdx.y * 128;

    float acc[4][4][4];
#pragma unroll
    for (int mt = 0; mt < 4; mt++)
#pragma unroll
        for (int nt = 0; nt < 4; nt++)
#pragma unroll
            for (int j = 0; j < 4; j++) acc[mt][nt][j] = 0.0f;

    const int srow = tid >> 1;
    const int scol = (tid & 1) * 32;
    const __nv_bfloat16* gA = g_hs_hi + (size_t)(row0 + srow) * NN + scol;
    const __nv_bfloat16* gL = g_hs_lo + (size_t)(row0 + srow) * NN + scol;
    const __nv_bfloat16* gB = g_wt_hi + (size_t)(n0 + srow) * NN + scol;
    const __nv_bfloat16* gM = g_wt_lo + (size_t)(n0 + srow) * NN + scol;
    const int sbase = srow * TS + scol;

    auto load_chunk = [&](int c, int buf) {
        __nv_bfloat16* base = smem + buf * BUF_ELEMS;
        const int k0 = c * 64;
#pragma unroll
        for (int q = 0; q < 4; q++) {
            cp16(base + 0 * TILE_ELEMS + sbase + q * 8, gA + k0 + q * 8);
            cp16(base + 1 * TILE_ELEMS + sbase + q * 8, gL + k0 + q * 8);
            cp16(base + 2 * TILE_ELEMS + sbase + q * 8, gB + k0 + q * 8);
            cp16(base + 3 * TILE_ELEMS + sbase + q * 8, gM + k0 + q * 8);
        }
    };

    load_chunk(0, 0); cp_commit();
    load_chunk(1, 1); cp_commit();

    int buf = 0;
    for (int c = 0; c < 16; c++) {
        if (c < 14) cp_wait<1>(); else cp_wait<0>();
        __syncthreads();               // chunk c visible; buf (c+2)%3 free
        if (c + 2 < 16) {
            load_chunk(c + 2, (buf + 2) % 3);
            cp_commit();
        }
        gemm_chunk(smem + buf * BUF_ELEMS, acc, wm, wn, lane);
        buf = (buf + 1) % 3;
    }

#pragma unroll
    for (int nt = 0; nt < 4; nt++) {
        const int col = n0 + wn * 32 + nt * 8 + tig * 2;
        const float b0 = outB[col], b1 = outB[col + 1];
#pragma unroll
        for (int mt = 0; mt < 4; mt++) {
            const int r = row0 + wm * 64 + mt * 16 + gid;
            float2 o0, o1;
            o0.x = fmaxf(acc[mt][nt][0] + b0, 0.0f);
            o0.y = fmaxf(acc[mt][nt][1] + b1, 0.0f);
            o1.x = fmaxf(acc[mt][nt][2] + b0, 0.0f);
            o1.y = fmaxf(acc[mt][nt][3] + b1, 0.0f);
            *(float2*)(g_out + (size_t)r * NO + col) = o0;
            *(float2*)(g_out + (size_t)(r + 8) * NO + col) = o1;
        }
    }
}

// ---------------- time-softmax -> centers, 2-phase (8 chunks) --------------
__global__ void __launch_bounds__(512) centers_part_kernel(const float* __restrict__ r) {
    const int b = blockIdx.x;
    const int ch = blockIdx.y;
    const int n = threadIdx.x;
    float m = -1e30f, s = 0.0f, c0 = 0.0f, c1 = 0.0f;
    const float* ob = g_out + (size_t)b * NT * NO + (size_t)ch * 32 * NO;
    const float* rb = r + (size_t)b * NT * 2 + ch * 32 * 2;
    for (int t = 0; t < 32; t++) {
        float v = ob[(size_t)t * NO + n];
        float r0 = rb[t * 2 + 0], r1 = rb[t * 2 + 1];
        if (v > m) {
            float f = expf(m - v);
            s = s * f + 1.0f; c0 = c0 * f + r0; c1 = c1 * f + r1; m = v;
        } else {
            float p = expf(v - m);
            s += p; c0 += p * r0; c1 += p * r1;
        }
    }
    g_cpart[((size_t)ch * NB + b) * NO + n] = make_float4(m, s, c0, c1);
}

__global__ void __launch_bounds__(512) centers_comb_kernel() {
    const int b = blockIdx.x;
    const int n = threadIdx.x;
    float m = -1e30f;
#pragma unroll
    for (int ch = 0; ch < 8; ch++)
        m = fmaxf(m, g_cpart[((size_t)ch * NB + b) * NO + n].x);
    float s = 0.0f, c0 = 0.0f, c1 = 0.0f;
#pragma unroll
    for (int ch = 0; ch < 8; ch++) {
        float4 p = g_cpart[((size_t)ch * NB + b) * NO + n];
        float f = expf(p.x - m);
        s += p.y * f; c0 += p.z * f; c1 += p.w * f;
    }
    float inv = 1.0f / s;
    g_centers[((size_t)b * NO + n) * 2 + 0] = c0 * inv;
    g_centers[((size_t)b * NO + n) * 2 + 1] = c1 * inv;
}

// ---------------- cell-softmax -> expected position ------------------------
__global__ void __launch_bounds__(256) final_kernel(float* __restrict__ outp) {
    const int wrp = threadIdx.x >> 5;
    const int lane = threadIdx.x & 31;
    const int row = blockIdx.x * 8 + wrp;
    const int b = row >> 8;
    const float* o = g_out + (size_t)row * NO;

    float v[16];
    float vmax = -1e30f;
#pragma unroll
    for (int i = 0; i < 16; i++) {
        v[i] = o[lane + 32 * i];
        vmax = fmaxf(vmax, v[i]);
    }
#pragma unroll
    for (int off = 16; off; off >>= 1)
        vmax = fmaxf(vmax, __shfl_xor_sync(0xffffffffu, vmax, off));

    float s = 0.0f, a0 = 0.0f, a1 = 0.0f;
    const float* cen = g_centers + (size_t)b * NO * 2;
#pragma unroll
    for (int i = 0; i < 16; i++) {
        int n = lane + 32 * i;
        float p = expf(v[i] - vmax);
        s += p;
        float2 c = *(const float2*)(cen + n * 2);
        a0 += p * c.x; a1 += p * c.y;
    }
#pragma unroll
    for (int off = 16; off; off >>= 1) {
        s  += __shfl_xor_sync(0xffffffffu, s, off);
        a0 += __shfl_xor_sync(0xffffffffu, a0, off);
        a1 += __shfl_xor_sync(0xffffffffu, a1, off);
    }
    if (lane == 0) {
        float inv = 1.0f / s;
        outp[row * 2 + 0] = a0 * inv;
        outp[row * 2 + 1] = a1 * inv;
    }
}

extern "C" void kernel_launch(void* const* d_in, const int* in_sizes, int n_in,
                              void* d_out, int out_size) {
    const float* x    = (const float*)d_in[0];
    const float* r    = (const float*)d_in[1];
    const float* sW   = (const float*)d_in[2];
    const float* hW   = (const float*)d_in[3];
    const float* recW = (const float*)d_in[4];
    const float* recb = (const float*)d_in[5];
    const float* outW = (const float*)d_in[6];
    const float* outb = (const float*)d_in[7];
    const float* init = (const float*)d_in[8];
    float* outp = (float*)d_out;

    csc_phase1<<<NN / 16, 256>>>(recW);
    csc_phase2<<<NN / 256, 256>>>();
    {
        dim3 g(NN / 32, NO / 32);
        wsplit_kernel<<<g, 256>>>(outW);
    }
    wdsplit_kernel<<<(NN * NKP) / 256, 256>>>(sW, hW);
    feat_kernel<<<(NB * NT * NKP) / 256, 256>>>(x);
    {
        cudaFuncSetAttribute(drivegemm_mma_kernel,
                             cudaFuncAttributeMaxDynamicSharedMemorySize, GEMM_SMEM2);
        dim3 g(NN / 128, (NB * NT) / 128);
        drivegemm_mma_kernel<<<g, 256, GEMM_SMEM2>>>();
    }
    rnn_diag_kernel<<<(NB * NN) / 256, 256>>>(recb, init);
    rnn_general_kernel<<<NB, 1024>>>(recb, init);
    {
        cudaFuncSetAttribute(outgemm_mma_kernel,
                             cudaFuncAttributeMaxDynamicSharedMemorySize, GEMM_SMEM3);
        dim3 g(NO / 128, (NB * NT) / 128);
        outgemm_mma_kernel<<<g, 256, GEMM_SMEM3>>>(outb);
    }
    {
        dim3 g(NB, 8);
        centers_part_kernel<<<g, 512>>>(r);
    }
    centers_comb_kernel<<<NB, 512>>>();
    final_kernel<<<(NB * NT) / 8, 256>>>(outp);
}

// round 13
// speedup vs baseline: 4.2431x; 1.2622x over previous
#include <cuda_runtime.h>
#include <cuda_bf16.h>
#include <math.h>
#include <stdint.h>

#define NB 64
#define NT 256
#define NN 1024
#define NO 512
#define NK_SPEED 20
#define NK_HD 50
#define NK_TOT 70
#define NKP 80
#define CMAX 4

__device__ float          g_drive[(size_t)NB * NT * NN];
__device__ __nv_bfloat16  g_ft_hi[(size_t)NB * NT * NKP];
__device__ __nv_bfloat16  g_ft_lo[(size_t)NB * NT * NKP];
__device__ __nv_bfloat16  g_wd_hi[(size_t)NN * NKP];
__device__ __nv_bfloat16  g_wd_lo[(size_t)NN * NKP];
__device__ __nv_bfloat16  g_hs_hi[(size_t)NB * NT * NN];
__device__ __nv_bfloat16  g_hs_lo[(size_t)NB * NT * NN];
__device__ __nv_bfloat16  g_wt_hi[(size_t)NO * NN];
__device__ __nv_bfloat16  g_wt_lo[(size_t)NO * NN];
__device__ float          g_out[(size_t)NB * NT * NO];
__device__ float          g_centers[NB * NO * 2];
__device__ float4         g_cpart[8 * NB * NO];
__device__ int            g_nnz_cnt[NN];
__device__ int            g_nnz_idx[(size_t)NN * NN];
__device__ float          g_nnz_val[(size_t)NN * NN];
__device__ int            g_tmp_idx[(size_t)NN * NN];
__device__ float          g_tmp_val[(size_t)NN * NN];
__device__ int            g_scnt[NN * 16];
__device__ float          g_wdiag[NN];
__device__ int            g_diag_flag;

// ---------------- CSC phase 1: 16 k-segments per column, 64 CTAs -----------
__global__ void __launch_bounds__(256) csc_phase1(const float* __restrict__ recW) {
    const int tid = threadIdx.x;
    const int n = blockIdx.x * 16 + (tid & 15);
    const int kt = tid >> 4;
    int c = 0;
    const int kbase = kt * 64;
    for (int i = 0; i < 64; i++) {
        float w = recW[(size_t)(kbase + i) * NN + n];
        if (w != 0.0f) {
            g_tmp_idx[(size_t)n * NN + kbase + c] = kbase + i;
            g_tmp_val[(size_t)n * NN + kbase + c] = w;
            c++;
        }
    }
    g_scnt[n * 16 + kt] = c;
    if (blockIdx.x == 0 && tid == 0) g_diag_flag = 1;
}

// ---------------- CSC phase 2: concat segments, detect diagonality ---------
__global__ void __launch_bounds__(256) csc_phase2() {
    const int n = blockIdx.x * 256 + threadIdx.x;
    int off = 0;
    bool diag = true;
    float wsum = 0.0f;
    for (int s = 0; s < 16; s++) {
        const int c = g_scnt[n * 16 + s];
        for (int i = 0; i < c; i++) {
            int k = g_tmp_idx[(size_t)n * NN + s * 64 + i];
            float w = g_tmp_val[(size_t)n * NN + s * 64 + i];
            g_nnz_idx[(size_t)n * NN + off] = k;
            g_nnz_val[(size_t)n * NN + off] = w;
            off++;
            if (k != n) diag = false; else wsum += w;
        }
    }
    g_nnz_cnt[n] = off;
    g_wdiag[n] = wsum;
    if (!diag) g_diag_flag = 0;
}

// ---------------- transpose + bf16-split out_W -> [NO][NN] -----------------
__global__ void __launch_bounds__(256) wsplit_kernel(const float* __restrict__ outW) {
    __shared__ float tile[32][33];
    const int k0 = blockIdx.x * 32, n0 = blockIdx.y * 32;
    const int tx = threadIdx.x & 31, ty = threadIdx.x >> 5;
#pragma unroll
    for (int i = 0; i < 4; i++)
        tile[ty + 8 * i][tx] = outW[(size_t)(k0 + ty + 8 * i) * NO + n0 + tx];
    __syncthreads();
#pragma unroll
    for (int i = 0; i < 4; i++) {
        int row = ty + 8 * i;
        float v = tile[tx][row];
        __nv_bfloat16 hi = __float2bfloat16(v);
        __nv_bfloat16 lo = __float2bfloat16(v - __bfloat162float(hi));
        size_t o = (size_t)(n0 + row) * NN + k0 + tx;
        g_wt_hi[o] = hi;
        g_wt_lo[o] = lo;
    }
}

// ---------------- bf16-split [speed_W; hd_W]^T -> [NN][NKP] ----------------
__global__ void __launch_bounds__(256) wdsplit_kernel(const float* __restrict__ sW,
                                                      const float* __restrict__ hW) {
    const int idx = blockIdx.x * 256 + threadIdx.x;
    const int n = idx / NKP;
    const int k = idx - n * NKP;
    float v = 0.0f;
    if (k < NK_SPEED)      v = sW[(size_t)k * NN + n];
    else if (k < NK_TOT)   v = hW[(size_t)(k - NK_SPEED) * NN + n];
    __nv_bfloat16 hi = __float2bfloat16(v);
    __nv_bfloat16 lo = __float2bfloat16(v - __bfloat162float(hi));
    g_wd_hi[idx] = hi;
    g_wd_lo[idx] = lo;
}

// ---------------- features -> bf16 hi/lo, K padded to 80 -------------------
__global__ void __launch_bounds__(256) feat_kernel(const float* __restrict__ x) {
    const int idx = blockIdx.x * 256 + threadIdx.x;
    const int row = idx / NKP;
    const int k = idx - row * NKP;
    const float TWO_PI = 6.2831853071795865f;
    const float LOGNORM = 6.3050317f;  // log(2*pi*I0(2*pi))
    float f = 0.0f;
    if (k < NK_SPEED) {
        float v = x[(size_t)row * 2 + 0];
        float dv = v - 0.5f * (float)k / 19.0f;
        f = expf(-800.0f * dv * dv);
    } else if (k < NK_TOT) {
        float th = x[(size_t)row * 2 + 1];
        float c = TWO_PI * (float)(k - NK_SPEED) / 49.0f;
        f = expf(TWO_PI * cosf(th - c) - LOGNORM);
    }
    __nv_bfloat16 hi = __float2bfloat16(f);
    __nv_bfloat16 lo = __float2bfloat16(f - __bfloat162float(hi));
    g_ft_hi[idx] = hi;
    g_ft_lo[idx] = lo;
}

// ---------------- common GEMM machinery ------------------------------------
#define TS 72
#define TILE_ELEMS (128 * TS)
#define BUF_ELEMS (4 * TILE_ELEMS)
#define GEMM_SMEM3 (3 * BUF_ELEMS * 2)

__device__ __forceinline__ void cp16(void* smem_dst, const void* gsrc) {
    uint32_t s = (uint32_t)__cvta_generic_to_shared(smem_dst);
    asm volatile("cp.async.cg.shared.global [%0], [%1], 16;" :: "r"(s), "l"(gsrc) : "memory");
}
__device__ __forceinline__ void cp_commit() {
    asm volatile("cp.async.commit_group;" ::: "memory");
}
template <int N>
__device__ __forceinline__ void cp_wait() {
    asm volatile("cp.async.wait_group %0;" :: "n"(N) : "memory");
}
__device__ __forceinline__ void mma_bf16(float* d, const uint32_t* a, const uint32_t* b) {
    asm volatile(
        "mma.sync.aligned.m16n8k16.row.col.f32.bf16.bf16.f32 "
        "{%0,%1,%2,%3}, {%4,%5,%6,%7}, {%8,%9}, {%0,%1,%2,%3};"
        : "+f"(d[0]), "+f"(d[1]), "+f"(d[2]), "+f"(d[3])
        : "r"(a[0]), "r"(a[1]), "r"(a[2]), "r"(a[3]), "r"(b[0]), "r"(b[1]));
}
__device__ __forceinline__ void ldsm4(uint32_t* r, const __nv_bfloat16* p) {
    uint32_t a = (uint32_t)__cvta_generic_to_shared(p);
    asm volatile("ldmatrix.sync.aligned.m8n8.x4.shared.b16 {%0,%1,%2,%3}, [%4];"
                 : "=r"(r[0]), "=r"(r[1]), "=r"(r[2]), "=r"(r[3]) : "r"(a));
}

// one 64-k chunk of MMAs from staged tiles (128x128 tile, 2x4 warps)
__device__ __forceinline__ void gemm_chunk(const __nv_bfloat16* Ah, float acc[4][4][4],
                                           int wm, int wn, int lane) {
    const __nv_bfloat16* Al = Ah + TILE_ELEMS;
    const __nv_bfloat16* Bh = Ah + 2 * TILE_ELEMS;
    const __nv_bfloat16* Bl = Ah + 3 * TILE_ELEMS;
    const int quad = lane >> 3, rowin = lane & 7;
    const int a_m = wm * 64 + (quad & 1) * 8 + rowin;
    const int a_k = (quad >> 1) * 8;
    const int b_n = wn * 32 + (quad >> 1) * 8 + rowin;
    const int b_k = (quad & 1) * 8;
#pragma unroll
    for (int ks = 0; ks < 4; ks++) {
        const int kc0 = ks * 16;
        uint32_t ahi[4][4], alo[4][4], bhi[4][2], blo[4][2];
#pragma unroll
        for (int mt = 0; mt < 4; mt++) {
            const int off = (a_m + mt * 16) * TS + kc0 + a_k;
            ldsm4(ahi[mt], Ah + off);
            ldsm4(alo[mt], Al + off);
        }
#pragma unroll
        for (int j = 0; j < 2; j++) {
            const int off = (b_n + j * 16) * TS + kc0 + b_k;
            uint32_t th[4], tl[4];
            ldsm4(th, Bh + off);
            ldsm4(tl, Bl + off);
            bhi[2 * j][0] = th[0]; bhi[2 * j][1] = th[1];
            bhi[2 * j + 1][0] = th[2]; bhi[2 * j + 1][1] = th[3];
            blo[2 * j][0] = tl[0]; blo[2 * j][1] = tl[1];
            blo[2 * j + 1][0] = tl[2]; blo[2 * j + 1][1] = tl[3];
        }
#pragma unroll
        for (int mt = 0; mt < 4; mt++)
#pragma unroll
            for (int nt = 0; nt < 4; nt++) {
                mma_bf16(acc[mt][nt], ahi[mt], bhi[nt]);
                mma_bf16(acc[mt][nt], ahi[mt], blo[nt]);
                mma_bf16(acc[mt][nt], alo[mt], bhi[nt]);
            }
    }
}

// ---------------- fused drive-GEMM + RNN scan ------------------------------
// CTA = (n-block of 128, batch b). Wd staged once; 8 t-chunks of 32:
// mma -> D tile in SMEM -> diagonal recurrence scan (or g_drive fallback).
#define TSW 88
#define FCHUNK (2 * 32 * TSW)                 // hi+lo feats chunk (elems)
#define FUSED_SMEM_ELEMS (2 * 128 * TSW + 2 * FCHUNK)
#define FUSED_SMEM (FUSED_SMEM_ELEMS * 2 + 32 * 128 * 4)

__global__ void __launch_bounds__(256, 1) fused_drive_rnn_kernel(const float* __restrict__ rec_b,
                                                                 const float* __restrict__ init_state) {
    extern __shared__ __nv_bfloat16 sm[];
    __nv_bfloat16* WdH = sm;
    __nv_bfloat16* WdL = sm + 128 * TSW;
    __nv_bfloat16* Fbase = sm + 2 * 128 * TSW;
    float* D = (float*)(sm + FUSED_SMEM_ELEMS);

    const int tid = threadIdx.x;
    const int wid = tid >> 5, lane = tid & 31;
    const int gid = lane >> 2, tig = lane & 3;
    const int wm = wid >> 2, wn = wid & 3;        // 2 x 4 warps, m=32 tile
    const int n0 = blockIdx.x * 128;
    const int b = blockIdx.y;
    const int diag = *(volatile int*)&g_diag_flag;

    // stage Wd hi/lo (once): 128 rows x 80 elems, row stride TSW
    {
        const int row = tid >> 1, half = tid & 1;
        const __nv_bfloat16* gh = g_wd_hi + (size_t)(n0 + row) * NKP + half * 40;
        const __nv_bfloat16* gl = g_wd_lo + (size_t)(n0 + row) * NKP + half * 40;
        __nv_bfloat16* dh = WdH + row * TSW + half * 40;
        __nv_bfloat16* dl = WdL + row * TSW + half * 40;
#pragma unroll
        for (int q = 0; q < 5; q++) {
            cp16(dh + q * 8, gh + q * 8);
            cp16(dl + q * 8, gl + q * 8);
        }
    }

    auto loadF = [&](int ch, int buf) {
        __nv_bfloat16* FH = Fbase + buf * FCHUNK;
        __nv_bfloat16* FL = FH + 32 * TSW;
        const int t0 = ch * 32;
#pragma unroll
        for (int i = 0; i < 2; i++) {
            int e = tid + i * 256;
            if (e < 320) {
                int row = e / 10, q = e - row * 10;
                size_t gro = ((size_t)b * NT + t0 + row) * NKP + q * 8;
                cp16(FH + row * TSW + q * 8, g_ft_hi + gro);
                cp16(FL + row * TSW + q * 8, g_ft_lo + gro);
            }
        }
    };
    loadF(0, 0);
    cp_commit();

    // persistent scan state (one n per scan thread)
    float h = 0.0f, w = 0.0f, rb = 0.0f;
    if (tid < 128) {
        const int n = n0 + tid;
        w = g_wdiag[n];
        rb = rec_b[n];
        h = init_state[n];
    }

    const int quad = lane >> 3, rowin = lane & 7;
    const int a_m = wm * 16 + (quad & 1) * 8 + rowin;
    const int a_k = (quad >> 1) * 8;
    const int b_n = wn * 32 + (quad >> 1) * 8 + rowin;
    const int b_k = (quad & 1) * 8;

    for (int ch = 0; ch < 8; ch++) {
        if (ch < 7) {
            loadF(ch + 1, (ch + 1) & 1);
            cp_commit();
            cp_wait<1>();
        } else {
            cp_wait<0>();
        }
        __syncthreads();                       // F[ch]+Wd visible; D free

        const __nv_bfloat16* FH = Fbase + (ch & 1) * FCHUNK;
        const __nv_bfloat16* FL = FH + 32 * TSW;

        float acc[4][4];
#pragma unroll
        for (int nt = 0; nt < 4; nt++)
#pragma unroll
            for (int j = 0; j < 4; j++) acc[nt][j] = 0.0f;

#pragma unroll
        for (int ks = 0; ks < 5; ks++) {
            const int kc0 = ks * 16;
            uint32_t ah[4], al[4], bh[4][2], bl[4][2];
            ldsm4(ah, FH + a_m * TSW + kc0 + a_k);
            ldsm4(al, FL + a_m * TSW + kc0 + a_k);
#pragma unroll
            for (int j = 0; j < 2; j++) {
                uint32_t th[4], tl[4];
                ldsm4(th, WdH + (b_n + j * 16) * TSW + kc0 + b_k);
                ldsm4(tl, WdL + (b_n + j * 16) * TSW + kc0 + b_k);
                bh[2 * j][0] = th[0]; bh[2 * j][1] = th[1];
                bh[2 * j + 1][0] = th[2]; bh[2 * j + 1][1] = th[3];
                bl[2 * j][0] = tl[0]; bl[2 * j][1] = tl[1];
                bl[2 * j + 1][0] = tl[2]; bl[2 * j + 1][1] = tl[3];
            }
#pragma unroll
            for (int nt = 0; nt < 4; nt++) {
                mma_bf16(acc[nt], ah, bh[nt]);
                mma_bf16(acc[nt], ah, bl[nt]);
                mma_bf16(acc[nt], al, bh[nt]);
            }
        }

        const int t0 = ch * 32;
        if (diag) {
#pragma unroll
            for (int nt = 0; nt < 4; nt++) {
                const int col = wn * 32 + nt * 8 + tig * 2;
                const int r = wm * 16 + gid;
                *(float2*)&D[r * 128 + col] = make_float2(acc[nt][0], acc[nt][1]);
                *(float2*)&D[(r + 8) * 128 + col] = make_float2(acc[nt][2], acc[nt][3]);
            }
            __syncthreads();
            if (tid < 128) {
                for (int tl2 = 0; tl2 < 32; tl2++) {
                    float d = D[tl2 * 128 + tid];
                    h = fmaxf(fmaf(h, w, rb + d), 0.0f);
                    __nv_bfloat16 hb = __float2bfloat16(h);
                    size_t o = ((size_t)b * NT + t0 + tl2) * NN + n0 + tid;
                    g_hs_hi[o] = hb;
                    g_hs_lo[o] = __float2bfloat16(h - __bfloat162float(hb));
                }
            }
        } else {
#pragma unroll
            for (int nt = 0; nt < 4; nt++) {
                const int col = n0 + wn * 32 + nt * 8 + tig * 2;
                const int r = wm * 16 + gid;
                *(float2*)(g_drive + ((size_t)b * NT + t0 + r) * NN + col)
                    = make_float2(acc[nt][0], acc[nt][1]);
                *(float2*)(g_drive + ((size_t)b * NT + t0 + r + 8) * NN + col)
                    = make_float2(acc[nt][2], acc[nt][3]);
            }
            __syncthreads();
        }
    }
}

// ---------------- RNN general fallback: h in SMEM, 1 bar/step --------------
__global__ void __launch_bounds__(1024, 1) rnn_general_kernel(const float* __restrict__ rec_b,
                                                              const float* __restrict__ init_state) {
    if (*(volatile int*)&g_diag_flag != 0) return;
    __shared__ float hbuf[2][NN];
    const int b = blockIdx.x;
    const int n = threadIdx.x;

    const float rb = rec_b[n];
    const int cnt = g_nnz_cnt[n];
    const int cr = cnt < CMAX ? cnt : CMAX;
    int kk[CMAX]; float ww[CMAX];
    for (int j = 0; j < cr; j++) {
        kk[j] = g_nnz_idx[(size_t)n * NN + j];
        ww[j] = g_nnz_val[(size_t)n * NN + j];
    }
    hbuf[0][n] = init_state[n];
    __syncthreads();

    float d = g_drive[(size_t)b * NT * NN + n];

    for (int t = 0; t < NT; t++) {
        const float* cur = hbuf[t & 1];
        float* nxt = hbuf[(t + 1) & 1];
        float dn = 0.0f;
        if (t + 1 < NT)
            dn = g_drive[((size_t)b * NT + t + 1) * NN + n];

        float acc = rb + d;
        for (int j = 0; j < cr; j++)
            acc += cur[kk[j]] * ww[j];
        for (int j = CMAX; j < cnt; j++)
            acc += cur[g_nnz_idx[(size_t)n * NN + j]] * g_nnz_val[(size_t)n * NN + j];
        float hv = fmaxf(acc, 0.0f);
        nxt[n] = hv;
        const size_t row = ((size_t)b * NT + t) * NN;
        __nv_bfloat16 hb = __float2bfloat16(hv);
        g_hs_hi[row + n] = hb;
        g_hs_lo[row + n] = __float2bfloat16(hv - __bfloat162float(hb));
        __syncthreads();
        d = dn;
    }
}

// ---------------- out-GEMM: hs @ out_W^T, K=1024, 3-stage pipeline ---------
__global__ void __launch_bounds__(256, 1) outgemm_mma_kernel(const float* __restrict__ outB) {
    extern __shared__ __nv_bfloat16 smem[];
    const int tid = threadIdx.x;
    const int wid = tid >> 5, lane = tid & 31;
    const int gid = lane >> 2, tig = lane & 3;
    const int wm = wid >> 2, wn = wid & 3;
    const int n0 = blockIdx.x * 128;
    const int row0 = blockIdx.y * 128;

    float acc[4][4][4];
#pragma unroll
    for (int mt = 0; mt < 4; mt++)
#pragma unroll
        for (int nt = 0; nt < 4; nt++)
#pragma unroll
            for (int j = 0; j < 4; j++) acc[mt][nt][j] = 0.0f;

    const int srow = tid >> 1;
    const int scol = (tid & 1) * 32;
    const __nv_bfloat16* gA = g_hs_hi + (size_t)(row0 + srow) * NN + scol;
    const __nv_bfloat16* gL = g_hs_lo + (size_t)(row0 + srow) * NN + scol;
    const __nv_bfloat16* gB = g_wt_hi + (size_t)(n0 + srow) * NN + scol;
    const __nv_bfloat16* gM = g_wt_lo + (size_t)(n0 + srow) * NN + scol;
    const int sbase = srow * TS + scol;

    auto load_chunk = [&](int c, int buf) {
        __nv_bfloat16* base = smem + buf * BUF_ELEMS;
        const int k0 = c * 64;
#pragma unroll
        for (int q = 0; q < 4; q++) {
            cp16(base + 0 * TILE_ELEMS + sbase + q * 8, gA + k0 + q * 8);
            cp16(base + 1 * TILE_ELEMS + sbase + q * 8, gL + k0 + q * 8);
            cp16(base + 2 * TILE_ELEMS + sbase + q * 8, gB + k0 + q * 8);
            cp16(base + 3 * TILE_ELEMS + sbase + q * 8, gM + k0 + q * 8);
        }
    };

    load_chunk(0, 0); cp_commit();
    load_chunk(1, 1); cp_commit();

    int buf = 0;
    for (int c = 0; c < 16; c++) {
        if (c < 14) cp_wait<1>(); else cp_wait<0>();
        __syncthreads();
        if (c + 2 < 16) {
            load_chunk(c + 2, (buf + 2) % 3);
            cp_commit();
        }
        gemm_chunk(smem + buf * BUF_ELEMS, acc, wm, wn, lane);
        buf = (buf + 1) % 3;
    }

#pragma unroll
    for (int nt = 0; nt < 4; nt++) {
        const int col = n0 + wn * 32 + nt * 8 + tig * 2;
        const float b0 = outB[col], b1 = outB[col + 1];
#pragma unroll
        for (int mt = 0; mt < 4; mt++) {
            const int r = row0 + wm * 64 + mt * 16 + gid;
            float2 o0, o1;
            o0.x = fmaxf(acc[mt][nt][0] + b0, 0.0f);
            o0.y = fmaxf(acc[mt][nt][1] + b1, 0.0f);
            o1.x = fmaxf(acc[mt][nt][2] + b0, 0.0f);
            o1.y = fmaxf(acc[mt][nt][3] + b1, 0.0f);
            *(float2*)(g_out + (size_t)r * NO + col) = o0;
            *(float2*)(g_out + (size_t)(r + 8) * NO + col) = o1;
        }
    }
}

// ---------------- time-softmax -> centers, 2-phase (8 chunks) --------------
__global__ void __launch_bounds__(512) centers_part_kernel(const float* __restrict__ r) {
    const int b = blockIdx.x;
    const int ch = blockIdx.y;
    const int n = threadIdx.x;
    float m = -1e30f, s = 0.0f, c0 = 0.0f, c1 = 0.0f;
    const float* ob = g_out + (size_t)b * NT * NO + (size_t)ch * 32 * NO;
    const float* rb = r + (size_t)b * NT * 2 + ch * 32 * 2;
    for (int t = 0; t < 32; t++) {
        float v = ob[(size_t)t * NO + n];
        float r0 = rb[t * 2 + 0], r1 = rb[t * 2 + 1];
        if (v > m) {
            float f = expf(m - v);
            s = s * f + 1.0f; c0 = c0 * f + r0; c1 = c1 * f + r1; m = v;
        } else {
            float p = expf(v - m);
            s += p; c0 += p * r0; c1 += p * r1;
        }
    }
    g_cpart[((size_t)ch * NB + b) * NO + n] = make_float4(m, s, c0, c1);
}

__global__ void __launch_bounds__(512) centers_comb_kernel() {
    const int b = blockIdx.x;
    const int n = threadIdx.x;
    float m = -1e30f;
#pragma unroll
    for (int ch = 0; ch < 8; ch++)
        m = fmaxf(m, g_cpart[((size_t)ch * NB + b) * NO + n].x);
    float s = 0.0f, c0 = 0.0f, c1 = 0.0f;
#pragma unroll
    for (int ch = 0; ch < 8; ch++) {
        float4 p = g_cpart[((size_t)ch * NB + b) * NO + n];
        float f = expf(p.x - m);
        s += p.y * f; c0 += p.z * f; c1 += p.w * f;
    }
    float inv = 1.0f / s;
    g_centers[((size_t)b * NO + n) * 2 + 0] = c0 * inv;
    g_centers[((size_t)b * NO + n) * 2 + 1] = c1 * inv;
}

// ---------------- cell-softmax -> expected position ------------------------
__global__ void __launch_bounds__(256) final_kernel(float* __restrict__ outp) {
    const int wrp = threadIdx.x >> 5;
    const int lane = threadIdx.x & 31;
    const int row = blockIdx.x * 8 + wrp;
    const int b = row >> 8;
    const float* o = g_out + (size_t)row * NO;

    float v[16];
    float vmax = -1e30f;
#pragma unroll
    for (int i = 0; i < 16; i++) {
        v[i] = o[lane + 32 * i];
        vmax = fmaxf(vmax, v[i]);
    }
#pragma unroll
    for (int off = 16; off; off >>= 1)
        vmax = fmaxf(vmax, __shfl_xor_sync(0xffffffffu, vmax, off));

    float s = 0.0f, a0 = 0.0f, a1 = 0.0f;
    const float* cen = g_centers + (size_t)b * NO * 2;
#pragma unroll
    for (int i = 0; i < 16; i++) {
        int n = lane + 32 * i;
        float p = expf(v[i] - vmax);
        s += p;
        float2 c = *(const float2*)(cen + n * 2);
        a0 += p * c.x; a1 += p * c.y;
    }
#pragma unroll
    for (int off = 16; off; off >>= 1) {
        s  += __shfl_xor_sync(0xffffffffu, s, off);
        a0 += __shfl_xor_sync(0xffffffffu, a0, off);
        a1 += __shfl_xor_sync(0xffffffffu, a1, off);
    }
    if (lane == 0) {
        float inv = 1.0f / s;
        outp[row * 2 + 0] = a0 * inv;
        outp[row * 2 + 1] = a1 * inv;
    }
}

extern "C" void kernel_launch(void* const* d_in, const int* in_sizes, int n_in,
                              void* d_out, int out_size) {
    const float* x    = (const float*)d_in[0];
    const float* r    = (const float*)d_in[1];
    const float* sW   = (const float*)d_in[2];
    const float* hW   = (const float*)d_in[3];
    const float* recW = (const float*)d_in[4];
    const float* recb = (const float*)d_in[5];
    const float* outW = (const float*)d_in[6];
    const float* outb = (const float*)d_in[7];
    const float* init = (const float*)d_in[8];
    float* outp = (float*)d_out;

    csc_phase1<<<NN / 16, 256>>>(recW);
    csc_phase2<<<NN / 256, 256>>>();
    {
        dim3 g(NN / 32, NO / 32);
        wsplit_kernel<<<g, 256>>>(outW);
    }
    wdsplit_kernel<<<(NN * NKP) / 256, 256>>>(sW, hW);
    feat_kernel<<<(NB * NT * NKP) / 256, 256>>>(x);
    {
        cudaFuncSetAttribute(fused_drive_rnn_kernel,
                             cudaFuncAttributeMaxDynamicSharedMemorySize, FUSED_SMEM);
        dim3 g(NN / 128, NB);
        fused_drive_rnn_kernel<<<g, 256, FUSED_SMEM>>>(recb, init);
    }
    rnn_general_kernel<<<NB, 1024>>>(recb, init);
    {
        cudaFuncSetAttribute(outgemm_mma_kernel,
                             cudaFuncAttributeMaxDynamicSharedMemorySize, GEMM_SMEM3);
        dim3 g(NO / 128, (NB * NT) / 128);
        outgemm_mma_kernel<<<g, 256, GEMM_SMEM3>>>(outb);
    }
    {
        dim3 g(NB, 8);
        centers_part_kernel<<<g, 512>>>(r);
    }
    centers_comb_kernel<<<NB, 512>>>();
    final_kernel<<<(NB * NT) / 8, 256>>>(outp);
}

// round 14
// speedup vs baseline: 4.4323x; 1.0446x over previous
#include <cuda_runtime.h>
#include <cuda_bf16.h>
#include <math.h>
#include <stdint.h>

#define NB 64
#define NT 256
#define NN 1024
#define NO 512
#define NK_SPEED 20
#define NK_HD 50
#define NK_TOT 70
#define NKP 80
#define CMAX 4

__device__ float          g_drive[(size_t)NB * NT * NN];
__device__ __nv_bfloat16  g_ft_hi[(size_t)NB * NT * NKP];
__device__ __nv_bfloat16  g_ft_lo[(size_t)NB * NT * NKP];
__device__ __nv_bfloat16  g_wd_hi[(size_t)NN * NKP];
__device__ __nv_bfloat16  g_wd_lo[(size_t)NN * NKP];
__device__ __nv_bfloat16  g_hs_hi[(size_t)NB * NT * NN];
__device__ __nv_bfloat16  g_hs_lo[(size_t)NB * NT * NN];
__device__ __nv_bfloat16  g_wt_hi[(size_t)NO * NN];
__device__ __nv_bfloat16  g_wt_lo[(size_t)NO * NN];
__device__ float          g_out[(size_t)NB * NT * NO];
__device__ float          g_centers[NB * NO * 2];
__device__ float4         g_cpart[8 * NB * NO];
__device__ int            g_nnz_cnt[NN];
__device__ int            g_nnz_idx[(size_t)NN * NN];
__device__ float          g_nnz_val[(size_t)NN * NN];
__device__ int            g_tmp_idx[(size_t)NN * NN];
__device__ float          g_tmp_val[(size_t)NN * NN];
__device__ int            g_scnt[NN * 16];
__device__ float          g_wdiag[NN];
__device__ int            g_diag_flag;

// ---------------- CSC phase 1: 16 k-segments per column, 64 CTAs -----------
__global__ void __launch_bounds__(256) csc_phase1(const float* __restrict__ recW) {
    const int tid = threadIdx.x;
    const int n = blockIdx.x * 16 + (tid & 15);
    const int kt = tid >> 4;
    int c = 0;
    const int kbase = kt * 64;
    for (int i = 0; i < 64; i++) {
        float w = recW[(size_t)(kbase + i) * NN + n];
        if (w != 0.0f) {
            g_tmp_idx[(size_t)n * NN + kbase + c] = kbase + i;
            g_tmp_val[(size_t)n * NN + kbase + c] = w;
            c++;
        }
    }
    g_scnt[n * 16 + kt] = c;
    if (blockIdx.x == 0 && tid == 0) g_diag_flag = 1;
}

// ---------------- CSC phase 2: concat segments, detect diagonality ---------
__global__ void __launch_bounds__(256) csc_phase2() {
    const int n = blockIdx.x * 256 + threadIdx.x;
    int off = 0;
    bool diag = true;
    float wsum = 0.0f;
    for (int s = 0; s < 16; s++) {
        const int c = g_scnt[n * 16 + s];
        for (int i = 0; i < c; i++) {
            int k = g_tmp_idx[(size_t)n * NN + s * 64 + i];
            float w = g_tmp_val[(size_t)n * NN + s * 64 + i];
            g_nnz_idx[(size_t)n * NN + off] = k;
            g_nnz_val[(size_t)n * NN + off] = w;
            off++;
            if (k != n) diag = false; else wsum += w;
        }
    }
    g_nnz_cnt[n] = off;
    g_wdiag[n] = wsum;
    if (!diag) g_diag_flag = 0;
}

// ---------------- transpose + bf16-split out_W -> [NO][NN] -----------------
__global__ void __launch_bounds__(256) wsplit_kernel(const float* __restrict__ outW) {
    __shared__ float tile[32][33];
    const int k0 = blockIdx.x * 32, n0 = blockIdx.y * 32;
    const int tx = threadIdx.x & 31, ty = threadIdx.x >> 5;
#pragma unroll
    for (int i = 0; i < 4; i++)
        tile[ty + 8 * i][tx] = outW[(size_t)(k0 + ty + 8 * i) * NO + n0 + tx];
    __syncthreads();
#pragma unroll
    for (int i = 0; i < 4; i++) {
        int row = ty + 8 * i;
        float v = tile[tx][row];
        __nv_bfloat16 hi = __float2bfloat16(v);
        __nv_bfloat16 lo = __float2bfloat16(v - __bfloat162float(hi));
        size_t o = (size_t)(n0 + row) * NN + k0 + tx;
        g_wt_hi[o] = hi;
        g_wt_lo[o] = lo;
    }
}

// ---------------- bf16-split [speed_W; hd_W]^T -> [NN][NKP] ----------------
__global__ void __launch_bounds__(256) wdsplit_kernel(const float* __restrict__ sW,
                                                      const float* __restrict__ hW) {
    const int idx = blockIdx.x * 256 + threadIdx.x;
    const int n = idx / NKP;
    const int k = idx - n * NKP;
    float v = 0.0f;
    if (k < NK_SPEED)      v = sW[(size_t)k * NN + n];
    else if (k < NK_TOT)   v = hW[(size_t)(k - NK_SPEED) * NN + n];
    __nv_bfloat16 hi = __float2bfloat16(v);
    __nv_bfloat16 lo = __float2bfloat16(v - __bfloat162float(hi));
    g_wd_hi[idx] = hi;
    g_wd_lo[idx] = lo;
}

// ---------------- features -> bf16 hi/lo, K padded to 80 -------------------
__global__ void __launch_bounds__(256) feat_kernel(const float* __restrict__ x) {
    const int idx = blockIdx.x * 256 + threadIdx.x;
    const int row = idx / NKP;
    const int k = idx - row * NKP;
    const float TWO_PI = 6.2831853071795865f;
    const float LOGNORM = 6.3050317f;  // log(2*pi*I0(2*pi))
    float f = 0.0f;
    if (k < NK_SPEED) {
        float v = x[(size_t)row * 2 + 0];
        float dv = v - 0.5f * (float)k / 19.0f;
        f = expf(-800.0f * dv * dv);
    } else if (k < NK_TOT) {
        float th = x[(size_t)row * 2 + 1];
        float c = TWO_PI * (float)(k - NK_SPEED) / 49.0f;
        f = expf(TWO_PI * cosf(th - c) - LOGNORM);
    }
    __nv_bfloat16 hi = __float2bfloat16(f);
    __nv_bfloat16 lo = __float2bfloat16(f - __bfloat162float(hi));
    g_ft_hi[idx] = hi;
    g_ft_lo[idx] = lo;
}

// ---------------- common machinery -----------------------------------------
#define TS 72

__device__ __forceinline__ void cp16(void* smem_dst, const void* gsrc) {
    uint32_t s = (uint32_t)__cvta_generic_to_shared(smem_dst);
    asm volatile("cp.async.cg.shared.global [%0], [%1], 16;" :: "r"(s), "l"(gsrc) : "memory");
}
__device__ __forceinline__ void cp_commit() {
    asm volatile("cp.async.commit_group;" ::: "memory");
}
template <int N>
__device__ __forceinline__ void cp_wait() {
    asm volatile("cp.async.wait_group %0;" :: "n"(N) : "memory");
}
__device__ __forceinline__ void mma_bf16(float* d, const uint32_t* a, const uint32_t* b) {
    asm volatile(
        "mma.sync.aligned.m16n8k16.row.col.f32.bf16.bf16.f32 "
        "{%0,%1,%2,%3}, {%4,%5,%6,%7}, {%8,%9}, {%0,%1,%2,%3};"
        : "+f"(d[0]), "+f"(d[1]), "+f"(d[2]), "+f"(d[3])
        : "r"(a[0]), "r"(a[1]), "r"(a[2]), "r"(a[3]), "r"(b[0]), "r"(b[1]));
}
__device__ __forceinline__ void ldsm4(uint32_t* r, const __nv_bfloat16* p) {
    uint32_t a = (uint32_t)__cvta_generic_to_shared(p);
    asm volatile("ldmatrix.sync.aligned.m8n8.x4.shared.b16 {%0,%1,%2,%3}, [%4];"
                 : "=r"(r[0]), "=r"(r[1]), "=r"(r[2]), "=r"(r[3]) : "r"(a));
}

// ---------------- fused drive-GEMM + RNN scan ------------------------------
#define TSW 88
#define FCHUNK (2 * 32 * TSW)
#define FUSED_SMEM_ELEMS (2 * 128 * TSW + 2 * FCHUNK)
#define FUSED_SMEM (FUSED_SMEM_ELEMS * 2 + 32 * 128 * 4)

__global__ void __launch_bounds__(256, 1) fused_drive_rnn_kernel(const float* __restrict__ rec_b,
                                                                 const float* __restrict__ init_state) {
    extern __shared__ __nv_bfloat16 sm[];
    __nv_bfloat16* WdH = sm;
    __nv_bfloat16* WdL = sm + 128 * TSW;
    __nv_bfloat16* Fbase = sm + 2 * 128 * TSW;
    float* D = (float*)(sm + FUSED_SMEM_ELEMS);

    const int tid = threadIdx.x;
    const int wid = tid >> 5, lane = tid & 31;
    const int gid = lane >> 2, tig = lane & 3;
    const int wm = wid >> 2, wn = wid & 3;
    const int n0 = blockIdx.x * 128;
    const int b = blockIdx.y;
    const int diag = *(volatile int*)&g_diag_flag;

    {
        const int row = tid >> 1, half = tid & 1;
        const __nv_bfloat16* gh = g_wd_hi + (size_t)(n0 + row) * NKP + half * 40;
        const __nv_bfloat16* gl = g_wd_lo + (size_t)(n0 + row) * NKP + half * 40;
        __nv_bfloat16* dh = WdH + row * TSW + half * 40;
        __nv_bfloat16* dl = WdL + row * TSW + half * 40;
#pragma unroll
        for (int q = 0; q < 5; q++) {
            cp16(dh + q * 8, gh + q * 8);
            cp16(dl + q * 8, gl + q * 8);
        }
    }

    auto loadF = [&](int ch, int buf) {
        __nv_bfloat16* FH = Fbase + buf * FCHUNK;
        __nv_bfloat16* FL = FH + 32 * TSW;
        const int t0 = ch * 32;
#pragma unroll
        for (int i = 0; i < 2; i++) {
            int e = tid + i * 256;
            if (e < 320) {
                int row = e / 10, q = e - row * 10;
                size_t gro = ((size_t)b * NT + t0 + row) * NKP + q * 8;
                cp16(FH + row * TSW + q * 8, g_ft_hi + gro);
                cp16(FL + row * TSW + q * 8, g_ft_lo + gro);
            }
        }
    };
    loadF(0, 0);
    cp_commit();

    float h = 0.0f, w = 0.0f, rb = 0.0f;
    if (tid < 128) {
        const int n = n0 + tid;
        w = g_wdiag[n];
        rb = rec_b[n];
        h = init_state[n];
    }

    const int quad = lane >> 3, rowin = lane & 7;
    const int a_m = wm * 16 + (quad & 1) * 8 + rowin;
    const int a_k = (quad >> 1) * 8;
    const int b_n = wn * 32 + (quad >> 1) * 8 + rowin;
    const int b_k = (quad & 1) * 8;

    for (int ch = 0; ch < 8; ch++) {
        if (ch < 7) {
            loadF(ch + 1, (ch + 1) & 1);
            cp_commit();
            cp_wait<1>();
        } else {
            cp_wait<0>();
        }
        __syncthreads();

        const __nv_bfloat16* FH = Fbase + (ch & 1) * FCHUNK;
        const __nv_bfloat16* FL = FH + 32 * TSW;

        float acc[4][4];
#pragma unroll
        for (int nt = 0; nt < 4; nt++)
#pragma unroll
            for (int j = 0; j < 4; j++) acc[nt][j] = 0.0f;

#pragma unroll
        for (int ks = 0; ks < 5; ks++) {
            const int kc0 = ks * 16;
            uint32_t ah[4], al[4], bh[4][2], bl[4][2];
            ldsm4(ah, FH + a_m * TSW + kc0 + a_k);
            ldsm4(al, FL + a_m * TSW + kc0 + a_k);
#pragma unroll
            for (int j = 0; j < 2; j++) {
                uint32_t th[4], tl[4];
                ldsm4(th, WdH + (b_n + j * 16) * TSW + kc0 + b_k);
                ldsm4(tl, WdL + (b_n + j * 16) * TSW + kc0 + b_k);
                bh[2 * j][0] = th[0]; bh[2 * j][1] = th[1];
                bh[2 * j + 1][0] = th[2]; bh[2 * j + 1][1] = th[3];
                bl[2 * j][0] = tl[0]; bl[2 * j][1] = tl[1];
                bl[2 * j + 1][0] = tl[2]; bl[2 * j + 1][1] = tl[3];
            }
#pragma unroll
            for (int nt = 0; nt < 4; nt++) {
                mma_bf16(acc[nt], ah, bh[nt]);
                mma_bf16(acc[nt], ah, bl[nt]);
                mma_bf16(acc[nt], al, bh[nt]);
            }
        }

        const int t0 = ch * 32;
        if (diag) {
#pragma unroll
            for (int nt = 0; nt < 4; nt++) {
                const int col = wn * 32 + nt * 8 + tig * 2;
                const int r = wm * 16 + gid;
                *(float2*)&D[r * 128 + col] = make_float2(acc[nt][0], acc[nt][1]);
                *(float2*)&D[(r + 8) * 128 + col] = make_float2(acc[nt][2], acc[nt][3]);
            }
            __syncthreads();
            if (tid < 128) {
                for (int tl2 = 0; tl2 < 32; tl2++) {
                    float d = D[tl2 * 128 + tid];
                    h = fmaxf(fmaf(h, w, rb + d), 0.0f);
                    __nv_bfloat16 hb = __float2bfloat16(h);
                    size_t o = ((size_t)b * NT + t0 + tl2) * NN + n0 + tid;
                    g_hs_hi[o] = hb;
                    g_hs_lo[o] = __float2bfloat16(h - __bfloat162float(hb));
                }
            }
        } else {
#pragma unroll
            for (int nt = 0; nt < 4; nt++) {
                const int col = n0 + wn * 32 + nt * 8 + tig * 2;
                const int r = wm * 16 + gid;
                *(float2*)(g_drive + ((size_t)b * NT + t0 + r) * NN + col)
                    = make_float2(acc[nt][0], acc[nt][1]);
                *(float2*)(g_drive + ((size_t)b * NT + t0 + r + 8) * NN + col)
                    = make_float2(acc[nt][2], acc[nt][3]);
            }
            __syncthreads();
        }
    }
}

// ---------------- RNN general fallback: h in SMEM, 1 bar/step --------------
__global__ void __launch_bounds__(1024, 1) rnn_general_kernel(const float* __restrict__ rec_b,
                                                              const float* __restrict__ init_state) {
    if (*(volatile int*)&g_diag_flag != 0) return;
    __shared__ float hbuf[2][NN];
    const int b = blockIdx.x;
    const int n = threadIdx.x;

    const float rb = rec_b[n];
    const int cnt = g_nnz_cnt[n];
    const int cr = cnt < CMAX ? cnt : CMAX;
    int kk[CMAX]; float ww[CMAX];
    for (int j = 0; j < cr; j++) {
        kk[j] = g_nnz_idx[(size_t)n * NN + j];
        ww[j] = g_nnz_val[(size_t)n * NN + j];
    }
    hbuf[0][n] = init_state[n];
    __syncthreads();

    float d = g_drive[(size_t)b * NT * NN + n];

    for (int t = 0; t < NT; t++) {
        const float* cur = hbuf[t & 1];
        float* nxt = hbuf[(t + 1) & 1];
        float dn = 0.0f;
        if (t + 1 < NT)
            dn = g_drive[((size_t)b * NT + t + 1) * NN + n];

        float acc = rb + d;
        for (int j = 0; j < cr; j++)
            acc += cur[kk[j]] * ww[j];
        for (int j = CMAX; j < cnt; j++)
            acc += cur[g_nnz_idx[(size_t)n * NN + j]] * g_nnz_val[(size_t)n * NN + j];
        float hv = fmaxf(acc, 0.0f);
        nxt[n] = hv;
        const size_t row = ((size_t)b * NT + t) * NN;
        __nv_bfloat16 hb = __float2bfloat16(hv);
        g_hs_hi[row + n] = hb;
        g_hs_lo[row + n] = __float2bfloat16(hv - __bfloat162float(hb));
        __syncthreads();
        d = dn;
    }
}

// ---------------- out-GEMM: 64m x 128n tiles, 2 CTAs/SM, double-buffered ---
#define SA_TILE (64 * TS)              // 4608 elems
#define SB_TILE (128 * TS)             // 9216 elems
#define OSTAGE (2 * SA_TILE + 2 * SB_TILE)   // 27648 elems
#define OGEMM_SMEM (2 * OSTAGE * 2)          // 110592 bytes

__global__ void __launch_bounds__(256) outgemm_mma_kernel(const float* __restrict__ outB) {
    extern __shared__ __nv_bfloat16 smem[];
    const int tid = threadIdx.x;
    const int wid = tid >> 5, lane = tid & 31;
    const int gid = lane >> 2, tig = lane & 3;
    const int wm = wid >> 2, wn = wid & 3;       // 2(m) x 4(n); warp tile 32x32
    const int n0 = blockIdx.x * 128;
    const int row0 = blockIdx.y * 64;

    float acc[2][4][4];
#pragma unroll
    for (int mt = 0; mt < 2; mt++)
#pragma unroll
        for (int nt = 0; nt < 4; nt++)
#pragma unroll
            for (int j = 0; j < 4; j++) acc[mt][nt][j] = 0.0f;

    const int arow = tid >> 2, aq = (tid & 3) * 16;     // A: 64 rows x 64 cols
    const int brow = tid >> 1, bq = (tid & 1) * 32;     // B: 128 rows x 64 cols
    const __nv_bfloat16* gA = g_hs_hi + (size_t)(row0 + arow) * NN + aq;
    const __nv_bfloat16* gL = g_hs_lo + (size_t)(row0 + arow) * NN + aq;
    const __nv_bfloat16* gB = g_wt_hi + (size_t)(n0 + brow) * NN + bq;
    const __nv_bfloat16* gM = g_wt_lo + (size_t)(n0 + brow) * NN + bq;
    const int sbA = arow * TS + aq;
    const int sbB = brow * TS + bq;

    auto load_chunk = [&](int c, int buf) {
        __nv_bfloat16* base = smem + buf * OSTAGE;
        const int k0 = c * 64;
        cp16(base + sbA, gA + k0);
        cp16(base + sbA + 8, gA + k0 + 8);
        cp16(base + SA_TILE + sbA, gL + k0);
        cp16(base + SA_TILE + sbA + 8, gL + k0 + 8);
#pragma unroll
        for (int q = 0; q < 4; q++) {
            cp16(base + 2 * SA_TILE + sbB + q * 8, gB + k0 + q * 8);
            cp16(base + 2 * SA_TILE + SB_TILE + sbB + q * 8, gM + k0 + q * 8);
        }
    };

    const int quad = lane >> 3, rowin = lane & 7;
    const int a_m = wm * 32 + (quad & 1) * 8 + rowin;
    const int a_k = (quad >> 1) * 8;
    const int b_n = wn * 32 + (quad >> 1) * 8 + rowin;
    const int b_k = (quad & 1) * 8;

    load_chunk(0, 0);
    cp_commit();

    for (int c = 0; c < 16; c++) {
        if (c < 15) {
            load_chunk(c + 1, (c + 1) & 1);
            cp_commit();
            cp_wait<1>();
        } else {
            cp_wait<0>();
        }
        __syncthreads();

        const __nv_bfloat16* Ah = smem + (c & 1) * OSTAGE;
        const __nv_bfloat16* Al = Ah + SA_TILE;
        const __nv_bfloat16* Bh = Ah + 2 * SA_TILE;
        const __nv_bfloat16* Bl = Bh + SB_TILE;

#pragma unroll
        for (int ks = 0; ks < 4; ks++) {
            const int kc0 = ks * 16;
            uint32_t ahi[2][4], alo[2][4], bhi[4][2], blo[4][2];
#pragma unroll
            for (int mt = 0; mt < 2; mt++) {
                const int off = (a_m + mt * 16) * TS + kc0 + a_k;
                ldsm4(ahi[mt], Ah + off);
                ldsm4(alo[mt], Al + off);
            }
#pragma unroll
            for (int j = 0; j < 2; j++) {
                const int off = (b_n + j * 16) * TS + kc0 + b_k;
                uint32_t th[4], tl[4];
                ldsm4(th, Bh + off);
                ldsm4(tl, Bl + off);
                bhi[2 * j][0] = th[0]; bhi[2 * j][1] = th[1];
                bhi[2 * j + 1][0] = th[2]; bhi[2 * j + 1][1] = th[3];
                blo[2 * j][0] = tl[0]; blo[2 * j][1] = tl[1];
                blo[2 * j + 1][0] = tl[2]; blo[2 * j + 1][1] = tl[3];
            }
#pragma unroll
            for (int mt = 0; mt < 2; mt++)
#pragma unroll
                for (int nt = 0; nt < 4; nt++) {
                    mma_bf16(acc[mt][nt], ahi[mt], bhi[nt]);
                    mma_bf16(acc[mt][nt], ahi[mt], blo[nt]);
                    mma_bf16(acc[mt][nt], alo[mt], bhi[nt]);
                }
        }
        __syncthreads();
    }

#pragma unroll
    for (int nt = 0; nt < 4; nt++) {
        const int col = n0 + wn * 32 + nt * 8 + tig * 2;
        const float b0 = outB[col], b1 = outB[col + 1];
#pragma unroll
        for (int mt = 0; mt < 2; mt++) {
            const int r = row0 + wm * 32 + mt * 16 + gid;
            float2 o0, o1;
            o0.x = fmaxf(acc[mt][nt][0] + b0, 0.0f);
            o0.y = fmaxf(acc[mt][nt][1] + b1, 0.0f);
            o1.x = fmaxf(acc[mt][nt][2] + b0, 0.0f);
            o1.y = fmaxf(acc[mt][nt][3] + b1, 0.0f);
            *(float2*)(g_out + (size_t)r * NO + col) = o0;
            *(float2*)(g_out + (size_t)(r + 8) * NO + col) = o1;
        }
    }
}

// ---------------- time-softmax -> centers, 2-phase (8 chunks) --------------
__global__ void __launch_bounds__(512) centers_part_kernel(const float* __restrict__ r) {
    const int b = blockIdx.x;
    const int ch = blockIdx.y;
    const int n = threadIdx.x;
    float m = -1e30f, s = 0.0f, c0 = 0.0f, c1 = 0.0f;
    const float* ob = g_out + (size_t)b * NT * NO + (size_t)ch * 32 * NO;
    const float* rb = r + (size_t)b * NT * 2 + ch * 32 * 2;
    for (int t = 0; t < 32; t++) {
        float v = ob[(size_t)t * NO + n];
        float r0 = rb[t * 2 + 0], r1 = rb[t * 2 + 1];
        if (v > m) {
            float f = expf(m - v);
            s = s * f + 1.0f; c0 = c0 * f + r0; c1 = c1 * f + r1; m = v;
        } else {
            float p = expf(v - m);
            s += p; c0 += p * r0; c1 += p * r1;
        }
    }
    g_cpart[((size_t)ch * NB + b) * NO + n] = make_float4(m, s, c0, c1);
}

__global__ void __launch_bounds__(512) centers_comb_kernel() {
    const int b = blockIdx.x;
    const int n = threadIdx.x;
    float m = -1e30f;
#pragma unroll
    for (int ch = 0; ch < 8; ch++)
        m = fmaxf(m, g_cpart[((size_t)ch * NB + b) * NO + n].x);
    float s = 0.0f, c0 = 0.0f, c1 = 0.0f;
#pragma unroll
    for (int ch = 0; ch < 8; ch++) {
        float4 p = g_cpart[((size_t)ch * NB + b) * NO + n];
        float f = expf(p.x - m);
        s += p.y * f; c0 += p.z * f; c1 += p.w * f;
    }
    float inv = 1.0f / s;
    g_centers[((size_t)b * NO + n) * 2 + 0] = c0 * inv;
    g_centers[((size_t)b * NO + n) * 2 + 1] = c1 * inv;
}

// ---------------- cell-softmax -> expected position ------------------------
__global__ void __launch_bounds__(256) final_kernel(float* __restrict__ outp) {
    const int wrp = threadIdx.x >> 5;
    const int lane = threadIdx.x & 31;
    const int row = blockIdx.x * 8 + wrp;
    const int b = row >> 8;
    const float* o = g_out + (size_t)row * NO;

    float v[16];
    float vmax = -1e30f;
#pragma unroll
    for (int i = 0; i < 16; i++) {
        v[i] = o[lane + 32 * i];
        vmax = fmaxf(vmax, v[i]);
    }
#pragma unroll
    for (int off = 16; off; off >>= 1)
        vmax = fmaxf(vmax, __shfl_xor_sync(0xffffffffu, vmax, off));

    float s = 0.0f, a0 = 0.0f, a1 = 0.0f;
    const float* cen = g_centers + (size_t)b * NO * 2;
#pragma unroll
    for (int i = 0; i < 16; i++) {
        int n = lane + 32 * i;
        float p = expf(v[i] - vmax);
        s += p;
        float2 c = *(const float2*)(cen + n * 2);
        a0 += p * c.x; a1 += p * c.y;
    }
#pragma unroll
    for (int off = 16; off; off >>= 1) {
        s  += __shfl_xor_sync(0xffffffffu, s, off);
        a0 += __shfl_xor_sync(0xffffffffu, a0, off);
        a1 += __shfl_xor_sync(0xffffffffu, a1, off);
    }
    if (lane == 0) {
        float inv = 1.0f / s;
        outp[row * 2 + 0] = a0 * inv;
        outp[row * 2 + 1] = a1 * inv;
    }
}

extern "C" void kernel_launch(void* const* d_in, const int* in_sizes, int n_in,
                              void* d_out, int out_size) {
    const float* x    = (const float*)d_in[0];
    const float* r    = (const float*)d_in[1];
    const float* sW   = (const float*)d_in[2];
    const float* hW   = (const float*)d_in[3];
    const float* recW = (const float*)d_in[4];
    const float* recb = (const float*)d_in[5];
    const float* outW = (const float*)d_in[6];
    const float* outb = (const float*)d_in[7];
    const float* init = (const float*)d_in[8];
    float* outp = (float*)d_out;

    csc_phase1<<<NN / 16, 256>>>(recW);
    csc_phase2<<<NN / 256, 256>>>();
    {
        dim3 g(NN / 32, NO / 32);
        wsplit_kernel<<<g, 256>>>(outW);
    }
    wdsplit_kernel<<<(NN * NKP) / 256, 256>>>(sW, hW);
    feat_kernel<<<(NB * NT * NKP) / 256, 256>>>(x);
    {
        cudaFuncSetAttribute(fused_drive_rnn_kernel,
                             cudaFuncAttributeMaxDynamicSharedMemorySize, FUSED_SMEM);
        dim3 g(NN / 128, NB);
        fused_drive_rnn_kernel<<<g, 256, FUSED_SMEM>>>(recb, init);
    }
    rnn_general_kernel<<<NB, 1024>>>(recb, init);
    {
        cudaFuncSetAttribute(outgemm_mma_kernel,
                             cudaFuncAttributeMaxDynamicSharedMemorySize, OGEMM_SMEM);
        dim3 g(NO / 128, (NB * NT) / 64);
        outgemm_mma_kernel<<<g, 256, OGEMM_SMEM>>>(outb);
    }
    {
        dim3 g(NB, 8);
        centers_part_kernel<<<g, 512>>>(r);
    }
    centers_comb_kernel<<<NB, 512>>>();
    final_kernel<<<(NB * NT) / 8, 256>>>(outp);
}

// round 15
// speedup vs baseline: 5.8446x; 1.3186x over previous
#include <cuda_runtime.h>
#include <cuda_bf16.h>
#include <cuda_fp16.h>
#include <math.h>
#include <stdint.h>

#define NB 64
#define NT 256
#define NN 1024
#define NO 512
#define NK_SPEED 20
#define NK_HD 50
#define NK_TOT 70
#define NKP 80
#define CMAX 4

__device__ float          g_drive[(size_t)NB * NT * NN];
__device__ __nv_bfloat16  g_ft_hi[(size_t)NB * NT * NKP];
__device__ __nv_bfloat16  g_ft_lo[(size_t)NB * NT * NKP];
__device__ __nv_bfloat16  g_wd_hi[(size_t)NN * NKP];
__device__ __nv_bfloat16  g_wd_lo[(size_t)NN * NKP];
__device__ __half         g_hs_hi[(size_t)NB * NT * NN];
__device__ __half         g_hs_lo[(size_t)NB * NT * NN];
__device__ __half         g_wt[(size_t)NO * NN];
__device__ float          g_out[(size_t)NB * NT * NO];
__device__ float          g_centers[NB * NO * 2];
__device__ float4         g_cpart[8 * NB * NO];
__device__ int            g_nnz_cnt[NN];
__device__ int            g_nnz_idx[(size_t)NN * NN];
__device__ float          g_nnz_val[(size_t)NN * NN];
__device__ int            g_tmp_idx[(size_t)NN * NN];
__device__ float          g_tmp_val[(size_t)NN * NN];
__device__ int            g_scnt[NN * 16];
__device__ float          g_wdiag[NN];
__device__ int            g_diag_flag;

// ---------------- CSC phase 1: 16 k-segments per column, 64 CTAs -----------
__global__ void __launch_bounds__(256) csc_phase1(const float* __restrict__ recW) {
    const int tid = threadIdx.x;
    const int n = blockIdx.x * 16 + (tid & 15);
    const int kt = tid >> 4;
    int c = 0;
    const int kbase = kt * 64;
    for (int i = 0; i < 64; i++) {
        float w = recW[(size_t)(kbase + i) * NN + n];
        if (w != 0.0f) {
            g_tmp_idx[(size_t)n * NN + kbase + c] = kbase + i;
            g_tmp_val[(size_t)n * NN + kbase + c] = w;
            c++;
        }
    }
    g_scnt[n * 16 + kt] = c;
    if (blockIdx.x == 0 && tid == 0) g_diag_flag = 1;
}

// ---------------- CSC phase 2: concat segments, detect diagonality ---------
__global__ void __launch_bounds__(256) csc_phase2() {
    const int n = blockIdx.x * 256 + threadIdx.x;
    int off = 0;
    bool diag = true;
    float wsum = 0.0f;
    for (int s = 0; s < 16; s++) {
        const int c = g_scnt[n * 16 + s];
        for (int i = 0; i < c; i++) {
            int k = g_tmp_idx[(size_t)n * NN + s * 64 + i];
            float w = g_tmp_val[(size_t)n * NN + s * 64 + i];
            g_nnz_idx[(size_t)n * NN + off] = k;
            g_nnz_val[(size_t)n * NN + off] = w;
            off++;
            if (k != n) diag = false; else wsum += w;
        }
    }
    g_nnz_cnt[n] = off;
    g_wdiag[n] = wsum;
    if (!diag) g_diag_flag = 0;
}

// ---------------- transpose out_W -> [NO][NN] fp16 -------------------------
__global__ void __launch_bounds__(256) wsplit_kernel(const float* __restrict__ outW) {
    __shared__ float tile[32][33];
    const int k0 = blockIdx.x * 32, n0 = blockIdx.y * 32;
    const int tx = threadIdx.x & 31, ty = threadIdx.x >> 5;
#pragma unroll
    for (int i = 0; i < 4; i++)
        tile[ty + 8 * i][tx] = outW[(size_t)(k0 + ty + 8 * i) * NO + n0 + tx];
    __syncthreads();
#pragma unroll
    for (int i = 0; i < 4; i++) {
        int row = ty + 8 * i;
        float v = tile[tx][row];
        g_wt[(size_t)(n0 + row) * NN + k0 + tx] = __float2half(v);
    }
}

// ---------------- bf16-split [speed_W; hd_W]^T -> [NN][NKP] ----------------
__global__ void __launch_bounds__(256) wdsplit_kernel(const float* __restrict__ sW,
                                                      const float* __restrict__ hW) {
    const int idx = blockIdx.x * 256 + threadIdx.x;
    const int n = idx / NKP;
    const int k = idx - n * NKP;
    float v = 0.0f;
    if (k < NK_SPEED)      v = sW[(size_t)k * NN + n];
    else if (k < NK_TOT)   v = hW[(size_t)(k - NK_SPEED) * NN + n];
    __nv_bfloat16 hi = __float2bfloat16(v);
    __nv_bfloat16 lo = __float2bfloat16(v - __bfloat162float(hi));
    g_wd_hi[idx] = hi;
    g_wd_lo[idx] = lo;
}

// ---------------- features -> bf16 hi/lo, K padded to 80 -------------------
__global__ void __launch_bounds__(256) feat_kernel(const float* __restrict__ x) {
    const int idx = blockIdx.x * 256 + threadIdx.x;
    const int row = idx / NKP;
    const int k = idx - row * NKP;
    const float TWO_PI = 6.2831853071795865f;
    const float LOGNORM = 6.3050317f;  // log(2*pi*I0(2*pi))
    float f = 0.0f;
    if (k < NK_SPEED) {
        float v = x[(size_t)row * 2 + 0];
        float dv = v - 0.5f * (float)k / 19.0f;
        f = expf(-800.0f * dv * dv);
    } else if (k < NK_TOT) {
        float th = x[(size_t)row * 2 + 1];
        float c = TWO_PI * (float)(k - NK_SPEED) / 49.0f;
        f = expf(TWO_PI * cosf(th - c) - LOGNORM);
    }
    __nv_bfloat16 hi = __float2bfloat16(f);
    __nv_bfloat16 lo = __float2bfloat16(f - __bfloat162float(hi));
    g_ft_hi[idx] = hi;
    g_ft_lo[idx] = lo;
}

// ---------------- common machinery -----------------------------------------
#define TS 72

__device__ __forceinline__ void cp16(void* smem_dst, const void* gsrc) {
    uint32_t s = (uint32_t)__cvta_generic_to_shared(smem_dst);
    asm volatile("cp.async.cg.shared.global [%0], [%1], 16;" :: "r"(s), "l"(gsrc) : "memory");
}
__device__ __forceinline__ void cp_commit() {
    asm volatile("cp.async.commit_group;" ::: "memory");
}
template <int N>
__device__ __forceinline__ void cp_wait() {
    asm volatile("cp.async.wait_group %0;" :: "n"(N) : "memory");
}
__device__ __forceinline__ void mma_bf16(float* d, const uint32_t* a, const uint32_t* b) {
    asm volatile(
        "mma.sync.aligned.m16n8k16.row.col.f32.bf16.bf16.f32 "
        "{%0,%1,%2,%3}, {%4,%5,%6,%7}, {%8,%9}, {%0,%1,%2,%3};"
        : "+f"(d[0]), "+f"(d[1]), "+f"(d[2]), "+f"(d[3])
        : "r"(a[0]), "r"(a[1]), "r"(a[2]), "r"(a[3]), "r"(b[0]), "r"(b[1]));
}
__device__ __forceinline__ void mma_f16(float* d, const uint32_t* a, const uint32_t* b) {
    asm volatile(
        "mma.sync.aligned.m16n8k16.row.col.f32.f16.f16.f32 "
        "{%0,%1,%2,%3}, {%4,%5,%6,%7}, {%8,%9}, {%0,%1,%2,%3};"
        : "+f"(d[0]), "+f"(d[1]), "+f"(d[2]), "+f"(d[3])
        : "r"(a[0]), "r"(a[1]), "r"(a[2]), "r"(a[3]), "r"(b[0]), "r"(b[1]));
}
__device__ __forceinline__ void ldsm4(uint32_t* r, const void* p) {
    uint32_t a = (uint32_t)__cvta_generic_to_shared(p);
    asm volatile("ldmatrix.sync.aligned.m8n8.x4.shared.b16 {%0,%1,%2,%3}, [%4];"
                 : "=r"(r[0]), "=r"(r[1]), "=r"(r[2]), "=r"(r[3]) : "r"(a));
}

// ---------------- fused drive-GEMM + RNN scan (bf16 3-pass, unchanged) -----
#define TSW 88
#define FCHUNK (2 * 32 * TSW)
#define FUSED_SMEM_ELEMS (2 * 128 * TSW + 2 * FCHUNK)
#define FUSED_SMEM (FUSED_SMEM_ELEMS * 2 + 32 * 128 * 4)

__global__ void __launch_bounds__(256, 1) fused_drive_rnn_kernel(const float* __restrict__ rec_b,
                                                                 const float* __restrict__ init_state) {
    extern __shared__ __nv_bfloat16 sm[];
    __nv_bfloat16* WdH = sm;
    __nv_bfloat16* WdL = sm + 128 * TSW;
    __nv_bfloat16* Fbase = sm + 2 * 128 * TSW;
    float* D = (float*)(sm + FUSED_SMEM_ELEMS);

    const int tid = threadIdx.x;
    const int wid = tid >> 5, lane = tid & 31;
    const int gid = lane >> 2, tig = lane & 3;
    const int wm = wid >> 2, wn = wid & 3;
    const int n0 = blockIdx.x * 128;
    const int b = blockIdx.y;
    const int diag = *(volatile int*)&g_diag_flag;

    {
        const int row = tid >> 1, half = tid & 1;
        const __nv_bfloat16* gh = g_wd_hi + (size_t)(n0 + row) * NKP + half * 40;
        const __nv_bfloat16* gl = g_wd_lo + (size_t)(n0 + row) * NKP + half * 40;
        __nv_bfloat16* dh = WdH + row * TSW + half * 40;
        __nv_bfloat16* dl = WdL + row * TSW + half * 40;
#pragma unroll
        for (int q = 0; q < 5; q++) {
            cp16(dh + q * 8, gh + q * 8);
            cp16(dl + q * 8, gl + q * 8);
        }
    }

    auto loadF = [&](int ch, int buf) {
        __nv_bfloat16* FH = Fbase + buf * FCHUNK;
        __nv_bfloat16* FL = FH + 32 * TSW;
        const int t0 = ch * 32;
#pragma unroll
        for (int i = 0; i < 2; i++) {
            int e = tid + i * 256;
            if (e < 320) {
                int row = e / 10, q = e - row * 10;
                size_t gro = ((size_t)b * NT + t0 + row) * NKP + q * 8;
                cp16(FH + row * TSW + q * 8, g_ft_hi + gro);
                cp16(FL + row * TSW + q * 8, g_ft_lo + gro);
            }
        }
    };
    loadF(0, 0);
    cp_commit();

    float h = 0.0f, w = 0.0f, rb = 0.0f;
    if (tid < 128) {
        const int n = n0 + tid;
        w = g_wdiag[n];
        rb = rec_b[n];
        h = init_state[n];
    }

    const int quad = lane >> 3, rowin = lane & 7;
    const int a_m = wm * 16 + (quad & 1) * 8 + rowin;
    const int a_k = (quad >> 1) * 8;
    const int b_n = wn * 32 + (quad >> 1) * 8 + rowin;
    const int b_k = (quad & 1) * 8;

    for (int ch = 0; ch < 8; ch++) {
        if (ch < 7) {
            loadF(ch + 1, (ch + 1) & 1);
            cp_commit();
            cp_wait<1>();
        } else {
            cp_wait<0>();
        }
        __syncthreads();

        const __nv_bfloat16* FH = Fbase + (ch & 1) * FCHUNK;
        const __nv_bfloat16* FL = FH + 32 * TSW;

        float acc[4][4];
#pragma unroll
        for (int nt = 0; nt < 4; nt++)
#pragma unroll
            for (int j = 0; j < 4; j++) acc[nt][j] = 0.0f;

#pragma unroll
        for (int ks = 0; ks < 5; ks++) {
            const int kc0 = ks * 16;
            uint32_t ah[4], al[4], bh[4][2], bl[4][2];
            ldsm4(ah, FH + a_m * TSW + kc0 + a_k);
            ldsm4(al, FL + a_m * TSW + kc0 + a_k);
#pragma unroll
            for (int j = 0; j < 2; j++) {
                uint32_t th[4], tl[4];
                ldsm4(th, WdH + (b_n + j * 16) * TSW + kc0 + b_k);
                ldsm4(tl, WdL + (b_n + j * 16) * TSW + kc0 + b_k);
                bh[2 * j][0] = th[0]; bh[2 * j][1] = th[1];
                bh[2 * j + 1][0] = th[2]; bh[2 * j + 1][1] = th[3];
                bl[2 * j][0] = tl[0]; bl[2 * j][1] = tl[1];
                bl[2 * j + 1][0] = tl[2]; bl[2 * j + 1][1] = tl[3];
            }
#pragma unroll
            for (int nt = 0; nt < 4; nt++) {
                mma_bf16(acc[nt], ah, bh[nt]);
                mma_bf16(acc[nt], ah, bl[nt]);
                mma_bf16(acc[nt], al, bh[nt]);
            }
        }

        const int t0 = ch * 32;
        if (diag) {
#pragma unroll
            for (int nt = 0; nt < 4; nt++) {
                const int col = wn * 32 + nt * 8 + tig * 2;
                const int r = wm * 16 + gid;
                *(float2*)&D[r * 128 + col] = make_float2(acc[nt][0], acc[nt][1]);
                *(float2*)&D[(r + 8) * 128 + col] = make_float2(acc[nt][2], acc[nt][3]);
            }
            __syncthreads();
            if (tid < 128) {
                for (int tl2 = 0; tl2 < 32; tl2++) {
                    float d = D[tl2 * 128 + tid];
                    h = fmaxf(fmaf(h, w, rb + d), 0.0f);
                    __half hb = __float2half(h);
                    size_t o = ((size_t)b * NT + t0 + tl2) * NN + n0 + tid;
                    g_hs_hi[o] = hb;
                    g_hs_lo[o] = __float2half(h - __half2float(hb));
                }
            }
        } else {
#pragma unroll
            for (int nt = 0; nt < 4; nt++) {
                const int col = n0 + wn * 32 + nt * 8 + tig * 2;
                const int r = wm * 16 + gid;
                *(float2*)(g_drive + ((size_t)b * NT + t0 + r) * NN + col)
                    = make_float2(acc[nt][0], acc[nt][1]);
                *(float2*)(g_drive + ((size_t)b * NT + t0 + r + 8) * NN + col)
                    = make_float2(acc[nt][2], acc[nt][3]);
            }
            __syncthreads();
        }
    }
}

// ---------------- RNN general fallback: h in SMEM, 1 bar/step --------------
__global__ void __launch_bounds__(1024, 1) rnn_general_kernel(const float* __restrict__ rec_b,
                                                              const float* __restrict__ init_state) {
    if (*(volatile int*)&g_diag_flag != 0) return;
    __shared__ float hbuf[2][NN];
    const int b = blockIdx.x;
    const int n = threadIdx.x;

    const float rb = rec_b[n];
    const int cnt = g_nnz_cnt[n];
    const int cr = cnt < CMAX ? cnt : CMAX;
    int kk[CMAX]; float ww[CMAX];
    for (int j = 0; j < cr; j++) {
        kk[j] = g_nnz_idx[(size_t)n * NN + j];
        ww[j] = g_nnz_val[(size_t)n * NN + j];
    }
    hbuf[0][n] = init_state[n];
    __syncthreads();

    float d = g_drive[(size_t)b * NT * NN + n];

    for (int t = 0; t < NT; t++) {
        const float* cur = hbuf[t & 1];
        float* nxt = hbuf[(t + 1) & 1];
        float dn = 0.0f;
        if (t + 1 < NT)
            dn = g_drive[((size_t)b * NT + t + 1) * NN + n];

        float acc = rb + d;
        for (int j = 0; j < cr; j++)
            acc += cur[kk[j]] * ww[j];
        for (int j = CMAX; j < cnt; j++)
            acc += cur[g_nnz_idx[(size_t)n * NN + j]] * g_nnz_val[(size_t)n * NN + j];
        float hv = fmaxf(acc, 0.0f);
        nxt[n] = hv;
        const size_t row = ((size_t)b * NT + t) * NN;
        __half hb = __float2half(hv);
        g_hs_hi[row + n] = hb;
        g_hs_lo[row + n] = __float2half(hv - __half2float(hb));
        __syncthreads();
        d = dn;
    }
}

// ---------------- out-GEMM: fp16 2-pass, 64m x 128n, 3 CTAs/SM -------------
#define SA_TILE (64 * TS)                    // 4608 elems
#define SB_TILE (128 * TS)                   // 9216 elems
#define OSTAGE (2 * SA_TILE + SB_TILE)       // 18432 elems (Ahi, Alo, B)
#define OGEMM_SMEM (2 * OSTAGE * 2)          // 73728 bytes

__global__ void __launch_bounds__(256) outgemm_mma_kernel(const float* __restrict__ outB) {
    extern __shared__ __half smemh[];
    const int tid = threadIdx.x;
    const int wid = tid >> 5, lane = tid & 31;
    const int gid = lane >> 2, tig = lane & 3;
    const int wm = wid >> 2, wn = wid & 3;       // 2(m) x 4(n); warp tile 32x32
    const int n0 = blockIdx.x * 128;
    const int row0 = blockIdx.y * 64;

    float acc[2][4][4];
#pragma unroll
    for (int mt = 0; mt < 2; mt++)
#pragma unroll
        for (int nt = 0; nt < 4; nt++)
#pragma unroll
            for (int j = 0; j < 4; j++) acc[mt][nt][j] = 0.0f;

    const int arow = tid >> 2, aq = (tid & 3) * 16;     // A: 64 rows x 64 cols
    const int brow = tid >> 1, bq = (tid & 1) * 32;     // B: 128 rows x 64 cols
    const __half* gA = g_hs_hi + (size_t)(row0 + arow) * NN + aq;
    const __half* gL = g_hs_lo + (size_t)(row0 + arow) * NN + aq;
    const __half* gB = g_wt + (size_t)(n0 + brow) * NN + bq;
    const int sbA = arow * TS + aq;
    const int sbB = brow * TS + bq;

    auto load_chunk = [&](int c, int buf) {
        __half* base = smemh + buf * OSTAGE;
        const int k0 = c * 64;
        cp16(base + sbA, gA + k0);
        cp16(base + sbA + 8, gA + k0 + 8);
        cp16(base + SA_TILE + sbA, gL + k0);
        cp16(base + SA_TILE + sbA + 8, gL + k0 + 8);
#pragma unroll
        for (int q = 0; q < 4; q++)
            cp16(base + 2 * SA_TILE + sbB + q * 8, gB + k0 + q * 8);
    };

    const int quad = lane >> 3, rowin = lane & 7;
    const int a_m = wm * 32 + (quad & 1) * 8 + rowin;
    const int a_k = (quad >> 1) * 8;
    const int b_n = wn * 32 + (quad >> 1) * 8 + rowin;
    const int b_k = (quad & 1) * 8;

    load_chunk(0, 0);
    cp_commit();

    for (int c = 0; c < 16; c++) {
        if (c < 15) {
            load_chunk(c + 1, (c + 1) & 1);
            cp_commit();
            cp_wait<1>();
        } else {
            cp_wait<0>();
        }
        __syncthreads();

        const __half* Ah = smemh + (c & 1) * OSTAGE;
        const __half* Al = Ah + SA_TILE;
        const __half* Bt = Ah + 2 * SA_TILE;

#pragma unroll
        for (int ks = 0; ks < 4; ks++) {
            const int kc0 = ks * 16;
            uint32_t ahi[2][4], alo[2][4], bf[4][2];
#pragma unroll
            for (int mt = 0; mt < 2; mt++) {
                const int off = (a_m + mt * 16) * TS + kc0 + a_k;
                ldsm4(ahi[mt], Ah + off);
                ldsm4(alo[mt], Al + off);
            }
#pragma unroll
            for (int j = 0; j < 2; j++) {
                const int off = (b_n + j * 16) * TS + kc0 + b_k;
                uint32_t tb[4];
                ldsm4(tb, Bt + off);
                bf[2 * j][0] = tb[0]; bf[2 * j][1] = tb[1];
                bf[2 * j + 1][0] = tb[2]; bf[2 * j + 1][1] = tb[3];
            }
#pragma unroll
            for (int mt = 0; mt < 2; mt++)
#pragma unroll
                for (int nt = 0; nt < 4; nt++) {
                    mma_f16(acc[mt][nt], ahi[mt], bf[nt]);
                    mma_f16(acc[mt][nt], alo[mt], bf[nt]);
                }
        }
        __syncthreads();
    }

#pragma unroll
    for (int nt = 0; nt < 4; nt++) {
        const int col = n0 + wn * 32 + nt * 8 + tig * 2;
        const float b0 = outB[col], b1 = outB[col + 1];
#pragma unroll
        for (int mt = 0; mt < 2; mt++) {
            const int r = row0 + wm * 32 + mt * 16 + gid;
            float2 o0, o1;
            o0.x = fmaxf(acc[mt][nt][0] + b0, 0.0f);
            o0.y = fmaxf(acc[mt][nt][1] + b1, 0.0f);
            o1.x = fmaxf(acc[mt][nt][2] + b0, 0.0f);
            o1.y = fmaxf(acc[mt][nt][3] + b1, 0.0f);
            *(float2*)(g_out + (size_t)r * NO + col) = o0;
            *(float2*)(g_out + (size_t)(r + 8) * NO + col) = o1;
        }
    }
}

// ---------------- time-softmax -> centers, 2-phase (8 chunks) --------------
__global__ void __launch_bounds__(512) centers_part_kernel(const float* __restrict__ r) {
    const int b = blockIdx.x;
    const int ch = blockIdx.y;
    const int n = threadIdx.x;
    float m = -1e30f, s = 0.0f, c0 = 0.0f, c1 = 0.0f;
    const float* ob = g_out + (size_t)b * NT * NO + (size_t)ch * 32 * NO;
    const float* rb = r + (size_t)b * NT * 2 + ch * 32 * 2;
    for (int t = 0; t < 32; t++) {
        float v = ob[(size_t)t * NO + n];
        float r0 = rb[t * 2 + 0], r1 = rb[t * 2 + 1];
        if (v > m) {
            float f = expf(m - v);
            s = s * f + 1.0f; c0 = c0 * f + r0; c1 = c1 * f + r1; m = v;
        } else {
            float p = expf(v - m);
            s += p; c0 += p * r0; c1 += p * r1;
        }
    }
    g_cpart[((size_t)ch * NB + b) * NO + n] = make_float4(m, s, c0, c1);
}

__global__ void __launch_bounds__(512) centers_comb_kernel() {
    const int b = blockIdx.x;
    const int n = threadIdx.x;
    float m = -1e30f;
#pragma unroll
    for (int ch = 0; ch < 8; ch++)
        m = fmaxf(m, g_cpart[((size_t)ch * NB + b) * NO + n].x);
    float s = 0.0f, c0 = 0.0f, c1 = 0.0f;
#pragma unroll
    for (int ch = 0; ch < 8; ch++) {
        float4 p = g_cpart[((size_t)ch * NB + b) * NO + n];
        float f = expf(p.x - m);
        s += p.y * f; c0 += p.z * f; c1 += p.w * f;
    }
    float inv = 1.0f / s;
    g_centers[((size_t)b * NO + n) * 2 + 0] = c0 * inv;
    g_centers[((size_t)b * NO + n) * 2 + 1] = c1 * inv;
}

// ---------------- cell-softmax -> expected position ------------------------
__global__ void __launch_bounds__(256) final_kernel(float* __restrict__ outp) {
    const int wrp = threadIdx.x >> 5;
    const int lane = threadIdx.x & 31;
    const int row = blockIdx.x * 8 + wrp;
    const int b = row >> 8;
    const float* o = g_out + (size_t)row * NO;

    float v[16];
    float vmax = -1e30f;
#pragma unroll
    for (int i = 0; i < 16; i++) {
        v[i] = o[lane + 32 * i];
        vmax = fmaxf(vmax, v[i]);
    }
#pragma unroll
    for (int off = 16; off; off >>= 1)
        vmax = fmaxf(vmax, __shfl_xor_sync(0xffffffffu, vmax, off));

    float s = 0.0f, a0 = 0.0f, a1 = 0.0f;
    const float* cen = g_centers + (size_t)b * NO * 2;
#pragma unroll
    for (int i = 0; i < 16; i++) {
        int n = lane + 32 * i;
        float p = expf(v[i] - vmax);
        s += p;
        float2 c = *(const float2*)(cen + n * 2);
        a0 += p * c.x; a1 += p * c.y;
    }
#pragma unroll
    for (int off = 16; off; off >>= 1) {
        s  += __shfl_xor_sync(0xffffffffu, s, off);
        a0 += __shfl_xor_sync(0xffffffffu, a0, off);
        a1 += __shfl_xor_sync(0xffffffffu, a1, off);
    }
    if (lane == 0) {
        float inv = 1.0f / s;
        outp[row * 2 + 0] = a0 * inv;
        outp[row * 2 + 1] = a1 * inv;
    }
}

extern "C" void kernel_launch(void* const* d_in, const int* in_sizes, int n_in,
                              void* d_out, int out_size) {
    const float* x    = (const float*)d_in[0];
    const float* r    = (const float*)d_in[1];
    const float* sW   = (const float*)d_in[2];
    const float* hW   = (const float*)d_in[3];
    const float* recW = (const float*)d_in[4];
    const float* recb = (const float*)d_in[5];
    const float* outW = (const float*)d_in[6];
    const float* outb = (const float*)d_in[7];
    const float* init = (const float*)d_in[8];
    float* outp = (float*)d_out;

    csc_phase1<<<NN / 16, 256>>>(recW);
    csc_phase2<<<NN / 256, 256>>>();
    {
        dim3 g(NN / 32, NO / 32);
        wsplit_kernel<<<g, 256>>>(outW);
    }
    wdsplit_kernel<<<(NN * NKP) / 256, 256>>>(sW, hW);
    feat_kernel<<<(NB * NT * NKP) / 256, 256>>>(x);
    {
        cudaFuncSetAttribute(fused_drive_rnn_kernel,
                             cudaFuncAttributeMaxDynamicSharedMemorySize, FUSED_SMEM);
        dim3 g(NN / 128, NB);
        fused_drive_rnn_kernel<<<g, 256, FUSED_SMEM>>>(recb, init);
    }
    rnn_general_kernel<<<NB, 1024>>>(recb, init);
    {
        cudaFuncSetAttribute(outgemm_mma_kernel,
                             cudaFuncAttributeMaxDynamicSharedMemorySize, OGEMM_SMEM);
        dim3 g(NO / 128, (NB * NT) / 64);
        outgemm_mma_kernel<<<g, 256, OGEMM_SMEM>>>(outb);
    }
    {
        dim3 g(NB, 8);
        centers_part_kernel<<<g, 512>>>(r);
    }
    centers_comb_kernel<<<NB, 512>>>();
    final_kernel<<<(NB * NT) / 8, 256>>>(outp);
}

// round 16
// speedup vs baseline: 7.8188x; 1.3378x over previous
#include <cuda_runtime.h>
#include <cuda_bf16.h>
#include <cuda_fp16.h>
#include <math.h>
#include <stdint.h>

#define NB 64
#define NT 256
#define NN 1024
#define NO 512
#define NK_SPEED 20
#define NK_HD 50
#define NK_TOT 70
#define NKP 80
#define CMAX 4

__device__ float  g_drive[(size_t)NB * NT * NN];
__device__ __half g_ft_hi[(size_t)NB * NT * NKP];
__device__ __half g_ft_lo[(size_t)NB * NT * NKP];
__device__ __half g_wd[(size_t)NN * NKP];
__device__ __half g_hs[(size_t)NB * NT * NN];
__device__ __half g_wt[(size_t)NO * NN];
__device__ float  g_out[(size_t)NB * NT * NO];
__device__ float  g_centers[NB * NO * 2];
__device__ float4 g_cpart[8 * NB * NO];
__device__ int    g_nnz_cnt[NN];
__device__ int    g_nnz_idx[(size_t)NN * NN];
__device__ float  g_nnz_val[(size_t)NN * NN];
__device__ int    g_tmp_idx[(size_t)NN * NN];
__device__ float  g_tmp_val[(size_t)NN * NN];
__device__ int    g_scnt[NN * 16];
__device__ float  g_wdiag[NN];
__device__ int    g_diag_flag;

// ---------------- CSC phase 1: 16 k-segments per column, 64 CTAs -----------
__global__ void __launch_bounds__(256) csc_phase1(const float* __restrict__ recW) {
    const int tid = threadIdx.x;
    const int n = blockIdx.x * 16 + (tid & 15);
    const int kt = tid >> 4;
    int c = 0;
    const int kbase = kt * 64;
    for (int i = 0; i < 64; i++) {
        float w = recW[(size_t)(kbase + i) * NN + n];
        if (w != 0.0f) {
            g_tmp_idx[(size_t)n * NN + kbase + c] = kbase + i;
            g_tmp_val[(size_t)n * NN + kbase + c] = w;
            c++;
        }
    }
    g_scnt[n * 16 + kt] = c;
    if (blockIdx.x == 0 && tid == 0) g_diag_flag = 1;
}

// ---------------- CSC phase 2: concat segments, detect diagonality ---------
__global__ void __launch_bounds__(256) csc_phase2() {
    const int n = blockIdx.x * 256 + threadIdx.x;
    int off = 0;
    bool diag = true;
    float wsum = 0.0f;
    for (int s = 0; s < 16; s++) {
        const int c = g_scnt[n * 16 + s];
        for (int i = 0; i < c; i++) {
            int k = g_tmp_idx[(size_t)n * NN + s * 64 + i];
            float w = g_tmp_val[(size_t)n * NN + s * 64 + i];
            g_nnz_idx[(size_t)n * NN + off] = k;
            g_nnz_val[(size_t)n * NN + off] = w;
            off++;
            if (k != n) diag = false; else wsum += w;
        }
    }
    g_nnz_cnt[n] = off;
    g_wdiag[n] = wsum;
    if (!diag) g_diag_flag = 0;
}

// ---------------- transpose out_W -> [NO][NN] fp16 -------------------------
__global__ void __launch_bounds__(256) wsplit_kernel(const float* __restrict__ outW) {
    __shared__ float tile[32][33];
    const int k0 = blockIdx.x * 32, n0 = blockIdx.y * 32;
    const int tx = threadIdx.x & 31, ty = threadIdx.x >> 5;
#pragma unroll
    for (int i = 0; i < 4; i++)
        tile[ty + 8 * i][tx] = outW[(size_t)(k0 + ty + 8 * i) * NO + n0 + tx];
    __syncthreads();
#pragma unroll
    for (int i = 0; i < 4; i++) {
        int row = ty + 8 * i;
        g_wt[(size_t)(n0 + row) * NN + k0 + tx] = __float2half(tile[tx][row]);
    }
}

// ---------------- [speed_W; hd_W]^T -> [NN][NKP] fp16 ----------------------
__global__ void __launch_bounds__(256) wdsplit_kernel(const float* __restrict__ sW,
                                                      const float* __restrict__ hW) {
    const int idx = blockIdx.x * 256 + threadIdx.x;
    const int n = idx / NKP;
    const int k = idx - n * NKP;
    float v = 0.0f;
    if (k < NK_SPEED)      v = sW[(size_t)k * NN + n];
    else if (k < NK_TOT)   v = hW[(size_t)(k - NK_SPEED) * NN + n];
    g_wd[idx] = __float2half(v);
}

// ---------------- features -> fp16 hi/lo, K padded to 80 -------------------
__global__ void __launch_bounds__(256) feat_kernel(const float* __restrict__ x) {
    const int idx = blockIdx.x * 256 + threadIdx.x;
    const int row = idx / NKP;
    const int k = idx - row * NKP;
    const float TWO_PI = 6.2831853071795865f;
    const float LOGNORM = 6.3050317f;  // log(2*pi*I0(2*pi))
    float f = 0.0f;
    if (k < NK_SPEED) {
        float v = x[(size_t)row * 2 + 0];
        float dv = v - 0.5f * (float)k / 19.0f;
        f = expf(-800.0f * dv * dv);
    } else if (k < NK_TOT) {
        float th = x[(size_t)row * 2 + 1];
        float c = TWO_PI * (float)(k - NK_SPEED) / 49.0f;
        f = expf(TWO_PI * cosf(th - c) - LOGNORM);
    }
    __half hi = __float2half(f);
    __half lo = __float2half(f - __half2float(hi));
    g_ft_hi[idx] = hi;
    g_ft_lo[idx] = lo;
}

// ---------------- common machinery -----------------------------------------
#define TS 72

__device__ __forceinline__ void cp16(void* smem_dst, const void* gsrc) {
    uint32_t s = (uint32_t)__cvta_generic_to_shared(smem_dst);
    asm volatile("cp.async.cg.shared.global [%0], [%1], 16;" :: "r"(s), "l"(gsrc) : "memory");
}
__device__ __forceinline__ void cp_commit() {
    asm volatile("cp.async.commit_group;" ::: "memory");
}
template <int N>
__device__ __forceinline__ void cp_wait() {
    asm volatile("cp.async.wait_group %0;" :: "n"(N) : "memory");
}
__device__ __forceinline__ void mma_f16(float* d, const uint32_t* a, const uint32_t* b) {
    asm volatile(
        "mma.sync.aligned.m16n8k16.row.col.f32.f16.f16.f32 "
        "{%0,%1,%2,%3}, {%4,%5,%6,%7}, {%8,%9}, {%0,%1,%2,%3};"
        : "+f"(d[0]), "+f"(d[1]), "+f"(d[2]), "+f"(d[3])
        : "r"(a[0]), "r"(a[1]), "r"(a[2]), "r"(a[3]), "r"(b[0]), "r"(b[1]));
}
__device__ __forceinline__ void ldsm4(uint32_t* r, const void* p) {
    uint32_t a = (uint32_t)__cvta_generic_to_shared(p);
    asm volatile("ldmatrix.sync.aligned.m8n8.x4.shared.b16 {%0,%1,%2,%3}, [%4];"
                 : "=r"(r[0]), "=r"(r[1]), "=r"(r[2]), "=r"(r[3]) : "r"(a));
}

// ---------------- fused drive-GEMM + RNN scan (fp16 2-pass) ----------------
#define TSW 88
#define FCHUNK (2 * 32 * TSW)                         // Fhi+Flo chunk (halfs)
#define FUSED_SMEM_ELEMS (128 * TSW + 2 * FCHUNK)     // Wd + 2 F chunks
#define FUSED_SMEM (FUSED_SMEM_ELEMS * 2 + 32 * 128 * 4)

__global__ void __launch_bounds__(256, 1) fused_drive_rnn_kernel(const float* __restrict__ rec_b,
                                                                 const float* __restrict__ init_state) {
    extern __shared__ __half smh[];
    __half* WdS = smh;
    __half* Fbase = smh + 128 * TSW;
    float* D = (float*)(smh + FUSED_SMEM_ELEMS);

    const int tid = threadIdx.x;
    const int wid = tid >> 5, lane = tid & 31;
    const int gid = lane >> 2, tig = lane & 3;
    const int wm = wid >> 2, wn = wid & 3;
    const int n0 = blockIdx.x * 128;
    const int b = blockIdx.y;
    const int diag = *(volatile int*)&g_diag_flag;

    {   // stage Wd (once): 128 rows x 80 halfs
        const int row = tid >> 1, half = tid & 1;
        const __half* gw = g_wd + (size_t)(n0 + row) * NKP + half * 40;
        __half* dw = WdS + row * TSW + half * 40;
#pragma unroll
        for (int q = 0; q < 5; q++)
            cp16(dw + q * 8, gw + q * 8);
    }

    auto loadF = [&](int ch, int buf) {
        __half* FH = Fbase + buf * FCHUNK;
        __half* FL = FH + 32 * TSW;
        const int t0 = ch * 32;
#pragma unroll
        for (int i = 0; i < 2; i++) {
            int e = tid + i * 256;
            if (e < 320) {
                int row = e / 10, q = e - row * 10;
                size_t gro = ((size_t)b * NT + t0 + row) * NKP + q * 8;
                cp16(FH + row * TSW + q * 8, g_ft_hi + gro);
                cp16(FL + row * TSW + q * 8, g_ft_lo + gro);
            }
        }
    };
    loadF(0, 0);
    cp_commit();

    float h = 0.0f, w = 0.0f, rb = 0.0f;
    if (tid < 128) {
        const int n = n0 + tid;
        w = g_wdiag[n];
        rb = rec_b[n];
        h = init_state[n];
    }

    const int quad = lane >> 3, rowin = lane & 7;
    const int a_m = wm * 16 + (quad & 1) * 8 + rowin;
    const int a_k = (quad >> 1) * 8;
    const int b_n = wn * 32 + (quad >> 1) * 8 + rowin;
    const int b_k = (quad & 1) * 8;

    for (int ch = 0; ch < 8; ch++) {
        if (ch < 7) {
            loadF(ch + 1, (ch + 1) & 1);
            cp_commit();
            cp_wait<1>();
        } else {
            cp_wait<0>();
        }
        __syncthreads();

        const __half* FH = Fbase + (ch & 1) * FCHUNK;
        const __half* FL = FH + 32 * TSW;

        float acc[4][4];
#pragma unroll
        for (int nt = 0; nt < 4; nt++)
#pragma unroll
            for (int j = 0; j < 4; j++) acc[nt][j] = 0.0f;

#pragma unroll
        for (int ks = 0; ks < 5; ks++) {
            const int kc0 = ks * 16;
            uint32_t ah[4], al[4], bw[4][2];
            ldsm4(ah, FH + a_m * TSW + kc0 + a_k);
            ldsm4(al, FL + a_m * TSW + kc0 + a_k);
#pragma unroll
            for (int j = 0; j < 2; j++) {
                uint32_t tb[4];
                ldsm4(tb, WdS + (b_n + j * 16) * TSW + kc0 + b_k);
                bw[2 * j][0] = tb[0]; bw[2 * j][1] = tb[1];
                bw[2 * j + 1][0] = tb[2]; bw[2 * j + 1][1] = tb[3];
            }
#pragma unroll
            for (int nt = 0; nt < 4; nt++) {
                mma_f16(acc[nt], ah, bw[nt]);
                mma_f16(acc[nt], al, bw[nt]);
            }
        }

        const int t0 = ch * 32;
        if (diag) {
#pragma unroll
            for (int nt = 0; nt < 4; nt++) {
                const int col = wn * 32 + nt * 8 + tig * 2;
                const int r = wm * 16 + gid;
                *(float2*)&D[r * 128 + col] = make_float2(acc[nt][0], acc[nt][1]);
                *(float2*)&D[(r + 8) * 128 + col] = make_float2(acc[nt][2], acc[nt][3]);
            }
            __syncthreads();
            if (tid < 128) {
                for (int tl2 = 0; tl2 < 32; tl2++) {
                    float d = D[tl2 * 128 + tid];
                    h = fmaxf(fmaf(h, w, rb + d), 0.0f);
                    g_hs[((size_t)b * NT + t0 + tl2) * NN + n0 + tid] = __float2half(h);
                }
            }
        } else {
#pragma unroll
            for (int nt = 0; nt < 4; nt++) {
                const int col = n0 + wn * 32 + nt * 8 + tig * 2;
                const int r = wm * 16 + gid;
                *(float2*)(g_drive + ((size_t)b * NT + t0 + r) * NN + col)
                    = make_float2(acc[nt][0], acc[nt][1]);
                *(float2*)(g_drive + ((size_t)b * NT + t0 + r + 8) * NN + col)
                    = make_float2(acc[nt][2], acc[nt][3]);
            }
            __syncthreads();
        }
    }
}

// ---------------- RNN general fallback: h in SMEM, 1 bar/step --------------
__global__ void __launch_bounds__(1024, 1) rnn_general_kernel(const float* __restrict__ rec_b,
                                                              const float* __restrict__ init_state) {
    if (*(volatile int*)&g_diag_flag != 0) return;
    __shared__ float hbuf[2][NN];
    const int b = blockIdx.x;
    const int n = threadIdx.x;

    const float rb = rec_b[n];
    const int cnt = g_nnz_cnt[n];
    const int cr = cnt < CMAX ? cnt : CMAX;
    int kk[CMAX]; float ww[CMAX];
    for (int j = 0; j < cr; j++) {
        kk[j] = g_nnz_idx[(size_t)n * NN + j];
        ww[j] = g_nnz_val[(size_t)n * NN + j];
    }
    hbuf[0][n] = init_state[n];
    __syncthreads();

    float d = g_drive[(size_t)b * NT * NN + n];

    for (int t = 0; t < NT; t++) {
        const float* cur = hbuf[t & 1];
        float* nxt = hbuf[(t + 1) & 1];
        float dn = 0.0f;
        if (t + 1 < NT)
            dn = g_drive[((size_t)b * NT + t + 1) * NN + n];

        float acc = rb + d;
        for (int j = 0; j < cr; j++)
            acc += cur[kk[j]] * ww[j];
        for (int j = CMAX; j < cnt; j++)
            acc += cur[g_nnz_idx[(size_t)n * NN + j]] * g_nnz_val[(size_t)n * NN + j];
        float hv = fmaxf(acc, 0.0f);
        nxt[n] = hv;
        g_hs[((size_t)b * NT + t) * NN + n] = __float2half(hv);
        __syncthreads();
        d = dn;
    }
}

// ---------------- out-GEMM: fp16 1-pass, 64m x 128n, 4 CTAs/SM -------------
#define SA_TILE (64 * TS)                    // 4608 halfs
#define SB_TILE (128 * TS)                   // 9216 halfs
#define OSTAGE (SA_TILE + SB_TILE)           // 13824 halfs
#define OGEMM_SMEM (2 * OSTAGE * 2)          // 55296 bytes

__global__ void __launch_bounds__(256) outgemm_mma_kernel(const float* __restrict__ outB) {
    extern __shared__ __half smemh[];
    const int tid = threadIdx.x;
    const int wid = tid >> 5, lane = tid & 31;
    const int gid = lane >> 2, tig = lane & 3;
    const int wm = wid >> 2, wn = wid & 3;       // 2(m) x 4(n); warp tile 32x32
    const int n0 = blockIdx.x * 128;
    const int row0 = blockIdx.y * 64;

    float acc[2][4][4];
#pragma unroll
    for (int mt = 0; mt < 2; mt++)
#pragma unroll
        for (int nt = 0; nt < 4; nt++)
#pragma unroll
            for (int j = 0; j < 4; j++) acc[mt][nt][j] = 0.0f;

    const int arow = tid >> 2, aq = (tid & 3) * 16;     // A: 64 rows x 64 cols
    const int brow = tid >> 1, bq = (tid & 1) * 32;     // B: 128 rows x 64 cols
    const __half* gA = g_hs + (size_t)(row0 + arow) * NN + aq;
    const __half* gB = g_wt + (size_t)(n0 + brow) * NN + bq;
    const int sbA = arow * TS + aq;
    const int sbB = brow * TS + bq;

    auto load_chunk = [&](int c, int buf) {
        __half* base = smemh + buf * OSTAGE;
        const int k0 = c * 64;
        cp16(base + sbA, gA + k0);
        cp16(base + sbA + 8, gA + k0 + 8);
#pragma unroll
        for (int q = 0; q < 4; q++)
            cp16(base + SA_TILE + sbB + q * 8, gB + k0 + q * 8);
    };

    const int quad = lane >> 3, rowin = lane & 7;
    const int a_m = wm * 32 + (quad & 1) * 8 + rowin;
    const int a_k = (quad >> 1) * 8;
    const int b_n = wn * 32 + (quad >> 1) * 8 + rowin;
    const int b_k = (quad & 1) * 8;

    load_chunk(0, 0);
    cp_commit();

    for (int c = 0; c < 16; c++) {
        if (c < 15) {
            load_chunk(c + 1, (c + 1) & 1);
            cp_commit();
            cp_wait<1>();
        } else {
            cp_wait<0>();
        }
        __syncthreads();

        const __half* Ah = smemh + (c & 1) * OSTAGE;
        const __half* Bt = Ah + SA_TILE;

#pragma unroll
        for (int ks = 0; ks < 4; ks++) {
            const int kc0 = ks * 16;
            uint32_t af[2][4], bf[4][2];
#pragma unroll
            for (int mt = 0; mt < 2; mt++)
                ldsm4(af[mt], Ah + (a_m + mt * 16) * TS + kc0 + a_k);
#pragma unroll
            for (int j = 0; j < 2; j++) {
                uint32_t tb[4];
                ldsm4(tb, Bt + (b_n + j * 16) * TS + kc0 + b_k);
                bf[2 * j][0] = tb[0]; bf[2 * j][1] = tb[1];
                bf[2 * j + 1][0] = tb[2]; bf[2 * j + 1][1] = tb[3];
            }
#pragma unroll
            for (int mt = 0; mt < 2; mt++)
#pragma unroll
                for (int nt = 0; nt < 4; nt++)
                    mma_f16(acc[mt][nt], af[mt], bf[nt]);
        }
        __syncthreads();
    }

#pragma unroll
    for (int nt = 0; nt < 4; nt++) {
        const int col = n0 + wn * 32 + nt * 8 + tig * 2;
        const float b0 = outB[col], b1 = outB[col + 1];
#pragma unroll
        for (int mt = 0; mt < 2; mt++) {
            const int r = row0 + wm * 32 + mt * 16 + gid;
            float2 o0, o1;
            o0.x = fmaxf(acc[mt][nt][0] + b0, 0.0f);
            o0.y = fmaxf(acc[mt][nt][1] + b1, 0.0f);
            o1.x = fmaxf(acc[mt][nt][2] + b0, 0.0f);
            o1.y = fmaxf(acc[mt][nt][3] + b1, 0.0f);
            *(float2*)(g_out + (size_t)r * NO + col) = o0;
            *(float2*)(g_out + (size_t)(r + 8) * NO + col) = o1;
        }
    }
}

// ---------------- time-softmax -> centers, 2-phase (8 chunks) --------------
__global__ void __launch_bounds__(512) centers_part_kernel(const float* __restrict__ r) {
    const int b = blockIdx.x;
    const int ch = blockIdx.y;
    const int n = threadIdx.x;
    float m = -1e30f, s = 0.0f, c0 = 0.0f, c1 = 0.0f;
    const float* ob = g_out + (size_t)b * NT * NO + (size_t)ch * 32 * NO;
    const float* rb = r + (size_t)b * NT * 2 + ch * 32 * 2;
    for (int t = 0; t < 32; t++) {
        float v = ob[(size_t)t * NO + n];
        float r0 = rb[t * 2 + 0], r1 = rb[t * 2 + 1];
        if (v > m) {
            float f = expf(m - v);
            s = s * f + 1.0f; c0 = c0 * f + r0; c1 = c1 * f + r1; m = v;
        } else {
            float p = expf(v - m);
            s += p; c0 += p * r0; c1 += p * r1;
        }
    }
    g_cpart[((size_t)ch * NB + b) * NO + n] = make_float4(m, s, c0, c1);
}

__global__ void __launch_bounds__(512) centers_comb_kernel() {
    const int b = blockIdx.x;
    const int n = threadIdx.x;
    float m = -1e30f;
#pragma unroll
    for (int ch = 0; ch < 8; ch++)
        m = fmaxf(m, g_cpart[((size_t)ch * NB + b) * NO + n].x);
    float s = 0.0f, c0 = 0.0f, c1 = 0.0f;
#pragma unroll
    for (int ch = 0; ch < 8; ch++) {
        float4 p = g_cpart[((size_t)ch * NB + b) * NO + n];
        float f = expf(p.x - m);
        s += p.y * f; c0 += p.z * f; c1 += p.w * f;
    }
    float inv = 1.0f / s;
    g_centers[((size_t)b * NO + n) * 2 + 0] = c0 * inv;
    g_centers[((size_t)b * NO + n) * 2 + 1] = c1 * inv;
}

// ---------------- cell-softmax -> expected position ------------------------
__global__ void __launch_bounds__(256) final_kernel(float* __restrict__ outp) {
    const int wrp = threadIdx.x >> 5;
    const int lane = threadIdx.x & 31;
    const int row = blockIdx.x * 8 + wrp;
    const int b = row >> 8;
    const float* o = g_out + (size_t)row * NO;

    float v[16];
    float vmax = -1e30f;
#pragma unroll
    for (int i = 0; i < 16; i++) {
        v[i] = o[lane + 32 * i];
        vmax = fmaxf(vmax, v[i]);
    }
#pragma unroll
    for (int off = 16; off; off >>= 1)
        vmax = fmaxf(vmax, __shfl_xor_sync(0xffffffffu, vmax, off));

    float s = 0.0f, a0 = 0.0f, a1 = 0.0f;
    const float* cen = g_centers + (size_t)b * NO * 2;
#pragma unroll
    for (int i = 0; i < 16; i++) {
        int n = lane + 32 * i;
        float p = expf(v[i] - vmax);
        s += p;
        float2 c = *(const float2*)(cen + n * 2);
        a0 += p * c.x; a1 += p * c.y;
    }
#pragma unroll
    for (int off = 16; off; off >>= 1) {
        s  += __shfl_xor_sync(0xffffffffu, s, off);
        a0 += __shfl_xor_sync(0xffffffffu, a0, off);
        a1 += __shfl_xor_sync(0xffffffffu, a1, off);
    }
    if (lane == 0) {
        float inv = 1.0f / s;
        outp[row * 2 + 0] = a0 * inv;
        outp[row * 2 + 1] = a1 * inv;
    }
}

extern "C" void kernel_launch(void* const* d_in, const int* in_sizes, int n_in,
                              void* d_out, int out_size) {
    const float* x    = (const float*)d_in[0];
    const float* r    = (const float*)d_in[1];
    const float* sW   = (const float*)d_in[2];
    const float* hW   = (const float*)d_in[3];
    const float* recW = (const float*)d_in[4];
    const float* recb = (const float*)d_in[5];
    const float* outW = (const float*)d_in[6];
    const float* outb = (const float*)d_in[7];
    const float* init = (const float*)d_in[8];
    float* outp = (float*)d_out;

    csc_phase1<<<NN / 16, 256>>>(recW);
    csc_phase2<<<NN / 256, 256>>>();
    {
        dim3 g(NN / 32, NO / 32);
        wsplit_kernel<<<g, 256>>>(outW);
    }
    wdsplit_kernel<<<(NN * NKP) / 256, 256>>>(sW, hW);
    feat_kernel<<<(NB * NT * NKP) / 256, 256>>>(x);
    {
        cudaFuncSetAttribute(fused_drive_rnn_kernel,
                             cudaFuncAttributeMaxDynamicSharedMemorySize, FUSED_SMEM);
        dim3 g(NN / 128, NB);
        fused_drive_rnn_kernel<<<g, 256, FUSED_SMEM>>>(recb, init);
    }
    rnn_general_kernel<<<NB, 1024>>>(recb, init);
    {
        cudaFuncSetAttribute(outgemm_mma_kernel,
                             cudaFuncAttributeMaxDynamicSharedMemorySize, OGEMM_SMEM);
        dim3 g(NO / 128, (NB * NT) / 64);
        outgemm_mma_kernel<<<g, 256, OGEMM_SMEM>>>(outb);
    }
    {
        dim3 g(NB, 8);
        centers_part_kernel<<<g, 512>>>(r);
    }
    centers_comb_kernel<<<NB, 512>>>();
    final_kernel<<<(NB * NT) / 8, 256>>>(outp);
}

// round 17
// speedup vs baseline: 8.3825x; 1.0721x over previous
#include <cuda_runtime.h>
#include <cuda_fp16.h>
#include <math.h>
#include <stdint.h>

#define NB 64
#define NT 256
#define NN 1024
#define NO 512
#define NK_SPEED 20
#define NK_HD 50
#define NK_TOT 70
#define NKP 80
#define CMAX 4

__device__ float  g_drive[(size_t)NB * NT * NN];
__device__ __half g_ft[(size_t)NB * NT * NKP];
__device__ __half g_wd[(size_t)NN * NKP];
__device__ __half g_hs[(size_t)NB * NT * NN];
__device__ __half g_wt[(size_t)NO * NN];
__device__ __half g_out[(size_t)NB * NT * NO];
__device__ float  g_centers[NB * NO * 2];
__device__ float4 g_cpart[8 * NB * NO];
__device__ int    g_nnz_cnt[NN];
__device__ int    g_nnz_idx[(size_t)NN * NN];
__device__ float  g_nnz_val[(size_t)NN * NN];
__device__ int    g_tmp_idx[(size_t)NN * NN];
__device__ float  g_tmp_val[(size_t)NN * NN];
__device__ int    g_scnt[NN * 16];
__device__ float  g_wdiag[NN];
__device__ int    g_diag_flag;

// ---------------- CSC phase 1: 16 k-segments per column, 64 CTAs -----------
__global__ void __launch_bounds__(256) csc_phase1(const float* __restrict__ recW) {
    const int tid = threadIdx.x;
    const int n = blockIdx.x * 16 + (tid & 15);
    const int kt = tid >> 4;
    int c = 0;
    const int kbase = kt * 64;
    for (int i = 0; i < 64; i++) {
        float w = recW[(size_t)(kbase + i) * NN + n];
        if (w != 0.0f) {
            g_tmp_idx[(size_t)n * NN + kbase + c] = kbase + i;
            g_tmp_val[(size_t)n * NN + kbase + c] = w;
            c++;
        }
    }
    g_scnt[n * 16 + kt] = c;
    if (blockIdx.x == 0 && tid == 0) g_diag_flag = 1;
}

// ---------------- CSC phase 2: concat segments, detect diagonality ---------
__global__ void __launch_bounds__(256) csc_phase2() {
    const int n = blockIdx.x * 256 + threadIdx.x;
    int off = 0;
    bool diag = true;
    float wsum = 0.0f;
    for (int s = 0; s < 16; s++) {
        const int c = g_scnt[n * 16 + s];
        for (int i = 0; i < c; i++) {
            int k = g_tmp_idx[(size_t)n * NN + s * 64 + i];
            float w = g_tmp_val[(size_t)n * NN + s * 64 + i];
            g_nnz_idx[(size_t)n * NN + off] = k;
            g_nnz_val[(size_t)n * NN + off] = w;
            off++;
            if (k != n) diag = false; else wsum += w;
        }
    }
    g_nnz_cnt[n] = off;
    g_wdiag[n] = wsum;
    if (!diag) g_diag_flag = 0;
}

// ---------------- merged prep: wsplit (512) + wdsplit (320) + feat (5120) --
#define WSPLIT_BLOCKS 512
#define WDSPLIT_BLOCKS 320
#define FEAT_BLOCKS ((NB * NT * NKP) / 256)

__global__ void __launch_bounds__(256) prep_kernel(const float* __restrict__ outW,
                                                   const float* __restrict__ sW,
                                                   const float* __restrict__ hW,
                                                   const float* __restrict__ x) {
    __shared__ float tile[32][33];
    const int blk = blockIdx.x;
    if (blk < WSPLIT_BLOCKS) {
        // transpose out_W -> [NO][NN] fp16
        const int k0 = (blk & 31) * 32, n0 = (blk >> 5) * 32;
        const int tx = threadIdx.x & 31, ty = threadIdx.x >> 5;
#pragma unroll
        for (int i = 0; i < 4; i++)
            tile[ty + 8 * i][tx] = outW[(size_t)(k0 + ty + 8 * i) * NO + n0 + tx];
        __syncthreads();
#pragma unroll
        for (int i = 0; i < 4; i++) {
            int row = ty + 8 * i;
            g_wt[(size_t)(n0 + row) * NN + k0 + tx] = __float2half(tile[tx][row]);
        }
    } else if (blk < WSPLIT_BLOCKS + WDSPLIT_BLOCKS) {
        const int idx = (blk - WSPLIT_BLOCKS) * 256 + threadIdx.x;
        const int n = idx / NKP;
        const int k = idx - n * NKP;
        float v = 0.0f;
        if (k < NK_SPEED)      v = sW[(size_t)k * NN + n];
        else if (k < NK_TOT)   v = hW[(size_t)(k - NK_SPEED) * NN + n];
        g_wd[idx] = __float2half(v);
    } else {
        const int idx = (blk - WSPLIT_BLOCKS - WDSPLIT_BLOCKS) * 256 + threadIdx.x;
        const int row = idx / NKP;
        const int k = idx - row * NKP;
        const float TWO_PI = 6.2831853071795865f;
        const float LOGNORM = 6.3050317f;  // log(2*pi*I0(2*pi))
        float f = 0.0f;
        if (k < NK_SPEED) {
            float v = x[(size_t)row * 2 + 0];
            float dv = v - 0.5f * (float)k / 19.0f;
            f = expf(-800.0f * dv * dv);
        } else if (k < NK_TOT) {
            float th = x[(size_t)row * 2 + 1];
            float c = TWO_PI * (float)(k - NK_SPEED) / 49.0f;
            f = expf(TWO_PI * cosf(th - c) - LOGNORM);
        }
        g_ft[idx] = __float2half(f);
    }
}

// ---------------- common machinery -----------------------------------------
#define TS 72

__device__ __forceinline__ void cp16(void* smem_dst, const void* gsrc) {
    uint32_t s = (uint32_t)__cvta_generic_to_shared(smem_dst);
    asm volatile("cp.async.cg.shared.global [%0], [%1], 16;" :: "r"(s), "l"(gsrc) : "memory");
}
__device__ __forceinline__ void cp_commit() {
    asm volatile("cp.async.commit_group;" ::: "memory");
}
template <int N>
__device__ __forceinline__ void cp_wait() {
    asm volatile("cp.async.wait_group %0;" :: "n"(N) : "memory");
}
__device__ __forceinline__ void mma_f16(float* d, const uint32_t* a, const uint32_t* b) {
    asm volatile(
        "mma.sync.aligned.m16n8k16.row.col.f32.f16.f16.f32 "
        "{%0,%1,%2,%3}, {%4,%5,%6,%7}, {%8,%9}, {%0,%1,%2,%3};"
        : "+f"(d[0]), "+f"(d[1]), "+f"(d[2]), "+f"(d[3])
        : "r"(a[0]), "r"(a[1]), "r"(a[2]), "r"(a[3]), "r"(b[0]), "r"(b[1]));
}
__device__ __forceinline__ void ldsm4(uint32_t* r, const void* p) {
    uint32_t a = (uint32_t)__cvta_generic_to_shared(p);
    asm volatile("ldmatrix.sync.aligned.m8n8.x4.shared.b16 {%0,%1,%2,%3}, [%4];"
                 : "=r"(r[0]), "=r"(r[1]), "=r"(r[2]), "=r"(r[3]) : "r"(a));
}

// ---------------- fused drive-GEMM + RNN scan (fp16 1-pass) ----------------
#define TSW 88
#define FCHUNK (32 * TSW)                         // F chunk (halfs)
#define FUSED_SMEM_ELEMS (128 * TSW + 2 * FCHUNK) // Wd + 2 F chunks
#define FUSED_SMEM (FUSED_SMEM_ELEMS * 2 + 32 * 128 * 4)

__global__ void __launch_bounds__(256, 1) fused_drive_rnn_kernel(const float* __restrict__ rec_b,
                                                                 const float* __restrict__ init_state) {
    extern __shared__ __half smh[];
    __half* WdS = smh;
    __half* Fbase = smh + 128 * TSW;
    float* D = (float*)(smh + FUSED_SMEM_ELEMS);

    const int tid = threadIdx.x;
    const int wid = tid >> 5, lane = tid & 31;
    const int gid = lane >> 2, tig = lane & 3;
    const int wm = wid >> 2, wn = wid & 3;
    const int n0 = blockIdx.x * 128;
    const int b = blockIdx.y;
    const int diag = *(volatile int*)&g_diag_flag;

    {   // stage Wd (once): 128 rows x 80 halfs
        const int row = tid >> 1, half = tid & 1;
        const __half* gw = g_wd + (size_t)(n0 + row) * NKP + half * 40;
        __half* dw = WdS + row * TSW + half * 40;
#pragma unroll
        for (int q = 0; q < 5; q++)
            cp16(dw + q * 8, gw + q * 8);
    }

    auto loadF = [&](int ch, int buf) {
        __half* FH = Fbase + buf * FCHUNK;
        const int t0 = ch * 32;
#pragma unroll
        for (int i = 0; i < 2; i++) {
            int e = tid + i * 256;
            if (e < 320) {
                int row = e / 10, q = e - row * 10;
                cp16(FH + row * TSW + q * 8,
                     g_ft + ((size_t)b * NT + t0 + row) * NKP + q * 8);
            }
        }
    };
    loadF(0, 0);
    cp_commit();

    float h = 0.0f, w = 0.0f, rb = 0.0f;
    if (tid < 128) {
        const int n = n0 + tid;
        w = g_wdiag[n];
        rb = rec_b[n];
        h = init_state[n];
    }

    const int quad = lane >> 3, rowin = lane & 7;
    const int a_m = wm * 16 + (quad & 1) * 8 + rowin;
    const int a_k = (quad >> 1) * 8;
    const int b_n = wn * 32 + (quad >> 1) * 8 + rowin;
    const int b_k = (quad & 1) * 8;

    for (int ch = 0; ch < 8; ch++) {
        if (ch < 7) {
            loadF(ch + 1, (ch + 1) & 1);
            cp_commit();
            cp_wait<1>();
        } else {
            cp_wait<0>();
        }
        __syncthreads();

        const __half* FH = Fbase + (ch & 1) * FCHUNK;

        float acc[4][4];
#pragma unroll
        for (int nt = 0; nt < 4; nt++)
#pragma unroll
            for (int j = 0; j < 4; j++) acc[nt][j] = 0.0f;

#pragma unroll
        for (int ks = 0; ks < 5; ks++) {
            const int kc0 = ks * 16;
            uint32_t ah[4], bw[4][2];
            ldsm4(ah, FH + a_m * TSW + kc0 + a_k);
#pragma unroll
            for (int j = 0; j < 2; j++) {
                uint32_t tb[4];
                ldsm4(tb, WdS + (b_n + j * 16) * TSW + kc0 + b_k);
                bw[2 * j][0] = tb[0]; bw[2 * j][1] = tb[1];
                bw[2 * j + 1][0] = tb[2]; bw[2 * j + 1][1] = tb[3];
            }
#pragma unroll
            for (int nt = 0; nt < 4; nt++)
                mma_f16(acc[nt], ah, bw[nt]);
        }

        const int t0 = ch * 32;
        if (diag) {
#pragma unroll
            for (int nt = 0; nt < 4; nt++) {
                const int col = wn * 32 + nt * 8 + tig * 2;
                const int r = wm * 16 + gid;
                *(float2*)&D[r * 128 + col] = make_float2(acc[nt][0], acc[nt][1]);
                *(float2*)&D[(r + 8) * 128 + col] = make_float2(acc[nt][2], acc[nt][3]);
            }
            __syncthreads();
            if (tid < 128) {
                for (int tl2 = 0; tl2 < 32; tl2++) {
                    float d = D[tl2 * 128 + tid];
                    h = fmaxf(fmaf(h, w, rb + d), 0.0f);
                    g_hs[((size_t)b * NT + t0 + tl2) * NN + n0 + tid] = __float2half(h);
                }
            }
        } else {
#pragma unroll
            for (int nt = 0; nt < 4; nt++) {
                const int col = n0 + wn * 32 + nt * 8 + tig * 2;
                const int r = wm * 16 + gid;
                *(float2*)(g_drive + ((size_t)b * NT + t0 + r) * NN + col)
                    = make_float2(acc[nt][0], acc[nt][1]);
                *(float2*)(g_drive + ((size_t)b * NT + t0 + r + 8) * NN + col)
                    = make_float2(acc[nt][2], acc[nt][3]);
            }
            __syncthreads();
        }
    }
}

// ---------------- RNN general fallback: h in SMEM, 1 bar/step --------------
__global__ void __launch_bounds__(1024, 1) rnn_general_kernel(const float* __restrict__ rec_b,
                                                              const float* __restrict__ init_state) {
    if (*(volatile int*)&g_diag_flag != 0) return;
    __shared__ float hbuf[2][NN];
    const int b = blockIdx.x;
    const int n = threadIdx.x;

    const float rb = rec_b[n];
    const int cnt = g_nnz_cnt[n];
    const int cr = cnt < CMAX ? cnt : CMAX;
    int kk[CMAX]; float ww[CMAX];
    for (int j = 0; j < cr; j++) {
        kk[j] = g_nnz_idx[(size_t)n * NN + j];
        ww[j] = g_nnz_val[(size_t)n * NN + j];
    }
    hbuf[0][n] = init_state[n];
    __syncthreads();

    float d = g_drive[(size_t)b * NT * NN + n];

    for (int t = 0; t < NT; t++) {
        const float* cur = hbuf[t & 1];
        float* nxt = hbuf[(t + 1) & 1];
        float dn = 0.0f;
        if (t + 1 < NT)
            dn = g_drive[((size_t)b * NT + t + 1) * NN + n];

        float acc = rb + d;
        for (int j = 0; j < cr; j++)
            acc += cur[kk[j]] * ww[j];
        for (int j = CMAX; j < cnt; j++)
            acc += cur[g_nnz_idx[(size_t)n * NN + j]] * g_nnz_val[(size_t)n * NN + j];
        float hv = fmaxf(acc, 0.0f);
        nxt[n] = hv;
        g_hs[((size_t)b * NT + t) * NN + n] = __float2half(hv);
        __syncthreads();
        d = dn;
    }
}

// ---------------- out-GEMM: fp16 1-pass, 64m x 128n, 4 CTAs/SM -------------
#define SA_TILE (64 * TS)
#define SB_TILE (128 * TS)
#define OSTAGE (SA_TILE + SB_TILE)
#define OGEMM_SMEM (2 * OSTAGE * 2)

__global__ void __launch_bounds__(256) outgemm_mma_kernel(const float* __restrict__ outB) {
    extern __shared__ __half smemh[];
    const int tid = threadIdx.x;
    const int wid = tid >> 5, lane = tid & 31;
    const int gid = lane >> 2, tig = lane & 3;
    const int wm = wid >> 2, wn = wid & 3;
    const int n0 = blockIdx.x * 128;
    const int row0 = blockIdx.y * 64;

    float acc[2][4][4];
#pragma unroll
    for (int mt = 0; mt < 2; mt++)
#pragma unroll
        for (int nt = 0; nt < 4; nt++)
#pragma unroll
            for (int j = 0; j < 4; j++) acc[mt][nt][j] = 0.0f;

    const int arow = tid >> 2, aq = (tid & 3) * 16;
    const int brow = tid >> 1, bq = (tid & 1) * 32;
    const __half* gA = g_hs + (size_t)(row0 + arow) * NN + aq;
    const __half* gB = g_wt + (size_t)(n0 + brow) * NN + bq;
    const int sbA = arow * TS + aq;
    const int sbB = brow * TS + bq;

    auto load_chunk = [&](int c, int buf) {
        __half* base = smemh + buf * OSTAGE;
        const int k0 = c * 64;
        cp16(base + sbA, gA + k0);
        cp16(base + sbA + 8, gA + k0 + 8);
#pragma unroll
        for (int q = 0; q < 4; q++)
            cp16(base + SA_TILE + sbB + q * 8, gB + k0 + q * 8);
    };

    const int quad = lane >> 3, rowin = lane & 7;
    const int a_m = wm * 32 + (quad & 1) * 8 + rowin;
    const int a_k = (quad >> 1) * 8;
    const int b_n = wn * 32 + (quad >> 1) * 8 + rowin;
    const int b_k = (quad & 1) * 8;

    load_chunk(0, 0);
    cp_commit();

    for (int c = 0; c < 16; c++) {
        if (c < 15) {
            load_chunk(c + 1, (c + 1) & 1);
            cp_commit();
            cp_wait<1>();
        } else {
            cp_wait<0>();
        }
        __syncthreads();

        const __half* Ah = smemh + (c & 1) * OSTAGE;
        const __half* Bt = Ah + SA_TILE;

#pragma unroll
        for (int ks = 0; ks < 4; ks++) {
            const int kc0 = ks * 16;
            uint32_t af[2][4], bf[4][2];
#pragma unroll
            for (int mt = 0; mt < 2; mt++)
                ldsm4(af[mt], Ah + (a_m + mt * 16) * TS + kc0 + a_k);
#pragma unroll
            for (int j = 0; j < 2; j++) {
                uint32_t tb[4];
                ldsm4(tb, Bt + (b_n + j * 16) * TS + kc0 + b_k);
                bf[2 * j][0] = tb[0]; bf[2 * j][1] = tb[1];
                bf[2 * j + 1][0] = tb[2]; bf[2 * j + 1][1] = tb[3];
            }
#pragma unroll
            for (int mt = 0; mt < 2; mt++)
#pragma unroll
                for (int nt = 0; nt < 4; nt++)
                    mma_f16(acc[mt][nt], af[mt], bf[nt]);
        }
        __syncthreads();
    }

#pragma unroll
    for (int nt = 0; nt < 4; nt++) {
        const int col = n0 + wn * 32 + nt * 8 + tig * 2;
        const float b0 = outB[col], b1 = outB[col + 1];
#pragma unroll
        for (int mt = 0; mt < 2; mt++) {
            const int r = row0 + wm * 32 + mt * 16 + gid;
            __half2 o0, o1;
            o0.x = __float2half(fmaxf(acc[mt][nt][0] + b0, 0.0f));
            o0.y = __float2half(fmaxf(acc[mt][nt][1] + b1, 0.0f));
            o1.x = __float2half(fmaxf(acc[mt][nt][2] + b0, 0.0f));
            o1.y = __float2half(fmaxf(acc[mt][nt][3] + b1, 0.0f));
            *(__half2*)(g_out + (size_t)r * NO + col) = o0;
            *(__half2*)(g_out + (size_t)(r + 8) * NO + col) = o1;
        }
    }
}

// ---------------- time-softmax -> centers, 2-phase (8 chunks) --------------
__global__ void __launch_bounds__(512) centers_part_kernel(const float* __restrict__ r) {
    const int b = blockIdx.x;
    const int ch = blockIdx.y;
    const int n = threadIdx.x;
    float m = -1e30f, s = 0.0f, c0 = 0.0f, c1 = 0.0f;
    const __half* ob = g_out + (size_t)b * NT * NO + (size_t)ch * 32 * NO;
    const float* rb = r + (size_t)b * NT * 2 + ch * 32 * 2;
    for (int t = 0; t < 32; t++) {
        float v = __half2float(ob[(size_t)t * NO + n]);
        float r0 = rb[t * 2 + 0], r1 = rb[t * 2 + 1];
        if (v > m) {
            float f = expf(m - v);
            s = s * f + 1.0f; c0 = c0 * f + r0; c1 = c1 * f + r1; m = v;
        } else {
            float p = expf(v - m);
            s += p; c0 += p * r0; c1 += p * r1;
        }
    }
    g_cpart[((size_t)ch * NB + b) * NO + n] = make_float4(m, s, c0, c1);
}

__global__ void __launch_bounds__(512) centers_comb_kernel() {
    const int b = blockIdx.x;
    const int n = threadIdx.x;
    float m = -1e30f;
#pragma unroll
    for (int ch = 0; ch < 8; ch++)
        m = fmaxf(m, g_cpart[((size_t)ch * NB + b) * NO + n].x);
    float s = 0.0f, c0 = 0.0f, c1 = 0.0f;
#pragma unroll
    for (int ch = 0; ch < 8; ch++) {
        float4 p = g_cpart[((size_t)ch * NB + b) * NO + n];
        float f = expf(p.x - m);
        s += p.y * f; c0 += p.z * f; c1 += p.w * f;
    }
    float inv = 1.0f / s;
    g_centers[((size_t)b * NO + n) * 2 + 0] = c0 * inv;
    g_centers[((size_t)b * NO + n) * 2 + 1] = c1 * inv;
}

// ---------------- cell-softmax -> expected position ------------------------
__global__ void __launch_bounds__(256) final_kernel(float* __restrict__ outp) {
    const int wrp = threadIdx.x >> 5;
    const int lane = threadIdx.x & 31;
    const int row = blockIdx.x * 8 + wrp;
    const int b = row >> 8;
    const __half* o = g_out + (size_t)row * NO;

    float v[16];
    float vmax = -1e30f;
#pragma unroll
    for (int i = 0; i < 16; i++) {
        v[i] = __half2float(o[lane + 32 * i]);
        vmax = fmaxf(vmax, v[i]);
    }
#pragma unroll
    for (int off = 16; off; off >>= 1)
        vmax = fmaxf(vmax, __shfl_xor_sync(0xffffffffu, vmax, off));

    float s = 0.0f, a0 = 0.0f, a1 = 0.0f;
    const float* cen = g_centers + (size_t)b * NO * 2;
#pragma unroll
    for (int i = 0; i < 16; i++) {
        int n = lane + 32 * i;
        float p = expf(v[i] - vmax);
        s += p;
        float2 c = *(const float2*)(cen + n * 2);
        a0 += p * c.x; a1 += p * c.y;
    }
#pragma unroll
    for (int off = 16; off; off >>= 1) {
        s  += __shfl_xor_sync(0xffffffffu, s, off);
        a0 += __shfl_xor_sync(0xffffffffu, a0, off);
        a1 += __shfl_xor_sync(0xffffffffu, a1, off);
    }
    if (lane == 0) {
        float inv = 1.0f / s;
        outp[row * 2 + 0] = a0 * inv;
        outp[row * 2 + 1] = a1 * inv;
    }
}

extern "C" void kernel_launch(void* const* d_in, const int* in_sizes, int n_in,
                              void* d_out, int out_size) {
    const float* x    = (const float*)d_in[0];
    const float* r    = (const float*)d_in[1];
    const float* sW   = (const float*)d_in[2];
    const float* hW   = (const float*)d_in[3];
    const float* recW = (const float*)d_in[4];
    const float* recb = (const float*)d_in[5];
    const float* outW = (const float*)d_in[6];
    const float* outb = (const float*)d_in[7];
    const float* init = (const float*)d_in[8];
    float* outp = (float*)d_out;

    csc_phase1<<<NN / 16, 256>>>(recW);
    csc_phase2<<<NN / 256, 256>>>();
    prep_kernel<<<WSPLIT_BLOCKS + WDSPLIT_BLOCKS + FEAT_BLOCKS, 256>>>(outW, sW, hW, x);
    {
        cudaFuncSetAttribute(fused_drive_rnn_kernel,
                             cudaFuncAttributeMaxDynamicSharedMemorySize, FUSED_SMEM);
        dim3 g(NN / 128, NB);
        fused_drive_rnn_kernel<<<g, 256, FUSED_SMEM>>>(recb, init);
    }
    rnn_general_kernel<<<NB, 1024>>>(recb, init);
    {
        cudaFuncSetAttribute(outgemm_mma_kernel,
                             cudaFuncAttributeMaxDynamicSharedMemorySize, OGEMM_SMEM);
        dim3 g(NO / 128, (NB * NT) / 64);
        outgemm_mma_kernel<<<g, 256, OGEMM_SMEM>>>(outb);
    }
    {
        dim3 g(NB, 8);
        centers_part_kernel<<<g, 512>>>(r);
    }
    centers_comb_kernel<<<NB, 512>>>();
    final_kernel<<<(NB * NT) / 8, 256>>>(outp);
}